// round 4
// baseline (speedup 1.0000x reference)
#include <cuda_runtime.h>
#include <cstdint>

// ---------------- problem constants ----------------
#define BT     8
#define NPIX   4096
#define DD     512
#define CFF    128
#define INCC   640
#define GG     64
#define NWIN   64
#define NGLOB  64
#define NHEAD  8
#define DHH    64
#define MTOK   32768

// ---------------- scratch ----------------
__device__ float g_qk [BT*NPIX*INCC];
__device__ float g_kg [BT*NGLOB*INCC];
__device__ float g_vg [BT*NGLOB*DD];
__device__ float g_Q  [BT*GG*NWIN*DD];
__device__ float g_Kl [BT*GG*NWIN*DD];
__device__ float g_Vl [BT*GG*NWIN*DD];
__device__ float g_Kg [BT*NGLOB*DD];
__device__ float g_Vg [BT*NGLOB*DD];
__device__ float g_O  [BT*GG*NWIN*DD];
__device__ float g_st_qk[MTOK*2];
__device__ float g_st_x [MTOK*2];
__device__ float g_st_kg[BT*NGLOB*2];
__device__ float g_st_vg[BT*NGLOB*2];
// folded / rounded weights
__device__ float g_fwq[DD*INCC];
__device__ float g_fwk[DD*INCC];
__device__ float g_fwv[DD*DD];
__device__ float g_fwo[DD*DD];
__device__ float g_frw[INCC*INCC];
__device__ float g_fbq[DD];
__device__ float g_fbk[DD];
__device__ float g_fbv[DD];

// ---------------- helpers ----------------
__device__ __forceinline__ int win_map(int r) {
    int b = r >> 12;
    int p = r & 4095;
    int h = p >> 6, w = p & 63;
    int g = ((h >> 3) << 3) | (w >> 3);
    int n = ((h & 7) << 3) | (w & 7);
    return (((b << 6) | g) << 6) | n;
}

__device__ __forceinline__ float to_tf32(float x) {
    uint32_t u;
    asm("cvt.rna.tf32.f32 %0, %1;" : "=r"(u) : "f"(x));
    return __uint_as_float(u);
}
__device__ __forceinline__ float4 to_tf32_4(float4 v) {
    v.x = to_tf32(v.x); v.y = to_tf32(v.y);
    v.z = to_tf32(v.z); v.w = to_tf32(v.w);
    return v;
}

__device__ __forceinline__ void mma16n8k8(float* d, const uint32_t* a, const uint32_t* b) {
    asm volatile(
        "mma.sync.aligned.m16n8k8.row.col.f32.tf32.tf32.f32 "
        "{%0,%1,%2,%3}, {%4,%5,%6,%7}, {%8,%9}, {%0,%1,%2,%3};"
        : "+f"(d[0]), "+f"(d[1]), "+f"(d[2]), "+f"(d[3])
        : "r"(a[0]), "r"(a[1]), "r"(a[2]), "r"(a[3]), "r"(b[0]), "r"(b[1]));
}

#define CP_ASYNC16(dst, src) \
    asm volatile("cp.async.ca.shared.global [%0], [%1], 16;" :: "r"(dst), "l"(src))
#define CP_COMMIT() asm volatile("cp.async.commit_group;" ::: "memory")
#define CP_WAIT0()  asm volatile("cp.async.wait_group 0;" ::: "memory")

__device__ __forceinline__ uint32_t bits(float f) { return __float_as_uint(f); }

// ---------------- weight fold: W' = rnd(W*gamma), b' = b + beta @ W^T ----------------
__global__ __launch_bounds__(256)
void fold_w_kernel(const float* __restrict__ W, const float* __restrict__ gamma,
                   const float* __restrict__ beta, const float* __restrict__ b,
                   float* __restrict__ Wo, float* __restrict__ bo, int N, int K) {
    int n = blockIdx.x * 8 + (threadIdx.x >> 5);
    if (n >= N) return;
    int lane = threadIdx.x & 31;
    const float* wr = W + (size_t)n * K;
    float* wor = Wo + (size_t)n * K;
    float acc = 0.f;
    for (int k = lane; k < K; k += 32) {
        float w = wr[k];
        if (beta) acc += beta[k] * w;
        wor[k] = to_tf32(gamma ? w * gamma[k] : w);
    }
    if (beta) {
        #pragma unroll
        for (int o = 16; o; o >>= 1) acc += __shfl_xor_sync(0xffffffffu, acc, o);
        if (lane == 0) bo[n] = b[n] + acc;
    }
}

// ---------------- LayerNorm stats: one warp per row ----------------
__global__ __launch_bounds__(256)
void ln_stats_kernel(const float* __restrict__ X, float* __restrict__ stats, int K) {
    int row = blockIdx.x * 8 + (threadIdx.x >> 5);
    int lane = threadIdx.x & 31;
    const float* xr = X + (size_t)row * K;
    float s = 0.f, ss = 0.f;
    for (int k = lane * 4; k < K; k += 128) {
        float4 v = *(const float4*)(xr + k);
        s  += v.x + v.y + v.z + v.w;
        ss += v.x * v.x + v.y * v.y + v.z * v.z + v.w * v.w;
    }
    #pragma unroll
    for (int o = 16; o; o >>= 1) {
        s  += __shfl_xor_sync(0xffffffffu, s, o);
        ss += __shfl_xor_sync(0xffffffffu, ss, o);
    }
    if (lane == 0) {
        float mean = s / K;
        float var = ss / K - mean * mean;
        *(float2*)(stats + (size_t)row * 2) = make_float2(mean, rsqrtf(var + 1e-5f));
    }
}

// ---------------- depthwise 8x8 stride-8 conv ----------------
__global__ __launch_bounds__(256)
void dwconv_kernel(const float* __restrict__ X, const float* __restrict__ Wc,
                   const float* __restrict__ bc, float* __restrict__ out, int C) {
    int bw = blockIdx.x;
    int b = bw >> 6;
    int g = bw & 63;
    int gh = g >> 3, gw = g & 7;
    const float* xb = X + (size_t)b * NPIX * C;
    for (int c = threadIdx.x; c < C; c += 256) {
        float s = bc[c];
        #pragma unroll
        for (int i = 0; i < 8; i++)
            #pragma unroll
            for (int j = 0; j < 8; j++)
                s += xb[(size_t)((gh * 8 + i) * 64 + (gw * 8 + j)) * C + c]
                     * Wc[c * 64 + i * 8 + j];
        out[(size_t)bw * C + c] = s;
    }
}

// ---------------- pipelined tf32 mma GEMM: C[M,N] = op(A)[M,K] @ W[N,K]^T ----------------
// MODE 0: A split (x|f); out = a * sigmoid(acc+bias); spatial write
// MODE 1: LN-normalized A ((a-m)*rstd, gamma folded into W); +bias; row = win_map
// MODE 2: as MODE 1, identity output rows
// MODE 3: A gathered via win_map; +bias; spatial write
// CTA tile: 128 x (NHALF*128), K chunks of 32, cp.async double-buffered B,
// register-staged A (transform+round fused).
template<int MODE, int NHALF>
__global__ __launch_bounds__(256, 1)
void mma_gemm(const float* __restrict__ A, const float* __restrict__ A2,
              const float* __restrict__ W, const float* __restrict__ bias,
              const float* __restrict__ stats, float* __restrict__ C,
              int M, int N, int K) {
    extern __shared__ float sm[];
    float* As = sm;                       // [2][128*36]
    float* Bs = sm + 2 * 128 * 36;        // [2][NHALF*128*36]

    const int tid = threadIdx.x;
    const int m0 = blockIdx.y * 128;
    const int n0 = blockIdx.x * (NHALF * 128);
    const int q = tid & 7;
    const int lrow = tid >> 3;            // 0..31
    const int lane = tid & 31, grp = lane >> 2, tig = lane & 3;
    const int w = tid >> 5, mblk = (w & 3) * 32, nblk = (w >> 2) * 64;
    const int NC = K >> 5;

    const uint32_t bs_base = (uint32_t)__cvta_generic_to_shared(Bs);

    int arow[4]; float mean[4], rstd[4];
    #pragma unroll
    for (int i = 0; i < 4; i++) {
        int r = m0 + lrow + i * 32;
        arow[i] = (MODE == 3) ? win_map(r) : r;
        if (MODE == 1 || MODE == 2) {
            float2 st = *(const float2*)(stats + (size_t)r * 2);
            mean[i] = st.x; rstd[i] = st.y;
        }
    }

    float acc[NHALF][2][8][4];
    #pragma unroll
    for (int hf = 0; hf < NHALF; hf++)
        #pragma unroll
        for (int mt = 0; mt < 2; mt++)
            #pragma unroll
            for (int nt = 0; nt < 8; nt++)
                #pragma unroll
                for (int e = 0; e < 4; e++) acc[hf][mt][nt][e] = 0.f;

    auto issue_B = [&](int ch, int buf) {
        int gk = (ch << 5) + q * 4;
        #pragma unroll
        for (int i = 0; i < NHALF * 4; i++) {
            int r = lrow + i * 32;
            const float* src = W + (size_t)(n0 + r) * K + gk;
            uint32_t dst = bs_base + (uint32_t)(((buf * NHALF * 128 + r) * 36 + q * 4) * 4);
            CP_ASYNC16(dst, src);
        }
    };
    auto load_A = [&](int ch, float4* areg) {
        int k0 = ch << 5;
        int gk = k0 + q * 4;
        #pragma unroll
        for (int i = 0; i < 4; i++) {
            float4 av;
            if (MODE == 0) {
                if (k0 < 512) av = *(const float4*)(A  + (size_t)arow[i] * 512 + gk);
                else          av = *(const float4*)(A2 + (size_t)arow[i] * 128 + (gk - 512));
            } else {
                av = *(const float4*)(A + (size_t)arow[i] * K + gk);
                if (MODE == 1 || MODE == 2) {
                    av.x = (av.x - mean[i]) * rstd[i];
                    av.y = (av.y - mean[i]) * rstd[i];
                    av.z = (av.z - mean[i]) * rstd[i];
                    av.w = (av.w - mean[i]) * rstd[i];
                }
            }
            areg[i] = to_tf32_4(av);
        }
    };
    auto sts_A = [&](int buf, const float4* areg) {
        #pragma unroll
        for (int i = 0; i < 4; i++)
            *(float4*)&As[(buf * 128 + lrow + i * 32) * 36 + q * 4] = areg[i];
    };
    auto compute = [&](int buf) {
        const float* Ab = &As[buf * 128 * 36];
        const float* Bb = &Bs[buf * NHALF * 128 * 36];
        #pragma unroll
        for (int k8 = 0; k8 < 4; k8++) {
            int k0 = k8 * 8;
            uint32_t af[2][4];
            #pragma unroll
            for (int mt = 0; mt < 2; mt++) {
                int rb = mblk + mt * 16;
                af[mt][0] = bits(Ab[(rb + grp)     * 36 + k0 + tig]);
                af[mt][1] = bits(Ab[(rb + grp + 8) * 36 + k0 + tig]);
                af[mt][2] = bits(Ab[(rb + grp)     * 36 + k0 + tig + 4]);
                af[mt][3] = bits(Ab[(rb + grp + 8) * 36 + k0 + tig + 4]);
            }
            #pragma unroll
            for (int hf = 0; hf < NHALF; hf++) {
                #pragma unroll
                for (int nt = 0; nt < 8; nt++) {
                    int nb = hf * 128 + nblk + nt * 8 + grp;
                    uint32_t bf[2] = { bits(Bb[nb * 36 + k0 + tig]),
                                       bits(Bb[nb * 36 + k0 + tig + 4]) };
                    mma16n8k8(acc[hf][0][nt], af[0], bf);
                    mma16n8k8(acc[hf][1][nt], af[1], bf);
                }
            }
        }
    };

    // prologue
    issue_B(0, 0); CP_COMMIT();
    {
        float4 areg0[4];
        load_A(0, areg0);
        sts_A(0, areg0);
    }
    CP_WAIT0();
    __syncthreads();

    float4 areg[4];
    for (int ch = 0; ch < NC; ch++) {
        int buf = ch & 1;
        int nx = ch + 1;
        if (nx < NC) {
            issue_B(nx, buf ^ 1); CP_COMMIT();
            load_A(nx, areg);
        }
        compute(buf);
        if (nx < NC) {
            sts_A(buf ^ 1, areg);
            CP_WAIT0();
        }
        __syncthreads();
    }

    // epilogue
    #pragma unroll
    for (int hf = 0; hf < NHALF; hf++) {
        #pragma unroll
        for (int mt = 0; mt < 2; mt++) {
            #pragma unroll
            for (int hr = 0; hr < 2; hr++) {
                int r = m0 + mblk + mt * 16 + grp + hr * 8;
                size_t orow = (MODE == 1) ? (size_t)win_map(r) : (size_t)r;
                float* crow = C + orow * (size_t)N;
                #pragma unroll
                for (int nt = 0; nt < 8; nt++) {
                    int c = n0 + hf * 128 + nblk + nt * 8 + 2 * tig;
                    float y0 = acc[hf][mt][nt][hr * 2 + 0] + bias[c];
                    float y1 = acc[hf][mt][nt][hr * 2 + 1] + bias[c + 1];
                    if (MODE == 0) {
                        float a0 = (c < 512) ? A[(size_t)r * 512 + c]
                                             : A2[(size_t)r * 128 + (c - 512)];
                        float a1 = (c + 1 < 512) ? A[(size_t)r * 512 + c + 1]
                                                 : A2[(size_t)r * 128 + (c + 1 - 512)];
                        y0 = a0 / (1.f + __expf(-y0));
                        y1 = a1 / (1.f + __expf(-y1));
                    }
                    *(float2*)(crow + c) = make_float2(y0, y1);
                }
            }
        }
    }
}

// ---------------- attention with mma.sync tf32 ----------------
// one block per (b, window, head): Q[64,64], K[128,64] (local|global), V[128,64]
#define ATTN_SMEM_FLOATS (64*68 + 128*68 + 64*132 + 64*132)   // 29952
#define ATTN_SMEM_BYTES  (ATTN_SMEM_FLOATS * 4)               // 119808

__global__ __launch_bounds__(256)
void attn_kernel(const float* __restrict__ Q, const float* __restrict__ Kl,
                 const float* __restrict__ Kg, const float* __restrict__ Vl,
                 const float* __restrict__ Vg, float* __restrict__ O) {
    extern __shared__ float sm[];
    float* Qs = sm;                // [64][68]  (m, k)
    float* Ks = Qs + 64 * 68;      // [128][68] (n=key, k)
    float* Vt = Ks + 128 * 68;     // [64][132] (d, key)
    float* S  = Vt + 64 * 132;     // [64][132] (m, key)

    int bid = blockIdx.x;
    int b = bid >> 9;
    int rem = bid & 511;
    int g = rem >> 3;
    int h = rem & 7;

    size_t wbase = ((size_t)(b * GG + g) * NWIN) * DD + (size_t)h * DHH;
    size_t gbase = ((size_t)b * NGLOB) * DD + (size_t)h * DHH;
    const float* Qp  = Q  + wbase;
    const float* Klp = Kl + wbase;
    const float* Vlp = Vl + wbase;
    const float* Kgp = Kg + gbase;
    const float* Vgp = Vg + gbase;
    float* Op = O + wbase;

    int tid = threadIdx.x;

    // load Q (rounded)
    for (int e = tid; e < 64 * 16; e += 256) {
        int m = e >> 4, d4 = (e & 15) << 2;
        float4 v = to_tf32_4(*(const float4*)(Qp + (size_t)m * DD + d4));
        *(float4*)&Qs[m * 68 + d4] = v;
    }
    // load K natural + V transposed (rounded)
    for (int e = tid; e < 128 * 16; e += 256) {
        int kk = e >> 4, d4 = (e & 15) << 2;
        const float* ksrc = (kk < 64) ? (Klp + (size_t)kk * DD)
                                      : (Kgp + (size_t)(kk - 64) * DD);
        float4 v = to_tf32_4(*(const float4*)(ksrc + d4));
        *(float4*)&Ks[kk * 68 + d4] = v;
        const float* vsrc = (kk < 64) ? (Vlp + (size_t)kk * DD)
                                      : (Vgp + (size_t)(kk - 64) * DD);
        float4 wv = to_tf32_4(*(const float4*)(vsrc + d4));
        Vt[(d4 + 0) * 132 + kk] = wv.x;
        Vt[(d4 + 1) * 132 + kk] = wv.y;
        Vt[(d4 + 2) * 132 + kk] = wv.z;
        Vt[(d4 + 3) * 132 + kk] = wv.w;
    }
    __syncthreads();

    int w = tid >> 5, lane = tid & 31, grp = lane >> 2, tig = lane & 3;
    int mrow = (w & 3) * 16;

    // S = Q @ K^T * 1/8  : per warp m16 x n64, k64
    {
        int nb0 = (w >> 2) * 64;
        float acc[8][4];
        #pragma unroll
        for (int nt = 0; nt < 8; nt++)
            #pragma unroll
            for (int e = 0; e < 4; e++) acc[nt][e] = 0.f;
        #pragma unroll
        for (int k8 = 0; k8 < 8; k8++) {
            int k0 = k8 * 8;
            uint32_t af[4] = {
                bits(Qs[(mrow + grp)     * 68 + k0 + tig]),
                bits(Qs[(mrow + grp + 8) * 68 + k0 + tig]),
                bits(Qs[(mrow + grp)     * 68 + k0 + tig + 4]),
                bits(Qs[(mrow + grp + 8) * 68 + k0 + tig + 4]) };
            #pragma unroll
            for (int nt = 0; nt < 8; nt++) {
                int nb = nb0 + nt * 8 + grp;
                uint32_t bf[2] = { bits(Ks[nb * 68 + k0 + tig]),
                                   bits(Ks[nb * 68 + k0 + tig + 4]) };
                mma16n8k8(acc[nt], af, bf);
            }
        }
        #pragma unroll
        for (int nt = 0; nt < 8; nt++) {
            int c = nb0 + nt * 8 + 2 * tig;
            S[(mrow + grp)     * 132 + c]     = acc[nt][0] * 0.125f;
            S[(mrow + grp)     * 132 + c + 1] = acc[nt][1] * 0.125f;
            S[(mrow + grp + 8) * 132 + c]     = acc[nt][2] * 0.125f;
            S[(mrow + grp + 8) * 132 + c + 1] = acc[nt][3] * 0.125f;
        }
    }
    __syncthreads();

    // softmax per row; store probabilities rounded to tf32
    for (int m = w; m < 64; m += 8) {
        float* sr = &S[m * 132];
        float v0 = sr[lane], v1 = sr[lane + 32], v2 = sr[lane + 64], v3 = sr[lane + 96];
        float mx = fmaxf(fmaxf(v0, v1), fmaxf(v2, v3));
        #pragma unroll
        for (int o = 16; o; o >>= 1) mx = fmaxf(mx, __shfl_xor_sync(0xffffffffu, mx, o));
        float e0 = __expf(v0 - mx), e1 = __expf(v1 - mx);
        float e2 = __expf(v2 - mx), e3 = __expf(v3 - mx);
        float s = e0 + e1 + e2 + e3;
        #pragma unroll
        for (int o = 16; o; o >>= 1) s += __shfl_xor_sync(0xffffffffu, s, o);
        float inv = 1.f / s;
        sr[lane]      = to_tf32(e0 * inv);
        sr[lane + 32] = to_tf32(e1 * inv);
        sr[lane + 64] = to_tf32(e2 * inv);
        sr[lane + 96] = to_tf32(e3 * inv);
    }
    __syncthreads();

    // out = P @ V : per warp m16 x n32, k128
    {
        int nb0 = (w >> 2) * 32;
        float acc[4][4];
        #pragma unroll
        for (int nt = 0; nt < 4; nt++)
            #pragma unroll
            for (int e = 0; e < 4; e++) acc[nt][e] = 0.f;
        #pragma unroll
        for (int k8 = 0; k8 < 16; k8++) {
            int k0 = k8 * 8;
            uint32_t af[4] = {
                bits(S[(mrow + grp)     * 132 + k0 + tig]),
                bits(S[(mrow + grp + 8) * 132 + k0 + tig]),
                bits(S[(mrow + grp)     * 132 + k0 + tig + 4]),
                bits(S[(mrow + grp + 8) * 132 + k0 + tig + 4]) };
            #pragma unroll
            for (int nt = 0; nt < 4; nt++) {
                int d = nb0 + nt * 8 + grp;
                uint32_t bf[2] = { bits(Vt[d * 132 + k0 + tig]),
                                   bits(Vt[d * 132 + k0 + tig + 4]) };
                mma16n8k8(acc[nt], af, bf);
            }
        }
        #pragma unroll
        for (int nt = 0; nt < 4; nt++) {
            int c = nb0 + nt * 8 + 2 * tig;
            *(float2*)(Op + (size_t)(mrow + grp) * DD + c) =
                make_float2(acc[nt][0], acc[nt][1]);
            *(float2*)(Op + (size_t)(mrow + grp + 8) * DD + c) =
                make_float2(acc[nt][2], acc[nt][3]);
        }
    }
}

// ---------------- launch ----------------
#define SMEM_N1 ((2*128*36 + 1*2*128*36) * 4)   // 73728
#define SMEM_N2 ((2*128*36 + 2*2*128*36) * 4)   // 110592

extern "C" void kernel_launch(void* const* d_in, const int* in_sizes, int n_in,
                              void* d_out, int out_size) {
    const float* x       = (const float*)d_in[0];
    const float* f       = (const float*)d_in[1];
    const float* wq      = (const float*)d_in[2];
    const float* bq      = (const float*)d_in[3];
    const float* wk      = (const float*)d_in[4];
    const float* bk      = (const float*)d_in[5];
    const float* wv      = (const float*)d_in[6];
    const float* bv      = (const float*)d_in[7];
    const float* wo      = (const float*)d_in[8];
    const float* bo      = (const float*)d_in[9];
    const float* rw_w    = (const float*)d_in[10];
    const float* rw_b    = (const float*)d_in[11];
    const float* convk_w = (const float*)d_in[12];
    const float* convk_b = (const float*)d_in[13];
    const float* convv_w = (const float*)d_in[14];
    const float* convv_b = (const float*)d_in[15];
    const float* qn_g    = (const float*)d_in[16];
    const float* qn_b    = (const float*)d_in[17];
    const float* kn_g    = (const float*)d_in[18];
    const float* kn_b    = (const float*)d_in[19];
    const float* vn_g    = (const float*)d_in[20];
    const float* vn_b    = (const float*)d_in[21];
    float* out = (float*)d_out;

    float *qk, *kg, *vg, *Q, *Kl, *Vl, *Kg, *Vg, *O;
    float *st_qk, *st_x, *st_kg, *st_vg;
    float *fwq, *fwk, *fwv, *fwo, *frw, *fbq, *fbk, *fbv;
    cudaGetSymbolAddress((void**)&qk,    g_qk);
    cudaGetSymbolAddress((void**)&kg,    g_kg);
    cudaGetSymbolAddress((void**)&vg,    g_vg);
    cudaGetSymbolAddress((void**)&Q,     g_Q);
    cudaGetSymbolAddress((void**)&Kl,    g_Kl);
    cudaGetSymbolAddress((void**)&Vl,    g_Vl);
    cudaGetSymbolAddress((void**)&Kg,    g_Kg);
    cudaGetSymbolAddress((void**)&Vg,    g_Vg);
    cudaGetSymbolAddress((void**)&O,     g_O);
    cudaGetSymbolAddress((void**)&st_qk, g_st_qk);
    cudaGetSymbolAddress((void**)&st_x,  g_st_x);
    cudaGetSymbolAddress((void**)&st_kg, g_st_kg);
    cudaGetSymbolAddress((void**)&st_vg, g_st_vg);
    cudaGetSymbolAddress((void**)&fwq,   g_fwq);
    cudaGetSymbolAddress((void**)&fwk,   g_fwk);
    cudaGetSymbolAddress((void**)&fwv,   g_fwv);
    cudaGetSymbolAddress((void**)&fwo,   g_fwo);
    cudaGetSymbolAddress((void**)&frw,   g_frw);
    cudaGetSymbolAddress((void**)&fbq,   g_fbq);
    cudaGetSymbolAddress((void**)&fbk,   g_fbk);
    cudaGetSymbolAddress((void**)&fbv,   g_fbv);

    cudaFuncSetAttribute(attn_kernel, cudaFuncAttributeMaxDynamicSharedMemorySize,
                         ATTN_SMEM_BYTES);
    cudaFuncSetAttribute(mma_gemm<0,1>, cudaFuncAttributeMaxDynamicSharedMemorySize, SMEM_N1);
    cudaFuncSetAttribute(mma_gemm<1,2>, cudaFuncAttributeMaxDynamicSharedMemorySize, SMEM_N2);
    cudaFuncSetAttribute(mma_gemm<2,2>, cudaFuncAttributeMaxDynamicSharedMemorySize, SMEM_N2);
    cudaFuncSetAttribute(mma_gemm<3,2>, cudaFuncAttributeMaxDynamicSharedMemorySize, SMEM_N2);

    // 0) fold + round weights
    fold_w_kernel<<<64, 256>>>(wq, qn_g, qn_b, bq, fwq, fbq, DD, INCC);
    fold_w_kernel<<<64, 256>>>(wk, kn_g, kn_b, bk, fwk, fbk, DD, INCC);
    fold_w_kernel<<<64, 256>>>(wv, vn_g, vn_b, bv, fwv, fbv, DD, DD);
    fold_w_kernel<<<64, 256>>>(wo, nullptr, nullptr, nullptr, fwo, nullptr, DD, DD);
    fold_w_kernel<<<80, 256>>>(rw_w, nullptr, nullptr, nullptr, frw, nullptr, INCC, INCC);

    // 1) reweight: qk = concat(x,f) * sigmoid(concat @ rw_w^T + rw_b)
    mma_gemm<0,1><<<dim3(5, 256), 256, SMEM_N1>>>(
        x, f, frw, rw_b, nullptr, qk, MTOK, INCC, INCC);
    // 2) independent of reweight
    ln_stats_kernel<<<MTOK / 8, 256>>>(x, st_x, DD);
    dwconv_kernel<<<BT * GG, 256>>>(x, convv_w, convv_b, vg, DD);
    // 3) after reweight
    ln_stats_kernel<<<MTOK / 8, 256>>>(qk, st_qk, INCC);
    dwconv_kernel<<<BT * GG, 256>>>(qk, convk_w, convk_b, kg, INCC);
    ln_stats_kernel<<<(BT * NGLOB) / 8, 256>>>(kg, st_kg, INCC);
    ln_stats_kernel<<<(BT * NGLOB) / 8, 256>>>(vg, st_vg, DD);
    // 4) projections
    mma_gemm<1,2><<<dim3(2, 256), 256, SMEM_N2>>>(
        qk, nullptr, fwq, fbq, st_qk, Q, MTOK, DD, INCC);
    mma_gemm<1,2><<<dim3(2, 256), 256, SMEM_N2>>>(
        qk, nullptr, fwk, fbk, st_qk, Kl, MTOK, DD, INCC);
    mma_gemm<2,2><<<dim3(2, 4), 256, SMEM_N2>>>(
        kg, nullptr, fwk, fbk, st_kg, Kg, BT * NGLOB, DD, INCC);
    mma_gemm<1,2><<<dim3(2, 256), 256, SMEM_N2>>>(
        x, nullptr, fwv, fbv, st_x, Vl, MTOK, DD, DD);
    mma_gemm<2,2><<<dim3(2, 4), 256, SMEM_N2>>>(
        vg, nullptr, fwv, fbv, st_vg, Vg, BT * NGLOB, DD, DD);
    // 5) attention
    attn_kernel<<<BT * GG * NHEAD, 256, ATTN_SMEM_BYTES>>>(Q, Kl, Kg, Vl, Vg, O);
    // 6) out projection (window-reverse gather)
    mma_gemm<3,2><<<dim3(2, 256), 256, SMEM_N2>>>(
        O, nullptr, fwo, bo, nullptr, out, MTOK, DD, DD);
}

// round 5
// speedup vs baseline: 1.1799x; 1.1799x over previous
#include <cuda_runtime.h>
#include <cstdint>

// ---------------- problem constants ----------------
#define BT     8
#define NPIX   4096
#define DD     512
#define CFF    128
#define INCC   640
#define GG     64
#define NWIN   64
#define NGLOB  64
#define NHEAD  8
#define DHH    64
#define MTOK   32768

// ---------------- scratch ----------------
__device__ float g_qk [BT*NPIX*INCC];
__device__ float g_kg [BT*NGLOB*INCC];
__device__ float g_vg [BT*NGLOB*DD];
__device__ float g_Q  [BT*GG*NWIN*DD];
__device__ float g_Kl [BT*GG*NWIN*DD];
__device__ float g_Vl [BT*GG*NWIN*DD];
__device__ float g_Kg [BT*NGLOB*DD];
__device__ float g_Vg [BT*NGLOB*DD];
__device__ float g_O  [BT*GG*NWIN*DD];
__device__ float g_st_qk[MTOK*2];
__device__ float g_st_x [MTOK*2];
__device__ float g_st_kg[BT*NGLOB*2];
__device__ float g_st_vg[BT*NGLOB*2];
// folded / rounded weights
__device__ float g_fwq[DD*INCC];
__device__ float g_fwk[DD*INCC];
__device__ float g_fwv[DD*DD];
__device__ float g_fwo[DD*DD];
__device__ float g_frw[INCC*INCC];
__device__ float g_fbq[DD];
__device__ float g_fbk[DD];
__device__ float g_fbv[DD];

// ---------------- helpers ----------------
__device__ __forceinline__ int win_map(int r) {
    int b = r >> 12;
    int p = r & 4095;
    int h = p >> 6, w = p & 63;
    int g = ((h >> 3) << 3) | (w >> 3);
    int n = ((h & 7) << 3) | (w & 7);
    return (((b << 6) | g) << 6) | n;
}

__device__ __forceinline__ float to_tf32(float x) {
    uint32_t u;
    asm("cvt.rna.tf32.f32 %0, %1;" : "=r"(u) : "f"(x));
    return __uint_as_float(u);
}
__device__ __forceinline__ float4 to_tf32_4(float4 v) {
    v.x = to_tf32(v.x); v.y = to_tf32(v.y);
    v.z = to_tf32(v.z); v.w = to_tf32(v.w);
    return v;
}

__device__ __forceinline__ void mma16n8k8(float* d, const uint32_t* a, const uint32_t* b) {
    asm volatile(
        "mma.sync.aligned.m16n8k8.row.col.f32.tf32.tf32.f32 "
        "{%0,%1,%2,%3}, {%4,%5,%6,%7}, {%8,%9}, {%0,%1,%2,%3};"
        : "+f"(d[0]), "+f"(d[1]), "+f"(d[2]), "+f"(d[3])
        : "r"(a[0]), "r"(a[1]), "r"(a[2]), "r"(a[3]), "r"(b[0]), "r"(b[1]));
}

#define CP_ASYNC16(dst, src) \
    asm volatile("cp.async.ca.shared.global [%0], [%1], 16;" :: "r"(dst), "l"(src))
#define CP_COMMIT() asm volatile("cp.async.commit_group;" ::: "memory")
#define CP_WAIT0()  asm volatile("cp.async.wait_group 0;" ::: "memory")

__device__ __forceinline__ uint32_t bits(float f) { return __float_as_uint(f); }

// ---------------- weight fold: W' = rnd(W*gamma), b' = b + beta @ W^T ----------------
__global__ __launch_bounds__(256)
void fold_w_kernel(const float* __restrict__ W, const float* __restrict__ gamma,
                   const float* __restrict__ beta, const float* __restrict__ b,
                   float* __restrict__ Wo, float* __restrict__ bo, int N, int K) {
    int n = blockIdx.x * 8 + (threadIdx.x >> 5);
    if (n >= N) return;
    int lane = threadIdx.x & 31;
    const float* wr = W + (size_t)n * K;
    float* wor = Wo + (size_t)n * K;
    float acc = 0.f;
    for (int k = lane; k < K; k += 32) {
        float w = wr[k];
        if (beta) acc += beta[k] * w;
        wor[k] = to_tf32(gamma ? w * gamma[k] : w);
    }
    if (beta) {
        #pragma unroll
        for (int o = 16; o; o >>= 1) acc += __shfl_xor_sync(0xffffffffu, acc, o);
        if (lane == 0) bo[n] = b[n] + acc;
    }
}

// ---------------- LayerNorm stats: one warp per row ----------------
__global__ __launch_bounds__(256)
void ln_stats_kernel(const float* __restrict__ X, float* __restrict__ stats, int K) {
    int row = blockIdx.x * 8 + (threadIdx.x >> 5);
    int lane = threadIdx.x & 31;
    const float* xr = X + (size_t)row * K;
    float s = 0.f, ss = 0.f;
    for (int k = lane * 4; k < K; k += 128) {
        float4 v = *(const float4*)(xr + k);
        s  += v.x + v.y + v.z + v.w;
        ss += v.x * v.x + v.y * v.y + v.z * v.z + v.w * v.w;
    }
    #pragma unroll
    for (int o = 16; o; o >>= 1) {
        s  += __shfl_xor_sync(0xffffffffu, s, o);
        ss += __shfl_xor_sync(0xffffffffu, ss, o);
    }
    if (lane == 0) {
        float mean = s / K;
        float var = ss / K - mean * mean;
        *(float2*)(stats + (size_t)row * 2) = make_float2(mean, rsqrtf(var + 1e-5f));
    }
}

// ---------------- depthwise 8x8 stride-8 conv ----------------
__global__ __launch_bounds__(256)
void dwconv_kernel(const float* __restrict__ X, const float* __restrict__ Wc,
                   const float* __restrict__ bc, float* __restrict__ out, int C) {
    int bw = blockIdx.x;
    int b = bw >> 6;
    int g = bw & 63;
    int gh = g >> 3, gw = g & 7;
    const float* xb = X + (size_t)b * NPIX * C;
    for (int c = threadIdx.x; c < C; c += 256) {
        float s = bc[c];
        #pragma unroll
        for (int i = 0; i < 8; i++)
            #pragma unroll
            for (int j = 0; j < 8; j++)
                s += xb[(size_t)((gh * 8 + i) * 64 + (gw * 8 + j)) * C + c]
                     * Wc[c * 64 + i * 8 + j];
        out[(size_t)bw * C + c] = s;
    }
}

// ---------------- pipelined tf32 mma GEMM: C[M,N] = op(A)[M,K] @ W[N,K]^T ----------------
// CTA tile 128x128, K chunks of 32, cp.async double-buffered B, register-staged A.
// MODE 0: A split (x|f); out = a * sigmoid(acc+bias); spatial write
// MODE 1: LN-normalized A (gamma folded into W); +bias; row = win_map
// MODE 2: as MODE 1, identity output rows
// MODE 3: A gathered via win_map; +bias; spatial write
template<int MODE>
__global__ __launch_bounds__(256)
void mma_gemm(const float* __restrict__ A, const float* __restrict__ A2,
              const float* __restrict__ W, const float* __restrict__ bias,
              const float* __restrict__ stats, float* __restrict__ C,
              int M, int N, int K) {
    extern __shared__ float sm[];
    float* As = sm;                       // [2][128*36]
    float* Bs = sm + 2 * 128 * 36;        // [2][128*36]

    const int tid = threadIdx.x;
    const int m0 = blockIdx.y * 128;
    const int n0 = blockIdx.x * 128;
    const int q = tid & 7;
    const int lrow = tid >> 3;            // 0..31
    const int lane = tid & 31, grp = lane >> 2, tig = lane & 3;
    const int w = tid >> 5, mblk = (w & 3) * 32, nblk = (w >> 2) * 64;
    const int NC = K >> 5;

    const uint32_t bs_base = (uint32_t)__cvta_generic_to_shared(Bs);

    int arow[4]; float mean[4], rstd[4];
    #pragma unroll
    for (int i = 0; i < 4; i++) {
        int r = m0 + lrow + i * 32;
        arow[i] = (MODE == 3) ? win_map(r) : r;
        if (MODE == 1 || MODE == 2) {
            float2 st = *(const float2*)(stats + (size_t)r * 2);
            mean[i] = st.x; rstd[i] = st.y;
        }
    }

    float acc[2][8][4];
    #pragma unroll
    for (int mt = 0; mt < 2; mt++)
        #pragma unroll
        for (int nt = 0; nt < 8; nt++)
            #pragma unroll
            for (int e = 0; e < 4; e++) acc[mt][nt][e] = 0.f;

    auto issue_B = [&](int ch, int buf) {
        int gk = (ch << 5) + q * 4;
        #pragma unroll
        for (int i = 0; i < 4; i++) {
            int r = lrow + i * 32;
            const float* src = W + (size_t)(n0 + r) * K + gk;
            uint32_t dst = bs_base + (uint32_t)(((buf * 128 + r) * 36 + q * 4) * 4);
            CP_ASYNC16(dst, src);
        }
    };
    auto load_A = [&](int ch, float4* areg) {
        int k0 = ch << 5;
        int gk = k0 + q * 4;
        #pragma unroll
        for (int i = 0; i < 4; i++) {
            float4 av;
            if (MODE == 0) {
                if (k0 < 512) av = *(const float4*)(A  + (size_t)arow[i] * 512 + gk);
                else          av = *(const float4*)(A2 + (size_t)arow[i] * 128 + (gk - 512));
            } else {
                av = *(const float4*)(A + (size_t)arow[i] * K + gk);
                if (MODE == 1 || MODE == 2) {
                    av.x = (av.x - mean[i]) * rstd[i];
                    av.y = (av.y - mean[i]) * rstd[i];
                    av.z = (av.z - mean[i]) * rstd[i];
                    av.w = (av.w - mean[i]) * rstd[i];
                }
            }
            areg[i] = to_tf32_4(av);
        }
    };
    auto sts_A = [&](int buf, const float4* areg) {
        #pragma unroll
        for (int i = 0; i < 4; i++)
            *(float4*)&As[(buf * 128 + lrow + i * 32) * 36 + q * 4] = areg[i];
    };
    auto compute = [&](int buf) {
        const float* Ab = &As[buf * 128 * 36];
        const float* Bb = &Bs[buf * 128 * 36];
        #pragma unroll
        for (int k8 = 0; k8 < 4; k8++) {
            int k0 = k8 * 8;
            uint32_t af[2][4];
            #pragma unroll
            for (int mt = 0; mt < 2; mt++) {
                int rb = mblk + mt * 16;
                af[mt][0] = bits(Ab[(rb + grp)     * 36 + k0 + tig]);
                af[mt][1] = bits(Ab[(rb + grp + 8) * 36 + k0 + tig]);
                af[mt][2] = bits(Ab[(rb + grp)     * 36 + k0 + tig + 4]);
                af[mt][3] = bits(Ab[(rb + grp + 8) * 36 + k0 + tig + 4]);
            }
            #pragma unroll
            for (int nt = 0; nt < 8; nt++) {
                int nb = nblk + nt * 8 + grp;
                uint32_t bf[2] = { bits(Bb[nb * 36 + k0 + tig]),
                                   bits(Bb[nb * 36 + k0 + tig + 4]) };
                mma16n8k8(acc[0][nt], af[0], bf);
                mma16n8k8(acc[1][nt], af[1], bf);
            }
        }
    };

    // prologue
    issue_B(0, 0); CP_COMMIT();
    {
        float4 areg0[4];
        load_A(0, areg0);
        sts_A(0, areg0);
    }
    CP_WAIT0();
    __syncthreads();

    float4 areg[4];
    for (int ch = 0; ch < NC; ch++) {
        int buf = ch & 1;
        int nx = ch + 1;
        if (nx < NC) {
            issue_B(nx, buf ^ 1); CP_COMMIT();
            load_A(nx, areg);
        }
        compute(buf);
        if (nx < NC) {
            sts_A(buf ^ 1, areg);
            CP_WAIT0();
        }
        __syncthreads();
    }

    // epilogue
    #pragma unroll
    for (int mt = 0; mt < 2; mt++) {
        #pragma unroll
        for (int hr = 0; hr < 2; hr++) {
            int r = m0 + mblk + mt * 16 + grp + hr * 8;
            size_t orow = (MODE == 1) ? (size_t)win_map(r) : (size_t)r;
            float* crow = C + orow * (size_t)N;
            #pragma unroll
            for (int nt = 0; nt < 8; nt++) {
                int c = n0 + nblk + nt * 8 + 2 * tig;
                float y0 = acc[mt][nt][hr * 2 + 0] + bias[c];
                float y1 = acc[mt][nt][hr * 2 + 1] + bias[c + 1];
                if (MODE == 0) {
                    float a0 = (c < 512) ? A[(size_t)r * 512 + c]
                                         : A2[(size_t)r * 128 + (c - 512)];
                    float a1 = (c + 1 < 512) ? A[(size_t)r * 512 + c + 1]
                                             : A2[(size_t)r * 128 + (c + 1 - 512)];
                    y0 = a0 / (1.f + __expf(-y0));
                    y1 = a1 / (1.f + __expf(-y1));
                }
                *(float2*)(crow + c) = make_float2(y0, y1);
            }
        }
    }
}

// ---------------- attention with mma.sync tf32 ----------------
#define ATTN_SMEM_FLOATS (64*68 + 128*68 + 64*132 + 64*132)   // 29952
#define ATTN_SMEM_BYTES  (ATTN_SMEM_FLOATS * 4)               // 119808

__global__ __launch_bounds__(256)
void attn_kernel(const float* __restrict__ Q, const float* __restrict__ Kl,
                 const float* __restrict__ Kg, const float* __restrict__ Vl,
                 const float* __restrict__ Vg, float* __restrict__ O) {
    extern __shared__ float sm[];
    float* Qs = sm;                // [64][68]
    float* Ks = Qs + 64 * 68;      // [128][68]
    float* Vt = Ks + 128 * 68;     // [64][132]
    float* S  = Vt + 64 * 132;     // [64][132]

    int bid = blockIdx.x;
    int b = bid >> 9;
    int rem = bid & 511;
    int g = rem >> 3;
    int h = rem & 7;

    size_t wbase = ((size_t)(b * GG + g) * NWIN) * DD + (size_t)h * DHH;
    size_t gbase = ((size_t)b * NGLOB) * DD + (size_t)h * DHH;
    const float* Qp  = Q  + wbase;
    const float* Klp = Kl + wbase;
    const float* Vlp = Vl + wbase;
    const float* Kgp = Kg + gbase;
    const float* Vgp = Vg + gbase;
    float* Op = O + wbase;

    int tid = threadIdx.x;

    for (int e = tid; e < 64 * 16; e += 256) {
        int m = e >> 4, d4 = (e & 15) << 2;
        float4 v = to_tf32_4(*(const float4*)(Qp + (size_t)m * DD + d4));
        *(float4*)&Qs[m * 68 + d4] = v;
    }
    for (int e = tid; e < 128 * 16; e += 256) {
        int kk = e >> 4, d4 = (e & 15) << 2;
        const float* ksrc = (kk < 64) ? (Klp + (size_t)kk * DD)
                                      : (Kgp + (size_t)(kk - 64) * DD);
        float4 v = to_tf32_4(*(const float4*)(ksrc + d4));
        *(float4*)&Ks[kk * 68 + d4] = v;
        const float* vsrc = (kk < 64) ? (Vlp + (size_t)kk * DD)
                                      : (Vgp + (size_t)(kk - 64) * DD);
        float4 wv = to_tf32_4(*(const float4*)(vsrc + d4));
        Vt[(d4 + 0) * 132 + kk] = wv.x;
        Vt[(d4 + 1) * 132 + kk] = wv.y;
        Vt[(d4 + 2) * 132 + kk] = wv.z;
        Vt[(d4 + 3) * 132 + kk] = wv.w;
    }
    __syncthreads();

    int w = tid >> 5, lane = tid & 31, grp = lane >> 2, tig = lane & 3;
    int mrow = (w & 3) * 16;

    // S = Q @ K^T * 1/8 : per warp m16 x n64, k64
    {
        int nb0 = (w >> 2) * 64;
        float acc[8][4];
        #pragma unroll
        for (int nt = 0; nt < 8; nt++)
            #pragma unroll
            for (int e = 0; e < 4; e++) acc[nt][e] = 0.f;
        #pragma unroll
        for (int k8 = 0; k8 < 8; k8++) {
            int k0 = k8 * 8;
            uint32_t af[4] = {
                bits(Qs[(mrow + grp)     * 68 + k0 + tig]),
                bits(Qs[(mrow + grp + 8) * 68 + k0 + tig]),
                bits(Qs[(mrow + grp)     * 68 + k0 + tig + 4]),
                bits(Qs[(mrow + grp + 8) * 68 + k0 + tig + 4]) };
            #pragma unroll
            for (int nt = 0; nt < 8; nt++) {
                int nb = nb0 + nt * 8 + grp;
                uint32_t bf[2] = { bits(Ks[nb * 68 + k0 + tig]),
                                   bits(Ks[nb * 68 + k0 + tig + 4]) };
                mma16n8k8(acc[nt], af, bf);
            }
        }
        #pragma unroll
        for (int nt = 0; nt < 8; nt++) {
            int c = nb0 + nt * 8 + 2 * tig;
            S[(mrow + grp)     * 132 + c]     = acc[nt][0] * 0.125f;
            S[(mrow + grp)     * 132 + c + 1] = acc[nt][1] * 0.125f;
            S[(mrow + grp + 8) * 132 + c]     = acc[nt][2] * 0.125f;
            S[(mrow + grp + 8) * 132 + c + 1] = acc[nt][3] * 0.125f;
        }
    }
    __syncthreads();

    // softmax per row; probabilities rounded to tf32
    for (int m = w; m < 64; m += 8) {
        float* sr = &S[m * 132];
        float v0 = sr[lane], v1 = sr[lane + 32], v2 = sr[lane + 64], v3 = sr[lane + 96];
        float mx = fmaxf(fmaxf(v0, v1), fmaxf(v2, v3));
        #pragma unroll
        for (int o = 16; o; o >>= 1) mx = fmaxf(mx, __shfl_xor_sync(0xffffffffu, mx, o));
        float e0 = __expf(v0 - mx), e1 = __expf(v1 - mx);
        float e2 = __expf(v2 - mx), e3 = __expf(v3 - mx);
        float s = e0 + e1 + e2 + e3;
        #pragma unroll
        for (int o = 16; o; o >>= 1) s += __shfl_xor_sync(0xffffffffu, s, o);
        float inv = 1.f / s;
        sr[lane]      = to_tf32(e0 * inv);
        sr[lane + 32] = to_tf32(e1 * inv);
        sr[lane + 64] = to_tf32(e2 * inv);
        sr[lane + 96] = to_tf32(e3 * inv);
    }
    __syncthreads();

    // out = P @ V : per warp m16 x n32, k128
    {
        int nb0 = (w >> 2) * 32;
        float acc[4][4];
        #pragma unroll
        for (int nt = 0; nt < 4; nt++)
            #pragma unroll
            for (int e = 0; e < 4; e++) acc[nt][e] = 0.f;
        #pragma unroll
        for (int k8 = 0; k8 < 16; k8++) {
            int k0 = k8 * 8;
            uint32_t af[4] = {
                bits(S[(mrow + grp)     * 132 + k0 + tig]),
                bits(S[(mrow + grp + 8) * 132 + k0 + tig]),
                bits(S[(mrow + grp)     * 132 + k0 + tig + 4]),
                bits(S[(mrow + grp + 8) * 132 + k0 + tig + 4]) };
            #pragma unroll
            for (int nt = 0; nt < 4; nt++) {
                int d = nb0 + nt * 8 + grp;
                uint32_t bf[2] = { bits(Vt[d * 132 + k0 + tig]),
                                   bits(Vt[d * 132 + k0 + tig + 4]) };
                mma16n8k8(acc[nt], af, bf);
            }
        }
        #pragma unroll
        for (int nt = 0; nt < 4; nt++) {
            int c = nb0 + nt * 8 + 2 * tig;
            *(float2*)(Op + (size_t)(mrow + grp) * DD + c) =
                make_float2(acc[nt][0], acc[nt][1]);
            *(float2*)(Op + (size_t)(mrow + grp + 8) * DD + c) =
                make_float2(acc[nt][2], acc[nt][3]);
        }
    }
}

// ---------------- launch ----------------
#define SMEM_GEMM ((2*128*36 + 2*128*36) * 4)   // 73728

extern "C" void kernel_launch(void* const* d_in, const int* in_sizes, int n_in,
                              void* d_out, int out_size) {
    const float* x       = (const float*)d_in[0];
    const float* f       = (const float*)d_in[1];
    const float* wq      = (const float*)d_in[2];
    const float* bq      = (const float*)d_in[3];
    const float* wk      = (const float*)d_in[4];
    const float* bk      = (const float*)d_in[5];
    const float* wv      = (const float*)d_in[6];
    const float* bv      = (const float*)d_in[7];
    const float* wo      = (const float*)d_in[8];
    const float* bo      = (const float*)d_in[9];
    const float* rw_w    = (const float*)d_in[10];
    const float* rw_b    = (const float*)d_in[11];
    const float* convk_w = (const float*)d_in[12];
    const float* convk_b = (const float*)d_in[13];
    const float* convv_w = (const float*)d_in[14];
    const float* convv_b = (const float*)d_in[15];
    const float* qn_g    = (const float*)d_in[16];
    const float* qn_b    = (const float*)d_in[17];
    const float* kn_g    = (const float*)d_in[18];
    const float* kn_b    = (const float*)d_in[19];
    const float* vn_g    = (const float*)d_in[20];
    const float* vn_b    = (const float*)d_in[21];
    float* out = (float*)d_out;

    float *qk, *kg, *vg, *Q, *Kl, *Vl, *Kg, *Vg, *O;
    float *st_qk, *st_x, *st_kg, *st_vg;
    float *fwq, *fwk, *fwv, *fwo, *frw, *fbq, *fbk, *fbv;
    cudaGetSymbolAddress((void**)&qk,    g_qk);
    cudaGetSymbolAddress((void**)&kg,    g_kg);
    cudaGetSymbolAddress((void**)&vg,    g_vg);
    cudaGetSymbolAddress((void**)&Q,     g_Q);
    cudaGetSymbolAddress((void**)&Kl,    g_Kl);
    cudaGetSymbolAddress((void**)&Vl,    g_Vl);
    cudaGetSymbolAddress((void**)&Kg,    g_Kg);
    cudaGetSymbolAddress((void**)&Vg,    g_Vg);
    cudaGetSymbolAddress((void**)&O,     g_O);
    cudaGetSymbolAddress((void**)&st_qk, g_st_qk);
    cudaGetSymbolAddress((void**)&st_x,  g_st_x);
    cudaGetSymbolAddress((void**)&st_kg, g_st_kg);
    cudaGetSymbolAddress((void**)&st_vg, g_st_vg);
    cudaGetSymbolAddress((void**)&fwq,   g_fwq);
    cudaGetSymbolAddress((void**)&fwk,   g_fwk);
    cudaGetSymbolAddress((void**)&fwv,   g_fwv);
    cudaGetSymbolAddress((void**)&fwo,   g_fwo);
    cudaGetSymbolAddress((void**)&frw,   g_frw);
    cudaGetSymbolAddress((void**)&fbq,   g_fbq);
    cudaGetSymbolAddress((void**)&fbk,   g_fbk);
    cudaGetSymbolAddress((void**)&fbv,   g_fbv);

    cudaFuncSetAttribute(attn_kernel, cudaFuncAttributeMaxDynamicSharedMemorySize,
                         ATTN_SMEM_BYTES);
    cudaFuncSetAttribute(mma_gemm<0>, cudaFuncAttributeMaxDynamicSharedMemorySize, SMEM_GEMM);
    cudaFuncSetAttribute(mma_gemm<1>, cudaFuncAttributeMaxDynamicSharedMemorySize, SMEM_GEMM);
    cudaFuncSetAttribute(mma_gemm<2>, cudaFuncAttributeMaxDynamicSharedMemorySize, SMEM_GEMM);
    cudaFuncSetAttribute(mma_gemm<3>, cudaFuncAttributeMaxDynamicSharedMemorySize, SMEM_GEMM);

    // 0) fold + round weights
    fold_w_kernel<<<64, 256>>>(wq, qn_g, qn_b, bq, fwq, fbq, DD, INCC);
    fold_w_kernel<<<64, 256>>>(wk, kn_g, kn_b, bk, fwk, fbk, DD, INCC);
    fold_w_kernel<<<64, 256>>>(wv, vn_g, vn_b, bv, fwv, fbv, DD, DD);
    fold_w_kernel<<<64, 256>>>(wo, nullptr, nullptr, nullptr, fwo, nullptr, DD, DD);
    fold_w_kernel<<<80, 256>>>(rw_w, nullptr, nullptr, nullptr, frw, nullptr, INCC, INCC);

    // 1) reweight: qk = concat(x,f) * sigmoid(concat @ rw_w^T + rw_b)
    mma_gemm<0><<<dim3(5, 256), 256, SMEM_GEMM>>>(
        x, f, frw, rw_b, nullptr, qk, MTOK, INCC, INCC);
    // 2) independent of reweight
    ln_stats_kernel<<<MTOK / 8, 256>>>(x, st_x, DD);
    dwconv_kernel<<<BT * GG, 256>>>(x, convv_w, convv_b, vg, DD);
    // 3) after reweight
    ln_stats_kernel<<<MTOK / 8, 256>>>(qk, st_qk, INCC);
    dwconv_kernel<<<BT * GG, 256>>>(qk, convk_w, convk_b, kg, INCC);
    ln_stats_kernel<<<(BT * NGLOB) / 8, 256>>>(kg, st_kg, INCC);
    ln_stats_kernel<<<(BT * NGLOB) / 8, 256>>>(vg, st_vg, DD);
    // 4) projections
    mma_gemm<1><<<dim3(4, 256), 256, SMEM_GEMM>>>(
        qk, nullptr, fwq, fbq, st_qk, Q, MTOK, DD, INCC);
    mma_gemm<1><<<dim3(4, 256), 256, SMEM_GEMM>>>(
        qk, nullptr, fwk, fbk, st_qk, Kl, MTOK, DD, INCC);
    mma_gemm<2><<<dim3(4, 4), 256, SMEM_GEMM>>>(
        kg, nullptr, fwk, fbk, st_kg, Kg, BT * NGLOB, DD, INCC);
    mma_gemm<1><<<dim3(4, 256), 256, SMEM_GEMM>>>(
        x, nullptr, fwv, fbv, st_x, Vl, MTOK, DD, DD);
    mma_gemm<2><<<dim3(4, 4), 256, SMEM_GEMM>>>(
        vg, nullptr, fwv, fbv, st_vg, Vg, BT * NGLOB, DD, DD);
    // 5) attention
    attn_kernel<<<BT * GG * NHEAD, 256, ATTN_SMEM_BYTES>>>(Q, Kl, Kg, Vl, Vg, O);
    // 6) out projection (window-reverse gather)
    mma_gemm<3><<<dim3(4, 256), 256, SMEM_GEMM>>>(
        O, nullptr, fwo, bo, nullptr, out, MTOK, DD, DD);
}

// round 6
// speedup vs baseline: 1.2602x; 1.0680x over previous
#include <cuda_runtime.h>
#include <cstdint>

// ---------------- problem constants ----------------
#define BT     8
#define NPIX   4096
#define DD     512
#define CFF    128
#define INCC   640
#define GG     64
#define NWIN   64
#define NGLOB  64
#define NHEAD  8
#define DHH    64
#define MTOK   32768

// ---------------- scratch ----------------
__device__ float g_qk [BT*NPIX*INCC];
__device__ float g_kg [BT*NGLOB*INCC];
__device__ float g_vg [BT*NGLOB*DD];
__device__ float g_Q  [BT*GG*NWIN*DD];
__device__ float g_Kl [BT*GG*NWIN*DD];
__device__ float g_Vl [BT*GG*NWIN*DD];
__device__ float g_Kg [BT*NGLOB*DD];
__device__ float g_Vg [BT*NGLOB*DD];
__device__ float g_O  [BT*GG*NWIN*DD];
__device__ float g_st_qk[MTOK*2];
__device__ float g_st_x [MTOK*2];
__device__ float g_st_kg[BT*NGLOB*2];
__device__ float g_st_vg[BT*NGLOB*2];
// folded / rounded weights
__device__ float g_fwqk[2*DD*INCC];   // [wq; wk] with gamma folded
__device__ float g_fbqk[2*DD];
__device__ float g_fwv[DD*DD];
__device__ float g_fwo[DD*DD];
__device__ float g_frw[INCC*INCC];
__device__ float g_fbv[DD];

// ---------------- helpers ----------------
__device__ __forceinline__ int win_map(int r) {
    int b = r >> 12;
    int p = r & 4095;
    int h = p >> 6, w = p & 63;
    int g = ((h >> 3) << 3) | (w >> 3);
    int n = ((h & 7) << 3) | (w & 7);
    return (((b << 6) | g) << 6) | n;
}

__device__ __forceinline__ float to_tf32(float x) {
    uint32_t u;
    asm("cvt.rna.tf32.f32 %0, %1;" : "=r"(u) : "f"(x));
    return __uint_as_float(u);
}
__device__ __forceinline__ float4 to_tf32_4(float4 v) {
    v.x = to_tf32(v.x); v.y = to_tf32(v.y);
    v.z = to_tf32(v.z); v.w = to_tf32(v.w);
    return v;
}

__device__ __forceinline__ void mma16n8k8(float* d, const uint32_t* a, const uint32_t* b) {
    asm volatile(
        "mma.sync.aligned.m16n8k8.row.col.f32.tf32.tf32.f32 "
        "{%0,%1,%2,%3}, {%4,%5,%6,%7}, {%8,%9}, {%0,%1,%2,%3};"
        : "+f"(d[0]), "+f"(d[1]), "+f"(d[2]), "+f"(d[3])
        : "r"(a[0]), "r"(a[1]), "r"(a[2]), "r"(a[3]), "r"(b[0]), "r"(b[1]));
}

__device__ __forceinline__ void ldsm_x4(uint32_t* r, uint32_t addr) {
    asm volatile("ldmatrix.sync.aligned.m8n8.x4.shared.b16 {%0,%1,%2,%3}, [%4];"
                 : "=r"(r[0]), "=r"(r[1]), "=r"(r[2]), "=r"(r[3]) : "r"(addr));
}

#define CP_ASYNC16(dst, src) \
    asm volatile("cp.async.ca.shared.global [%0], [%1], 16;" :: "r"(dst), "l"(src))
#define CP_COMMIT() asm volatile("cp.async.commit_group;" ::: "memory")
#define CP_WAIT0()  asm volatile("cp.async.wait_group 0;" ::: "memory")

// ---------------- weight fold ----------------
__global__ __launch_bounds__(256)
void fold_w_kernel(const float* __restrict__ W, const float* __restrict__ gamma,
                   const float* __restrict__ beta, const float* __restrict__ b,
                   float* __restrict__ Wo, float* __restrict__ bo, int N, int K) {
    int n = blockIdx.x * 8 + (threadIdx.x >> 5);
    if (n >= N) return;
    int lane = threadIdx.x & 31;
    const float* wr = W + (size_t)n * K;
    float* wor = Wo + (size_t)n * K;
    float acc = 0.f;
    for (int k = lane; k < K; k += 32) {
        float w = wr[k];
        if (beta) acc += beta[k] * w;
        wor[k] = to_tf32(gamma ? w * gamma[k] : w);
    }
    if (beta) {
        #pragma unroll
        for (int o = 16; o; o >>= 1) acc += __shfl_xor_sync(0xffffffffu, acc, o);
        if (lane == 0) bo[n] = b[n] + acc;
    }
}

// ---------------- LayerNorm stats ----------------
__global__ __launch_bounds__(256)
void ln_stats_kernel(const float* __restrict__ X, float* __restrict__ stats, int K) {
    int row = blockIdx.x * 8 + (threadIdx.x >> 5);
    int lane = threadIdx.x & 31;
    const float* xr = X + (size_t)row * K;
    float s = 0.f, ss = 0.f;
    for (int k = lane * 4; k < K; k += 128) {
        float4 v = *(const float4*)(xr + k);
        s  += v.x + v.y + v.z + v.w;
        ss += v.x * v.x + v.y * v.y + v.z * v.z + v.w * v.w;
    }
    #pragma unroll
    for (int o = 16; o; o >>= 1) {
        s  += __shfl_xor_sync(0xffffffffu, s, o);
        ss += __shfl_xor_sync(0xffffffffu, ss, o);
    }
    if (lane == 0) {
        float mean = s / K;
        float var = ss / K - mean * mean;
        *(float2*)(stats + (size_t)row * 2) = make_float2(mean, rsqrtf(var + 1e-5f));
    }
}

// ---------------- depthwise 8x8 stride-8 conv ----------------
__global__ __launch_bounds__(256)
void dwconv_kernel(const float* __restrict__ X, const float* __restrict__ Wc,
                   const float* __restrict__ bc, float* __restrict__ out, int C) {
    int bw = blockIdx.x;
    int b = bw >> 6;
    int g = bw & 63;
    int gh = g >> 3, gw = g & 7;
    const float* xb = X + (size_t)b * NPIX * C;
    for (int c = threadIdx.x; c < C; c += 256) {
        float s = bc[c];
        #pragma unroll
        for (int i = 0; i < 8; i++)
            #pragma unroll
            for (int j = 0; j < 8; j++)
                s += xb[(size_t)((gh * 8 + i) * 64 + (gw * 8 + j)) * C + c]
                     * Wc[c * 64 + i * 8 + j];
        out[(size_t)bw * C + c] = s;
    }
}

// ---------------- pipelined tf32 mma GEMM (ldmatrix fragments) ----------------
// C[M,N] = op(A)[M,K] @ W[N,K]^T ; CTA tile 128x128.
// MODE 0: A split (x|f); out = a * sigmoid(acc+bias); spatial write
// MODE 1: LN-normalized A; +bias; output row = win_map
// MODE 2: as MODE 1, identity output rows
// MODE 3: A gathered via win_map; +bias; spatial write
// SPLIT: columns [0,512) -> C, [512,1024) -> C2 (merged QK projection)
template<int MODE, int SPLIT>
__global__ __launch_bounds__(256)
void mma_gemm(const float* __restrict__ A, const float* __restrict__ A2,
              const float* __restrict__ W, const float* __restrict__ bias,
              const float* __restrict__ stats, float* __restrict__ C,
              float* __restrict__ C2, int M, int N, int K, int ldc) {
    extern __shared__ float sm[];
    float* As = sm;                       // [2][128*36]
    float* Bs = sm + 2 * 128 * 36;        // [2][128*36]

    const int tid = threadIdx.x;
    const int m0 = blockIdx.y * 128;
    const int n0 = blockIdx.x * 128;
    const int q = tid & 7;
    const int lrow = tid >> 3;
    const int lane = tid & 31, grp = lane >> 2, tig = lane & 3;
    const int w = tid >> 5, mblk = (w & 3) * 32, nblk = (w >> 2) * 64;
    const int NC = K >> 5;

    const uint32_t as_s = (uint32_t)__cvta_generic_to_shared(As);
    const uint32_t bs_s = (uint32_t)__cvta_generic_to_shared(Bs);

    // ldmatrix per-thread offsets (bytes, within one buffer, k0 = 0)
    const uint32_t aoff0 = (uint32_t)(((mblk + (lane & 15)) * 36 + (lane >> 4) * 4) * 4);
    const uint32_t aoff1 = aoff0 + (uint32_t)(16 * 36 * 4);
    const uint32_t boff  = (uint32_t)(((nblk + (lane & 7) + ((lane & 16) ? 8 : 0)) * 36
                                       + ((lane & 8) ? 4 : 0)) * 4);

    int arow[4]; float mean[4], rstd[4];
    #pragma unroll
    for (int i = 0; i < 4; i++) {
        int r = m0 + lrow + i * 32;
        arow[i] = (MODE == 3) ? win_map(r) : r;
        if (MODE == 1 || MODE == 2) {
            float2 st = *(const float2*)(stats + (size_t)r * 2);
            mean[i] = st.x; rstd[i] = st.y;
        }
    }

    float acc[2][8][4];
    #pragma unroll
    for (int mt = 0; mt < 2; mt++)
        #pragma unroll
        for (int nt = 0; nt < 8; nt++)
            #pragma unroll
            for (int e = 0; e < 4; e++) acc[mt][nt][e] = 0.f;

    auto issue_B = [&](int ch, int buf) {
        int gk = (ch << 5) + q * 4;
        #pragma unroll
        for (int i = 0; i < 4; i++) {
            int r = lrow + i * 32;
            const float* src = W + (size_t)(n0 + r) * K + gk;
            uint32_t dst = bs_s + (uint32_t)(((buf * 128 + r) * 36 + q * 4) * 4);
            CP_ASYNC16(dst, src);
        }
    };
    auto load_A = [&](int ch, float4* areg) {
        int k0 = ch << 5;
        int gk = k0 + q * 4;
        #pragma unroll
        for (int i = 0; i < 4; i++) {
            float4 av;
            if (MODE == 0) {
                if (k0 < 512) av = *(const float4*)(A  + (size_t)arow[i] * 512 + gk);
                else          av = *(const float4*)(A2 + (size_t)arow[i] * 128 + (gk - 512));
            } else {
                av = *(const float4*)(A + (size_t)arow[i] * K + gk);
                if (MODE == 1 || MODE == 2) {
                    av.x = (av.x - mean[i]) * rstd[i];
                    av.y = (av.y - mean[i]) * rstd[i];
                    av.z = (av.z - mean[i]) * rstd[i];
                    av.w = (av.w - mean[i]) * rstd[i];
                }
            }
            areg[i] = to_tf32_4(av);
        }
    };
    auto sts_A = [&](int buf, const float4* areg) {
        #pragma unroll
        for (int i = 0; i < 4; i++)
            *(float4*)&As[(buf * 128 + lrow + i * 32) * 36 + q * 4] = areg[i];
    };
    auto compute = [&](int buf) {
        uint32_t abase = as_s + (uint32_t)(buf * 128 * 36 * 4);
        uint32_t bbase = bs_s + (uint32_t)(buf * 128 * 36 * 4);
        #pragma unroll
        for (int k8 = 0; k8 < 4; k8++) {
            uint32_t kb = (uint32_t)(k8 * 32);
            uint32_t af0[4], af1[4];
            ldsm_x4(af0, abase + aoff0 + kb);
            ldsm_x4(af1, abase + aoff1 + kb);
            #pragma unroll
            for (int p = 0; p < 4; p++) {
                uint32_t bf[4];
                ldsm_x4(bf, bbase + boff + (uint32_t)(p * 16 * 36 * 4) + kb);
                mma16n8k8(acc[0][2 * p],     af0, bf);
                mma16n8k8(acc[1][2 * p],     af1, bf);
                mma16n8k8(acc[0][2 * p + 1], af0, bf + 2);
                mma16n8k8(acc[1][2 * p + 1], af1, bf + 2);
            }
        }
    };

    // prologue
    issue_B(0, 0); CP_COMMIT();
    {
        float4 areg0[4];
        load_A(0, areg0);
        sts_A(0, areg0);
    }
    CP_WAIT0();
    __syncthreads();

    float4 areg[4];
    for (int ch = 0; ch < NC; ch++) {
        int buf = ch & 1;
        int nx = ch + 1;
        if (nx < NC) {
            issue_B(nx, buf ^ 1); CP_COMMIT();
            load_A(nx, areg);
        }
        compute(buf);
        if (nx < NC) {
            sts_A(buf ^ 1, areg);
            CP_WAIT0();
        }
        __syncthreads();
    }

    // epilogue
    #pragma unroll
    for (int mt = 0; mt < 2; mt++) {
        #pragma unroll
        for (int hr = 0; hr < 2; hr++) {
            int r = m0 + mblk + mt * 16 + grp + hr * 8;
            size_t orow = (MODE == 1) ? (size_t)win_map(r) : (size_t)r;
            #pragma unroll
            for (int nt = 0; nt < 8; nt++) {
                int c = n0 + nblk + nt * 8 + 2 * tig;
                float y0 = acc[mt][nt][hr * 2 + 0] + bias[c];
                float y1 = acc[mt][nt][hr * 2 + 1] + bias[c + 1];
                float* base = C;
                int cc = c;
                if (SPLIT) {
                    base = (c < 512) ? C : C2;
                    cc = c & 511;
                }
                if (MODE == 0) {
                    float a0 = (c < 512) ? A[(size_t)r * 512 + c]
                                         : A2[(size_t)r * 128 + (c - 512)];
                    float a1 = (c + 1 < 512) ? A[(size_t)r * 512 + c + 1]
                                             : A2[(size_t)r * 128 + (c + 1 - 512)];
                    y0 = a0 / (1.f + __expf(-y0));
                    y1 = a1 / (1.f + __expf(-y1));
                }
                *(float2*)(base + orow * (size_t)ldc + cc) = make_float2(y0, y1);
            }
        }
    }
}

// ---------------- attention with mma.sync tf32 + ldmatrix ----------------
#define ATTN_SMEM_FLOATS (64*68 + 128*68 + 64*132 + 64*132)   // 29952
#define ATTN_SMEM_BYTES  (ATTN_SMEM_FLOATS * 4)               // 119808

__global__ __launch_bounds__(256)
void attn_kernel(const float* __restrict__ Q, const float* __restrict__ Kl,
                 const float* __restrict__ Kg, const float* __restrict__ Vl,
                 const float* __restrict__ Vg, float* __restrict__ O) {
    extern __shared__ float sm[];
    float* Qs = sm;                // [64][68]
    float* Ks = Qs + 64 * 68;      // [128][68]
    float* Vt = Ks + 128 * 68;     // [64][132]  (d, key)
    float* S  = Vt + 64 * 132;     // [64][132]  (m, key)

    int bid = blockIdx.x;
    int b = bid >> 9;
    int rem = bid & 511;
    int g = rem >> 3;
    int h = rem & 7;

    size_t wbase = ((size_t)(b * GG + g) * NWIN) * DD + (size_t)h * DHH;
    size_t gbase = ((size_t)b * NGLOB) * DD + (size_t)h * DHH;
    const float* Qp  = Q  + wbase;
    const float* Klp = Kl + wbase;
    const float* Vlp = Vl + wbase;
    const float* Kgp = Kg + gbase;
    const float* Vgp = Vg + gbase;
    float* Op = O + wbase;

    int tid = threadIdx.x;

    for (int e = tid; e < 64 * 16; e += 256) {
        int m = e >> 4, d4 = (e & 15) << 2;
        float4 v = to_tf32_4(*(const float4*)(Qp + (size_t)m * DD + d4));
        *(float4*)&Qs[m * 68 + d4] = v;
    }
    for (int e = tid; e < 128 * 16; e += 256) {
        int kk = e >> 4, d4 = (e & 15) << 2;
        const float* ksrc = (kk < 64) ? (Klp + (size_t)kk * DD)
                                      : (Kgp + (size_t)(kk - 64) * DD);
        float4 v = to_tf32_4(*(const float4*)(ksrc + d4));
        *(float4*)&Ks[kk * 68 + d4] = v;
        const float* vsrc = (kk < 64) ? (Vlp + (size_t)kk * DD)
                                      : (Vgp + (size_t)(kk - 64) * DD);
        float4 wv = to_tf32_4(*(const float4*)(vsrc + d4));
        Vt[(d4 + 0) * 132 + kk] = wv.x;
        Vt[(d4 + 1) * 132 + kk] = wv.y;
        Vt[(d4 + 2) * 132 + kk] = wv.z;
        Vt[(d4 + 3) * 132 + kk] = wv.w;
    }
    __syncthreads();

    const uint32_t qs_s = (uint32_t)__cvta_generic_to_shared(Qs);
    const uint32_t ks_s = (uint32_t)__cvta_generic_to_shared(Ks);
    const uint32_t vt_s = (uint32_t)__cvta_generic_to_shared(Vt);
    const uint32_t s_s  = (uint32_t)__cvta_generic_to_shared(S);

    int w = tid >> 5, lane = tid & 31, grp = lane >> 2, tig = lane & 3;
    int mrow = (w & 3) * 16;

    // S = Q @ K^T * 1/8 : per warp m16 x n64, k64
    {
        int nb0 = (w >> 2) * 64;
        const uint32_t aoff = qs_s +
            (uint32_t)(((mrow + (lane & 15)) * 68 + (lane >> 4) * 4) * 4);
        const uint32_t boff = ks_s +
            (uint32_t)(((nb0 + (lane & 7) + ((lane & 16) ? 8 : 0)) * 68
                        + ((lane & 8) ? 4 : 0)) * 4);
        float acc[8][4];
        #pragma unroll
        for (int nt = 0; nt < 8; nt++)
            #pragma unroll
            for (int e = 0; e < 4; e++) acc[nt][e] = 0.f;
        #pragma unroll
        for (int k8 = 0; k8 < 8; k8++) {
            uint32_t kb = (uint32_t)(k8 * 32);
            uint32_t af[4];
            ldsm_x4(af, aoff + kb);
            #pragma unroll
            for (int p = 0; p < 4; p++) {
                uint32_t bf[4];
                ldsm_x4(bf, boff + (uint32_t)(p * 16 * 68 * 4) + kb);
                mma16n8k8(acc[2 * p],     af, bf);
                mma16n8k8(acc[2 * p + 1], af, bf + 2);
            }
        }
        #pragma unroll
        for (int nt = 0; nt < 8; nt++) {
            int c = nb0 + nt * 8 + 2 * tig;
            S[(mrow + grp)     * 132 + c]     = acc[nt][0] * 0.125f;
            S[(mrow + grp)     * 132 + c + 1] = acc[nt][1] * 0.125f;
            S[(mrow + grp + 8) * 132 + c]     = acc[nt][2] * 0.125f;
            S[(mrow + grp + 8) * 132 + c + 1] = acc[nt][3] * 0.125f;
        }
    }
    __syncthreads();

    // softmax per row; probabilities rounded to tf32
    for (int m = w; m < 64; m += 8) {
        float* sr = &S[m * 132];
        float v0 = sr[lane], v1 = sr[lane + 32], v2 = sr[lane + 64], v3 = sr[lane + 96];
        float mx = fmaxf(fmaxf(v0, v1), fmaxf(v2, v3));
        #pragma unroll
        for (int o = 16; o; o >>= 1) mx = fmaxf(mx, __shfl_xor_sync(0xffffffffu, mx, o));
        float e0 = __expf(v0 - mx), e1 = __expf(v1 - mx);
        float e2 = __expf(v2 - mx), e3 = __expf(v3 - mx);
        float s = e0 + e1 + e2 + e3;
        #pragma unroll
        for (int o = 16; o; o >>= 1) s += __shfl_xor_sync(0xffffffffu, s, o);
        float inv = 1.f / s;
        sr[lane]      = to_tf32(e0 * inv);
        sr[lane + 32] = to_tf32(e1 * inv);
        sr[lane + 64] = to_tf32(e2 * inv);
        sr[lane + 96] = to_tf32(e3 * inv);
    }
    __syncthreads();

    // out = P @ V : per warp m16 x n32, k128
    {
        int nb0 = (w >> 2) * 32;
        const uint32_t aoff = s_s +
            (uint32_t)(((mrow + (lane & 15)) * 132 + (lane >> 4) * 4) * 4);
        const uint32_t boff = vt_s +
            (uint32_t)(((nb0 + (lane & 7) + ((lane & 16) ? 8 : 0)) * 132
                        + ((lane & 8) ? 4 : 0)) * 4);
        float acc[4][4];
        #pragma unroll
        for (int nt = 0; nt < 4; nt++)
            #pragma unroll
            for (int e = 0; e < 4; e++) acc[nt][e] = 0.f;
        #pragma unroll
        for (int k8 = 0; k8 < 16; k8++) {
            uint32_t kb = (uint32_t)(k8 * 32);
            uint32_t af[4];
            ldsm_x4(af, aoff + kb);
            #pragma unroll
            for (int p = 0; p < 2; p++) {
                uint32_t bf[4];
                ldsm_x4(bf, boff + (uint32_t)(p * 16 * 132 * 4) + kb);
                mma16n8k8(acc[2 * p],     af, bf);
                mma16n8k8(acc[2 * p + 1], af, bf + 2);
            }
        }
        #pragma unroll
        for (int nt = 0; nt < 4; nt++) {
            int c = nb0 + nt * 8 + 2 * tig;
            *(float2*)(Op + (size_t)(mrow + grp) * DD + c) =
                make_float2(acc[nt][0], acc[nt][1]);
            *(float2*)(Op + (size_t)(mrow + grp + 8) * DD + c) =
                make_float2(acc[nt][2], acc[nt][3]);
        }
    }
}

// ---------------- launch ----------------
#define SMEM_GEMM ((2*128*36 + 2*128*36) * 4)   // 73728

extern "C" void kernel_launch(void* const* d_in, const int* in_sizes, int n_in,
                              void* d_out, int out_size) {
    const float* x       = (const float*)d_in[0];
    const float* f       = (const float*)d_in[1];
    const float* wq      = (const float*)d_in[2];
    const float* bq      = (const float*)d_in[3];
    const float* wk      = (const float*)d_in[4];
    const float* bk      = (const float*)d_in[5];
    const float* wv      = (const float*)d_in[6];
    const float* bv      = (const float*)d_in[7];
    const float* wo      = (const float*)d_in[8];
    const float* bo      = (const float*)d_in[9];
    const float* rw_w    = (const float*)d_in[10];
    const float* rw_b    = (const float*)d_in[11];
    const float* convk_w = (const float*)d_in[12];
    const float* convk_b = (const float*)d_in[13];
    const float* convv_w = (const float*)d_in[14];
    const float* convv_b = (const float*)d_in[15];
    const float* qn_g    = (const float*)d_in[16];
    const float* qn_b    = (const float*)d_in[17];
    const float* kn_g    = (const float*)d_in[18];
    const float* kn_b    = (const float*)d_in[19];
    const float* vn_g    = (const float*)d_in[20];
    const float* vn_b    = (const float*)d_in[21];
    float* out = (float*)d_out;

    float *qk, *kg, *vg, *Q, *Kl, *Vl, *Kg, *Vg, *O;
    float *st_qk, *st_x, *st_kg, *st_vg;
    float *fwqk, *fbqk, *fwv, *fwo, *frw, *fbv;
    cudaGetSymbolAddress((void**)&qk,    g_qk);
    cudaGetSymbolAddress((void**)&kg,    g_kg);
    cudaGetSymbolAddress((void**)&vg,    g_vg);
    cudaGetSymbolAddress((void**)&Q,     g_Q);
    cudaGetSymbolAddress((void**)&Kl,    g_Kl);
    cudaGetSymbolAddress((void**)&Vl,    g_Vl);
    cudaGetSymbolAddress((void**)&Kg,    g_Kg);
    cudaGetSymbolAddress((void**)&Vg,    g_Vg);
    cudaGetSymbolAddress((void**)&O,     g_O);
    cudaGetSymbolAddress((void**)&st_qk, g_st_qk);
    cudaGetSymbolAddress((void**)&st_x,  g_st_x);
    cudaGetSymbolAddress((void**)&st_kg, g_st_kg);
    cudaGetSymbolAddress((void**)&st_vg, g_st_vg);
    cudaGetSymbolAddress((void**)&fwqk,  g_fwqk);
    cudaGetSymbolAddress((void**)&fbqk,  g_fbqk);
    cudaGetSymbolAddress((void**)&fwv,   g_fwv);
    cudaGetSymbolAddress((void**)&fwo,   g_fwo);
    cudaGetSymbolAddress((void**)&frw,   g_frw);
    cudaGetSymbolAddress((void**)&fbv,   g_fbv);

    cudaFuncSetAttribute(attn_kernel, cudaFuncAttributeMaxDynamicSharedMemorySize,
                         ATTN_SMEM_BYTES);
    cudaFuncSetAttribute(mma_gemm<0,0>, cudaFuncAttributeMaxDynamicSharedMemorySize, SMEM_GEMM);
    cudaFuncSetAttribute(mma_gemm<1,1>, cudaFuncAttributeMaxDynamicSharedMemorySize, SMEM_GEMM);
    cudaFuncSetAttribute(mma_gemm<1,0>, cudaFuncAttributeMaxDynamicSharedMemorySize, SMEM_GEMM);
    cudaFuncSetAttribute(mma_gemm<2,0>, cudaFuncAttributeMaxDynamicSharedMemorySize, SMEM_GEMM);
    cudaFuncSetAttribute(mma_gemm<3,0>, cudaFuncAttributeMaxDynamicSharedMemorySize, SMEM_GEMM);

    // 0) fold + round weights
    fold_w_kernel<<<64, 256>>>(wq, qn_g, qn_b, bq, fwqk, fbqk, DD, INCC);
    fold_w_kernel<<<64, 256>>>(wk, kn_g, kn_b, bk, fwqk + (size_t)DD * INCC, fbqk + DD, DD, INCC);
    fold_w_kernel<<<64, 256>>>(wv, vn_g, vn_b, bv, fwv, fbv, DD, DD);
    fold_w_kernel<<<64, 256>>>(wo, nullptr, nullptr, nullptr, fwo, nullptr, DD, DD);
    fold_w_kernel<<<80, 256>>>(rw_w, nullptr, nullptr, nullptr, frw, nullptr, INCC, INCC);

    // 1) reweight: qk = concat(x,f) * sigmoid(concat @ rw_w^T + rw_b)
    mma_gemm<0,0><<<dim3(5, 256), 256, SMEM_GEMM>>>(
        x, f, frw, rw_b, nullptr, qk, nullptr, MTOK, INCC, INCC, INCC);
    // 2) independent of reweight
    ln_stats_kernel<<<MTOK / 8, 256>>>(x, st_x, DD);
    dwconv_kernel<<<BT * GG, 256>>>(x, convv_w, convv_b, vg, DD);
    // 3) after reweight
    ln_stats_kernel<<<MTOK / 8, 256>>>(qk, st_qk, INCC);
    dwconv_kernel<<<BT * GG, 256>>>(qk, convk_w, convk_b, kg, INCC);
    ln_stats_kernel<<<(BT * NGLOB) / 8, 256>>>(kg, st_kg, INCC);
    ln_stats_kernel<<<(BT * NGLOB) / 8, 256>>>(vg, st_vg, DD);
    // 4) projections (Q+K merged, N=1024, split outputs)
    mma_gemm<1,1><<<dim3(8, 256), 256, SMEM_GEMM>>>(
        qk, nullptr, fwqk, fbqk, st_qk, Q, Kl, MTOK, 2 * DD, INCC, DD);
    mma_gemm<2,0><<<dim3(4, 4), 256, SMEM_GEMM>>>(
        kg, nullptr, fwqk + (size_t)DD * INCC, fbqk + DD, st_kg, Kg, nullptr,
        BT * NGLOB, DD, INCC, DD);
    mma_gemm<1,0><<<dim3(4, 256), 256, SMEM_GEMM>>>(
        x, nullptr, fwv, fbv, st_x, Vl, nullptr, MTOK, DD, DD, DD);
    mma_gemm<2,0><<<dim3(4, 4), 256, SMEM_GEMM>>>(
        vg, nullptr, fwv, fbv, st_vg, Vg, nullptr, BT * NGLOB, DD, DD, DD);
    // 5) attention
    attn_kernel<<<BT * GG * NHEAD, 256, ATTN_SMEM_BYTES>>>(Q, Kl, Kg, Vl, Vg, O);
    // 6) out projection (window-reverse gather)
    mma_gemm<3,0><<<dim3(4, 256), 256, SMEM_GEMM>>>(
        O, nullptr, fwo, bo, nullptr, out, nullptr, MTOK, DD, DD, DD);
}

// round 7
// speedup vs baseline: 1.7463x; 1.3858x over previous
#include <cuda_runtime.h>
#include <cuda_fp16.h>
#include <cstdint>

// ---------------- problem constants ----------------
#define BT     8
#define NPIX   4096
#define DD     512
#define CFF    128
#define INCC   640
#define GG     64
#define NWIN   64
#define NGLOB  64
#define NHEAD  8
#define DHH    64
#define MTOK   32768

// ---------------- scratch ----------------
__device__ float g_qk [BT*NPIX*INCC];
__device__ float g_kg [BT*NGLOB*INCC];
__device__ float g_vg [BT*NGLOB*DD];
__device__ float g_Q  [BT*GG*NWIN*DD];
__device__ float g_Kl [BT*GG*NWIN*DD];
__device__ float g_Vl [BT*GG*NWIN*DD];
__device__ float g_Kg [BT*NGLOB*DD];
__device__ float g_Vg [BT*NGLOB*DD];
__device__ float g_O  [BT*GG*NWIN*DD];
__device__ float g_st_qk[MTOK*2];
__device__ float g_st_x [MTOK*2];
__device__ float g_st_kg[BT*NGLOB*2];
__device__ float g_st_vg[BT*NGLOB*2];
// folded weights (fp16)
__device__ __half g_fwqk[2*DD*INCC];
__device__ float  g_fbqk[2*DD];
__device__ __half g_fwv[DD*DD];
__device__ __half g_fwo[DD*DD];
__device__ __half g_frw[INCC*INCC];
__device__ float  g_fbv[DD];

// ---------------- helpers ----------------
__device__ __forceinline__ int win_map(int r) {
    int b = r >> 12;
    int p = r & 4095;
    int h = p >> 6, w = p & 63;
    int g = ((h >> 3) << 3) | (w >> 3);
    int n = ((h & 7) << 3) | (w & 7);
    return (((b << 6) | g) << 6) | n;
}

__device__ __forceinline__ uint32_t h2b(float a, float b) {
    __half2 h = __floats2half2_rn(a, b);
    return *(uint32_t*)&h;
}

__device__ __forceinline__ void mma_f16(float* d, const uint32_t* a, const uint32_t* b) {
    asm volatile(
        "mma.sync.aligned.m16n8k16.row.col.f32.f16.f16.f32 "
        "{%0,%1,%2,%3}, {%4,%5,%6,%7}, {%8,%9}, {%0,%1,%2,%3};"
        : "+f"(d[0]), "+f"(d[1]), "+f"(d[2]), "+f"(d[3])
        : "r"(a[0]), "r"(a[1]), "r"(a[2]), "r"(a[3]), "r"(b[0]), "r"(b[1]));
}

__device__ __forceinline__ void ldsm_x4(uint32_t* r, uint32_t addr) {
    asm volatile("ldmatrix.sync.aligned.m8n8.x4.shared.b16 {%0,%1,%2,%3}, [%4];"
                 : "=r"(r[0]), "=r"(r[1]), "=r"(r[2]), "=r"(r[3]) : "r"(addr));
}

#define CP_ASYNC16(dst, src) \
    asm volatile("cp.async.ca.shared.global [%0], [%1], 16;" :: "r"(dst), "l"(src))
#define CP_COMMIT() asm volatile("cp.async.commit_group;" ::: "memory")
#define CP_WAIT0()  asm volatile("cp.async.wait_group 0;" ::: "memory")

// ---------------- weight fold (fp32 -> fp16, gamma folded; bias fold) ----------------
__global__ __launch_bounds__(256)
void fold_w_kernel(const float* __restrict__ W, const float* __restrict__ gamma,
                   const float* __restrict__ beta, const float* __restrict__ b,
                   __half* __restrict__ Wo, float* __restrict__ bo, int N, int K) {
    int n = blockIdx.x * 8 + (threadIdx.x >> 5);
    if (n >= N) return;
    int lane = threadIdx.x & 31;
    const float* wr = W + (size_t)n * K;
    __half* wor = Wo + (size_t)n * K;
    float acc = 0.f;
    for (int k = lane; k < K; k += 32) {
        float w = wr[k];
        if (beta) acc += beta[k] * w;
        wor[k] = __float2half(gamma ? w * gamma[k] : w);
    }
    if (beta) {
        #pragma unroll
        for (int o = 16; o; o >>= 1) acc += __shfl_xor_sync(0xffffffffu, acc, o);
        if (lane == 0) bo[n] = b[n] + acc;
    }
}

// ---------------- LayerNorm stats ----------------
__global__ __launch_bounds__(256)
void ln_stats_kernel(const float* __restrict__ X, float* __restrict__ stats, int K) {
    int row = blockIdx.x * 8 + (threadIdx.x >> 5);
    int lane = threadIdx.x & 31;
    const float* xr = X + (size_t)row * K;
    float s = 0.f, ss = 0.f;
    for (int k = lane * 4; k < K; k += 128) {
        float4 v = *(const float4*)(xr + k);
        s  += v.x + v.y + v.z + v.w;
        ss += v.x * v.x + v.y * v.y + v.z * v.z + v.w * v.w;
    }
    #pragma unroll
    for (int o = 16; o; o >>= 1) {
        s  += __shfl_xor_sync(0xffffffffu, s, o);
        ss += __shfl_xor_sync(0xffffffffu, ss, o);
    }
    if (lane == 0) {
        float mean = s / K;
        float var = ss / K - mean * mean;
        *(float2*)(stats + (size_t)row * 2) = make_float2(mean, rsqrtf(var + 1e-5f));
    }
}

// ---------------- depthwise 8x8 stride-8 conv ----------------
__global__ __launch_bounds__(256)
void dwconv_kernel(const float* __restrict__ X, const float* __restrict__ Wc,
                   const float* __restrict__ bc, float* __restrict__ out, int C) {
    int bw = blockIdx.x;
    int b = bw >> 6;
    int g = bw & 63;
    int gh = g >> 3, gw = g & 7;
    const float* xb = X + (size_t)b * NPIX * C;
    for (int c = threadIdx.x; c < C; c += 256) {
        float s = bc[c];
        #pragma unroll
        for (int i = 0; i < 8; i++)
            #pragma unroll
            for (int j = 0; j < 8; j++)
                s += xb[(size_t)((gh * 8 + i) * 64 + (gw * 8 + j)) * C + c]
                     * Wc[c * 64 + i * 8 + j];
        out[(size_t)bw * C + c] = s;
    }
}

// ---------------- pipelined fp16 mma GEMM ----------------
// C[M,N] = op(A)[M,K] @ W[N,K]^T ; CTA 128x128, K-chunks of 64 halves.
// MODE 0: A split (x|f); out = a * sigmoid(acc+bias); spatial write
// MODE 1: LN-normalized A; +bias; output row = win_map
// MODE 2: as MODE 1, identity output rows
// MODE 3: A gathered via win_map; +bias; spatial write
// SPLIT: columns [0,512)->C, [512,1024)->C2
#define GS 72   // smem row stride in halves
template<int MODE, int SPLIT>
__global__ __launch_bounds__(256)
void mma_gemm(const float* __restrict__ A, const float* __restrict__ A2,
              const __half* __restrict__ W, const float* __restrict__ bias,
              const float* __restrict__ stats, float* __restrict__ C,
              float* __restrict__ C2, int M, int N, int K, int ldc) {
    extern __shared__ __half sh[];
    __half* As = sh;                    // [2][128*GS]
    __half* Bs = sh + 2 * 128 * GS;     // [2][128*GS]

    const int tid = threadIdx.x;
    const int m0 = blockIdx.y * 128;
    const int n0 = blockIdx.x * 128;
    const int q = tid & 7;              // 8-half (16B) column slot
    const int lrow = tid >> 3;
    const int lane = tid & 31, grp = lane >> 2, tig = lane & 3;
    const int w = tid >> 5, mblk = (w & 3) * 32, nblk = (w >> 2) * 64;
    const int NC = K >> 6;

    const uint32_t as_s = (uint32_t)__cvta_generic_to_shared(As);
    const uint32_t bs_s = (uint32_t)__cvta_generic_to_shared(Bs);

    const uint32_t aoff0 = (uint32_t)(((mblk + (lane & 15)) * GS + (lane >> 4) * 8) * 2);
    const uint32_t aoff1 = aoff0 + (uint32_t)(16 * GS * 2);
    const uint32_t boff  = (uint32_t)(((nblk + (lane & 7) + ((lane & 16) ? 8 : 0)) * GS
                                       + ((lane & 8) ? 8 : 0)) * 2);

    int arow[4]; float mean[4], rstd[4];
    #pragma unroll
    for (int i = 0; i < 4; i++) {
        int r = m0 + lrow + i * 32;
        arow[i] = (MODE == 3) ? win_map(r) : r;
        if (MODE == 1 || MODE == 2) {
            float2 st = *(const float2*)(stats + (size_t)r * 2);
            mean[i] = st.x; rstd[i] = st.y;
        }
    }

    float acc[2][8][4];
    #pragma unroll
    for (int mt = 0; mt < 2; mt++)
        #pragma unroll
        for (int nt = 0; nt < 8; nt++)
            #pragma unroll
            for (int e = 0; e < 4; e++) acc[mt][nt][e] = 0.f;

    auto issue_B = [&](int ch, int buf) {
        int gk = (ch << 6) + q * 8;
        #pragma unroll
        for (int i = 0; i < 4; i++) {
            int r = lrow + i * 32;
            const __half* src = W + (size_t)(n0 + r) * K + gk;
            uint32_t dst = bs_s + (uint32_t)(((buf * 128 + r) * GS + q * 8) * 2);
            CP_ASYNC16(dst, src);
        }
    };
    auto load_A = [&](int ch, uint4* areg) {
        int gk = (ch << 6) + q * 8;
        #pragma unroll
        for (int i = 0; i < 4; i++) {
            float4 v0, v1;
            if (MODE == 0) {
                if (gk < 512) {
                    v0 = *(const float4*)(A + (size_t)arow[i] * 512 + gk);
                    v1 = *(const float4*)(A + (size_t)arow[i] * 512 + gk + 4);
                } else {
                    v0 = *(const float4*)(A2 + (size_t)arow[i] * 128 + (gk - 512));
                    v1 = *(const float4*)(A2 + (size_t)arow[i] * 128 + (gk - 512) + 4);
                }
            } else {
                v0 = *(const float4*)(A + (size_t)arow[i] * K + gk);
                v1 = *(const float4*)(A + (size_t)arow[i] * K + gk + 4);
                if (MODE == 1 || MODE == 2) {
                    v0.x = (v0.x - mean[i]) * rstd[i];
                    v0.y = (v0.y - mean[i]) * rstd[i];
                    v0.z = (v0.z - mean[i]) * rstd[i];
                    v0.w = (v0.w - mean[i]) * rstd[i];
                    v1.x = (v1.x - mean[i]) * rstd[i];
                    v1.y = (v1.y - mean[i]) * rstd[i];
                    v1.z = (v1.z - mean[i]) * rstd[i];
                    v1.w = (v1.w - mean[i]) * rstd[i];
                }
            }
            areg[i].x = h2b(v0.x, v0.y);
            areg[i].y = h2b(v0.z, v0.w);
            areg[i].z = h2b(v1.x, v1.y);
            areg[i].w = h2b(v1.z, v1.w);
        }
    };
    auto sts_A = [&](int buf, const uint4* areg) {
        #pragma unroll
        for (int i = 0; i < 4; i++)
            *(uint4*)&As[(buf * 128 + lrow + i * 32) * GS + q * 8] = areg[i];
    };
    auto compute = [&](int buf) {
        uint32_t abase = as_s + (uint32_t)(buf * 128 * GS * 2);
        uint32_t bbase = bs_s + (uint32_t)(buf * 128 * GS * 2);
        #pragma unroll
        for (int k16 = 0; k16 < 4; k16++) {
            uint32_t kb = (uint32_t)(k16 * 32);      // 16 halves
            uint32_t af0[4], af1[4];
            ldsm_x4(af0, abase + aoff0 + kb);
            ldsm_x4(af1, abase + aoff1 + kb);
            #pragma unroll
            for (int p = 0; p < 4; p++) {
                uint32_t bf[4];
                ldsm_x4(bf, bbase + boff + (uint32_t)(p * 16 * GS * 2) + kb);
                mma_f16(acc[0][2 * p],     af0, bf);
                mma_f16(acc[1][2 * p],     af1, bf);
                mma_f16(acc[0][2 * p + 1], af0, bf + 2);
                mma_f16(acc[1][2 * p + 1], af1, bf + 2);
            }
        }
    };

    issue_B(0, 0); CP_COMMIT();
    {
        uint4 areg0[4];
        load_A(0, areg0);
        sts_A(0, areg0);
    }
    CP_WAIT0();
    __syncthreads();

    uint4 areg[4];
    for (int ch = 0; ch < NC; ch++) {
        int buf = ch & 1;
        int nx = ch + 1;
        if (nx < NC) {
            issue_B(nx, buf ^ 1); CP_COMMIT();
            load_A(nx, areg);
        }
        compute(buf);
        if (nx < NC) {
            sts_A(buf ^ 1, areg);
            CP_WAIT0();
        }
        __syncthreads();
    }

    // epilogue
    #pragma unroll
    for (int mt = 0; mt < 2; mt++) {
        #pragma unroll
        for (int hr = 0; hr < 2; hr++) {
            int r = m0 + mblk + mt * 16 + grp + hr * 8;
            size_t orow = (MODE == 1) ? (size_t)win_map(r) : (size_t)r;
            #pragma unroll
            for (int nt = 0; nt < 8; nt++) {
                int c = n0 + nblk + nt * 8 + 2 * tig;
                float y0 = acc[mt][nt][hr * 2 + 0] + bias[c];
                float y1 = acc[mt][nt][hr * 2 + 1] + bias[c + 1];
                float* base = C;
                int cc = c;
                if (SPLIT) {
                    base = (c < 512) ? C : C2;
                    cc = c & 511;
                }
                if (MODE == 0) {
                    float a0 = (c < 512) ? A[(size_t)r * 512 + c]
                                         : A2[(size_t)r * 128 + (c - 512)];
                    float a1 = (c + 1 < 512) ? A[(size_t)r * 512 + c + 1]
                                             : A2[(size_t)r * 128 + (c + 1 - 512)];
                    y0 = a0 / (1.f + __expf(-y0));
                    y1 = a1 / (1.f + __expf(-y1));
                }
                *(float2*)(base + orow * (size_t)ldc + cc) = make_float2(y0, y1);
            }
        }
    }
}

// ---------------- attention: fp16 mma + ldmatrix ----------------
// Qs[64][72]h, Ks[128][72]h, Vt[64][136]h (d,key), Ps[64][136]h, Sf[64][132]f
#define AQ_STR 72
#define AV_STR 136
#define ATTN_SMEM_BYTES (64*72*2 + 128*72*2 + 64*136*2 + 64*136*2 + 64*132*4)  // 96256

__global__ __launch_bounds__(256)
void attn_kernel(const float* __restrict__ Q, const float* __restrict__ Kl,
                 const float* __restrict__ Kg, const float* __restrict__ Vl,
                 const float* __restrict__ Vg, float* __restrict__ O) {
    extern __shared__ char smraw[];
    __half* Qs = (__half*)smraw;                    // [64][72]
    __half* Ks = Qs + 64 * AQ_STR;                  // [128][72]
    __half* Vt = Ks + 128 * AQ_STR;                 // [64][136]
    __half* Ps = Vt + 64 * AV_STR;                  // [64][136]
    float*  Sf = (float*)(Ps + 64 * AV_STR);        // [64][132]

    int bid = blockIdx.x;
    int b = bid >> 9;
    int rem = bid & 511;
    int g = rem >> 3;
    int h = rem & 7;

    size_t wbase = ((size_t)(b * GG + g) * NWIN) * DD + (size_t)h * DHH;
    size_t gbase = ((size_t)b * NGLOB) * DD + (size_t)h * DHH;
    const float* Qp  = Q  + wbase;
    const float* Klp = Kl + wbase;
    const float* Vlp = Vl + wbase;
    const float* Kgp = Kg + gbase;
    const float* Vgp = Vg + gbase;
    float* Op = O + wbase;

    int tid = threadIdx.x;

    for (int e = tid; e < 64 * 16; e += 256) {
        int m = e >> 4, d4 = (e & 15) << 2;
        float4 v = *(const float4*)(Qp + (size_t)m * DD + d4);
        *(uint2*)&Qs[m * AQ_STR + d4] = make_uint2(h2b(v.x, v.y), h2b(v.z, v.w));
    }
    for (int e = tid; e < 128 * 16; e += 256) {
        int kk = e >> 4, d4 = (e & 15) << 2;
        const float* ksrc = (kk < 64) ? (Klp + (size_t)kk * DD)
                                      : (Kgp + (size_t)(kk - 64) * DD);
        float4 v = *(const float4*)(ksrc + d4);
        *(uint2*)&Ks[kk * AQ_STR + d4] = make_uint2(h2b(v.x, v.y), h2b(v.z, v.w));
        const float* vsrc = (kk < 64) ? (Vlp + (size_t)kk * DD)
                                      : (Vgp + (size_t)(kk - 64) * DD);
        float4 wv = *(const float4*)(vsrc + d4);
        Vt[(d4 + 0) * AV_STR + kk] = __float2half(wv.x);
        Vt[(d4 + 1) * AV_STR + kk] = __float2half(wv.y);
        Vt[(d4 + 2) * AV_STR + kk] = __float2half(wv.z);
        Vt[(d4 + 3) * AV_STR + kk] = __float2half(wv.w);
    }
    __syncthreads();

    const uint32_t qs_s = (uint32_t)__cvta_generic_to_shared(Qs);
    const uint32_t ks_s = (uint32_t)__cvta_generic_to_shared(Ks);
    const uint32_t vt_s = (uint32_t)__cvta_generic_to_shared(Vt);
    const uint32_t ps_s = (uint32_t)__cvta_generic_to_shared(Ps);

    int w = tid >> 5, lane = tid & 31, grp = lane >> 2, tig = lane & 3;
    int mrow = (w & 3) * 16;

    // S = Q @ K^T * 1/8 : per warp m16 x n64, k64 (4 k16-steps)
    {
        int nb0 = (w >> 2) * 64;
        const uint32_t aoff = qs_s +
            (uint32_t)(((mrow + (lane & 15)) * AQ_STR + (lane >> 4) * 8) * 2);
        const uint32_t boff = ks_s +
            (uint32_t)(((nb0 + (lane & 7) + ((lane & 16) ? 8 : 0)) * AQ_STR
                        + ((lane & 8) ? 8 : 0)) * 2);
        float acc[8][4];
        #pragma unroll
        for (int nt = 0; nt < 8; nt++)
            #pragma unroll
            for (int e = 0; e < 4; e++) acc[nt][e] = 0.f;
        #pragma unroll
        for (int k16 = 0; k16 < 4; k16++) {
            uint32_t kb = (uint32_t)(k16 * 32);
            uint32_t af[4];
            ldsm_x4(af, aoff + kb);
            #pragma unroll
            for (int p = 0; p < 4; p++) {
                uint32_t bf[4];
                ldsm_x4(bf, boff + (uint32_t)(p * 16 * AQ_STR * 2) + kb);
                mma_f16(acc[2 * p],     af, bf);
                mma_f16(acc[2 * p + 1], af, bf + 2);
            }
        }
        #pragma unroll
        for (int nt = 0; nt < 8; nt++) {
            int c = nb0 + nt * 8 + 2 * tig;
            Sf[(mrow + grp)     * 132 + c]     = acc[nt][0] * 0.125f;
            Sf[(mrow + grp)     * 132 + c + 1] = acc[nt][1] * 0.125f;
            Sf[(mrow + grp + 8) * 132 + c]     = acc[nt][2] * 0.125f;
            Sf[(mrow + grp + 8) * 132 + c + 1] = acc[nt][3] * 0.125f;
        }
    }
    __syncthreads();

    // softmax (fp32) -> Ps (fp16)
    for (int m = w; m < 64; m += 8) {
        float* sr = &Sf[m * 132];
        float v0 = sr[lane], v1 = sr[lane + 32], v2 = sr[lane + 64], v3 = sr[lane + 96];
        float mx = fmaxf(fmaxf(v0, v1), fmaxf(v2, v3));
        #pragma unroll
        for (int o = 16; o; o >>= 1) mx = fmaxf(mx, __shfl_xor_sync(0xffffffffu, mx, o));
        float e0 = __expf(v0 - mx), e1 = __expf(v1 - mx);
        float e2 = __expf(v2 - mx), e3 = __expf(v3 - mx);
        float s = e0 + e1 + e2 + e3;
        #pragma unroll
        for (int o = 16; o; o >>= 1) s += __shfl_xor_sync(0xffffffffu, s, o);
        float inv = 1.f / s;
        __half* pr = &Ps[m * AV_STR];
        pr[lane]      = __float2half(e0 * inv);
        pr[lane + 32] = __float2half(e1 * inv);
        pr[lane + 64] = __float2half(e2 * inv);
        pr[lane + 96] = __float2half(e3 * inv);
    }
    __syncthreads();

    // out = P @ V : per warp m16 x n32, k128 (8 k16-steps)
    {
        int db0 = (w >> 2) * 32;
        const uint32_t aoff = ps_s +
            (uint32_t)(((mrow + (lane & 15)) * AV_STR + (lane >> 4) * 8) * 2);
        const uint32_t boff = vt_s +
            (uint32_t)(((db0 + (lane & 7) + ((lane & 16) ? 8 : 0)) * AV_STR
                        + ((lane & 8) ? 8 : 0)) * 2);
        float acc[4][4];
        #pragma unroll
        for (int nt = 0; nt < 4; nt++)
            #pragma unroll
            for (int e = 0; e < 4; e++) acc[nt][e] = 0.f;
        #pragma unroll
        for (int k16 = 0; k16 < 8; k16++) {
            uint32_t kb = (uint32_t)(k16 * 32);
            uint32_t af[4];
            ldsm_x4(af, aoff + kb);
            #pragma unroll
            for (int p = 0; p < 2; p++) {
                uint32_t bf[4];
                ldsm_x4(bf, boff + (uint32_t)(p * 16 * AV_STR * 2) + kb);
                mma_f16(acc[2 * p],     af, bf);
                mma_f16(acc[2 * p + 1], af, bf + 2);
            }
        }
        #pragma unroll
        for (int nt = 0; nt < 4; nt++) {
            int c = db0 + nt * 8 + 2 * tig;
            *(float2*)(Op + (size_t)(mrow + grp) * DD + c) =
                make_float2(acc[nt][0], acc[nt][1]);
            *(float2*)(Op + (size_t)(mrow + grp + 8) * DD + c) =
                make_float2(acc[nt][2], acc[nt][3]);
        }
    }
}

// ---------------- launch ----------------
#define SMEM_GEMM (4 * 128 * GS * 2)   // 73728

extern "C" void kernel_launch(void* const* d_in, const int* in_sizes, int n_in,
                              void* d_out, int out_size) {
    const float* x       = (const float*)d_in[0];
    const float* f       = (const float*)d_in[1];
    const float* wq      = (const float*)d_in[2];
    const float* bq      = (const float*)d_in[3];
    const float* wk      = (const float*)d_in[4];
    const float* bk      = (const float*)d_in[5];
    const float* wv      = (const float*)d_in[6];
    const float* bv      = (const float*)d_in[7];
    const float* wo      = (const float*)d_in[8];
    const float* bo      = (const float*)d_in[9];
    const float* rw_w    = (const float*)d_in[10];
    const float* rw_b    = (const float*)d_in[11];
    const float* convk_w = (const float*)d_in[12];
    const float* convk_b = (const float*)d_in[13];
    const float* convv_w = (const float*)d_in[14];
    const float* convv_b = (const float*)d_in[15];
    const float* qn_g    = (const float*)d_in[16];
    const float* qn_b    = (const float*)d_in[17];
    const float* kn_g    = (const float*)d_in[18];
    const float* kn_b    = (const float*)d_in[19];
    const float* vn_g    = (const float*)d_in[20];
    const float* vn_b    = (const float*)d_in[21];
    float* out = (float*)d_out;

    float *qk, *kg, *vg, *Q, *Kl, *Vl, *Kg, *Vg, *O;
    float *st_qk, *st_x, *st_kg, *st_vg, *fbqk, *fbv;
    __half *fwqk, *fwv, *fwo, *frw;
    cudaGetSymbolAddress((void**)&qk,    g_qk);
    cudaGetSymbolAddress((void**)&kg,    g_kg);
    cudaGetSymbolAddress((void**)&vg,    g_vg);
    cudaGetSymbolAddress((void**)&Q,     g_Q);
    cudaGetSymbolAddress((void**)&Kl,    g_Kl);
    cudaGetSymbolAddress((void**)&Vl,    g_Vl);
    cudaGetSymbolAddress((void**)&Kg,    g_Kg);
    cudaGetSymbolAddress((void**)&Vg,    g_Vg);
    cudaGetSymbolAddress((void**)&O,     g_O);
    cudaGetSymbolAddress((void**)&st_qk, g_st_qk);
    cudaGetSymbolAddress((void**)&st_x,  g_st_x);
    cudaGetSymbolAddress((void**)&st_kg, g_st_kg);
    cudaGetSymbolAddress((void**)&st_vg, g_st_vg);
    cudaGetSymbolAddress((void**)&fwqk,  g_fwqk);
    cudaGetSymbolAddress((void**)&fbqk,  g_fbqk);
    cudaGetSymbolAddress((void**)&fwv,   g_fwv);
    cudaGetSymbolAddress((void**)&fwo,   g_fwo);
    cudaGetSymbolAddress((void**)&frw,   g_frw);
    cudaGetSymbolAddress((void**)&fbv,   g_fbv);

    cudaFuncSetAttribute(attn_kernel, cudaFuncAttributeMaxDynamicSharedMemorySize,
                         ATTN_SMEM_BYTES);
    cudaFuncSetAttribute(mma_gemm<0,0>, cudaFuncAttributeMaxDynamicSharedMemorySize, SMEM_GEMM);
    cudaFuncSetAttribute(mma_gemm<1,1>, cudaFuncAttributeMaxDynamicSharedMemorySize, SMEM_GEMM);
    cudaFuncSetAttribute(mma_gemm<1,0>, cudaFuncAttributeMaxDynamicSharedMemorySize, SMEM_GEMM);
    cudaFuncSetAttribute(mma_gemm<2,0>, cudaFuncAttributeMaxDynamicSharedMemorySize, SMEM_GEMM);
    cudaFuncSetAttribute(mma_gemm<3,0>, cudaFuncAttributeMaxDynamicSharedMemorySize, SMEM_GEMM);

    // 0) fold + convert weights (fp16)
    fold_w_kernel<<<64, 256>>>(wq, qn_g, qn_b, bq, fwqk, fbqk, DD, INCC);
    fold_w_kernel<<<64, 256>>>(wk, kn_g, kn_b, bk, fwqk + (size_t)DD * INCC, fbqk + DD, DD, INCC);
    fold_w_kernel<<<64, 256>>>(wv, vn_g, vn_b, bv, fwv, fbv, DD, DD);
    fold_w_kernel<<<64, 256>>>(wo, nullptr, nullptr, nullptr, fwo, nullptr, DD, DD);
    fold_w_kernel<<<80, 256>>>(rw_w, nullptr, nullptr, nullptr, frw, nullptr, INCC, INCC);

    // 1) reweight: qk = concat(x,f) * sigmoid(concat @ rw_w^T + rw_b)
    mma_gemm<0,0><<<dim3(5, 256), 256, SMEM_GEMM>>>(
        x, f, frw, rw_b, nullptr, qk, nullptr, MTOK, INCC, INCC, INCC);
    // 2) independent of reweight
    ln_stats_kernel<<<MTOK / 8, 256>>>(x, st_x, DD);
    dwconv_kernel<<<BT * GG, 256>>>(x, convv_w, convv_b, vg, DD);
    // 3) after reweight
    ln_stats_kernel<<<MTOK / 8, 256>>>(qk, st_qk, INCC);
    dwconv_kernel<<<BT * GG, 256>>>(qk, convk_w, convk_b, kg, INCC);
    ln_stats_kernel<<<(BT * NGLOB) / 8, 256>>>(kg, st_kg, INCC);
    ln_stats_kernel<<<(BT * NGLOB) / 8, 256>>>(vg, st_vg, DD);
    // 4) projections (Q+K merged, N=1024, split outputs)
    mma_gemm<1,1><<<dim3(8, 256), 256, SMEM_GEMM>>>(
        qk, nullptr, fwqk, fbqk, st_qk, Q, Kl, MTOK, 2 * DD, INCC, DD);
    mma_gemm<2,0><<<dim3(4, 4), 256, SMEM_GEMM>>>(
        kg, nullptr, fwqk + (size_t)DD * INCC, fbqk + DD, st_kg, Kg, nullptr,
        BT * NGLOB, DD, INCC, DD);
    mma_gemm<1,0><<<dim3(4, 256), 256, SMEM_GEMM>>>(
        x, nullptr, fwv, fbv, st_x, Vl, nullptr, MTOK, DD, DD, DD);
    mma_gemm<2,0><<<dim3(4, 4), 256, SMEM_GEMM>>>(
        vg, nullptr, fwv, fbv, st_vg, Vg, nullptr, BT * NGLOB, DD, DD, DD);
    // 5) attention
    attn_kernel<<<BT * GG * NHEAD, 256, ATTN_SMEM_BYTES>>>(Q, Kl, Kg, Vl, Vg, O);
    // 6) out projection (window-reverse gather)
    mma_gemm<3,0><<<dim3(4, 256), 256, SMEM_GEMM>>>(
        O, nullptr, fwo, bo, nullptr, out, nullptr, MTOK, DD, DD, DD);
}

// round 8
// speedup vs baseline: 2.0385x; 1.1673x over previous
#include <cuda_runtime.h>
#include <cuda_fp16.h>
#include <cstdint>

// ---------------- problem constants ----------------
#define BT     8
#define NPIX   4096
#define DD     512
#define CFF    128
#define INCC   640
#define GG     64
#define NWIN   64
#define NGLOB  64
#define NHEAD  8
#define DHH    64
#define MTOK   32768

// ---------------- scratch ----------------
__device__ float  g_qk [MTOK*INCC];          // reweighted concat (fp32, spatial)
__device__ float  g_kg [BT*NGLOB*INCC];
__device__ float  g_vg [BT*NGLOB*DD];
__device__ __half g_xf [MTOK*INCC];          // raw concat(x,f) half
__device__ __half g_qkn[MTOK*INCC];          // LN_qk(qk) half
__device__ __half g_xn [MTOK*DD];            // LN_v(x) half
__device__ __half g_kgn[BT*NGLOB*INCC];
__device__ __half g_vgn[BT*NGLOB*DD];
__device__ __half g_Q  [MTOK*DD];            // windowed
__device__ __half g_Kl [MTOK*DD];
__device__ __half g_Vl [MTOK*DD];
__device__ __half g_Kg [BT*NGLOB*DD];
__device__ __half g_Vg [BT*NGLOB*DD];
__device__ __half g_O  [MTOK*DD];            // attention out, windowed
// folded weights (fp16)
__device__ __half g_fwqk[2*DD*INCC];
__device__ float  g_fbqk[2*DD];
__device__ __half g_fwv[DD*DD];
__device__ __half g_fwo[DD*DD];
__device__ __half g_frw[INCC*INCC];
__device__ float  g_fbv[DD];

// ---------------- helpers ----------------
__device__ __forceinline__ int win_map(int r) {
    int b = r >> 12;
    int p = r & 4095;
    int h = p >> 6, w = p & 63;
    int g = ((h >> 3) << 3) | (w >> 3);
    int n = ((h & 7) << 3) | (w & 7);
    return (((b << 6) | g) << 6) | n;
}

__device__ __forceinline__ uint32_t h2b(float a, float b) {
    __half2 h = __floats2half2_rn(a, b);
    return *(uint32_t*)&h;
}

__device__ __forceinline__ void mma_f16(float* d, const uint32_t* a, const uint32_t* b) {
    asm volatile(
        "mma.sync.aligned.m16n8k16.row.col.f32.f16.f16.f32 "
        "{%0,%1,%2,%3}, {%4,%5,%6,%7}, {%8,%9}, {%0,%1,%2,%3};"
        : "+f"(d[0]), "+f"(d[1]), "+f"(d[2]), "+f"(d[3])
        : "r"(a[0]), "r"(a[1]), "r"(a[2]), "r"(a[3]), "r"(b[0]), "r"(b[1]));
}

__device__ __forceinline__ void ldsm_x4(uint32_t* r, uint32_t addr) {
    asm volatile("ldmatrix.sync.aligned.m8n8.x4.shared.b16 {%0,%1,%2,%3}, [%4];"
                 : "=r"(r[0]), "=r"(r[1]), "=r"(r[2]), "=r"(r[3]) : "r"(addr));
}

#define CP_ASYNC16(dst, src) \
    asm volatile("cp.async.ca.shared.global [%0], [%1], 16;" :: "r"(dst), "l"(src))
#define CP_COMMIT() asm volatile("cp.async.commit_group;" ::: "memory")
#define CP_WAIT0()  asm volatile("cp.async.wait_group 0;" ::: "memory")

// ---------------- weight fold ----------------
__global__ __launch_bounds__(256)
void fold_w_kernel(const float* __restrict__ W, const float* __restrict__ gamma,
                   const float* __restrict__ beta, const float* __restrict__ b,
                   __half* __restrict__ Wo, float* __restrict__ bo, int N, int K) {
    int n = blockIdx.x * 8 + (threadIdx.x >> 5);
    if (n >= N) return;
    int lane = threadIdx.x & 31;
    const float* wr = W + (size_t)n * K;
    __half* wor = Wo + (size_t)n * K;
    float acc = 0.f;
    for (int k = lane; k < K; k += 32) {
        float w = wr[k];
        if (beta) acc += beta[k] * w;
        wor[k] = __float2half(gamma ? w * gamma[k] : w);
    }
    if (beta) {
        #pragma unroll
        for (int o = 16; o; o >>= 1) acc += __shfl_xor_sync(0xffffffffu, acc, o);
        if (lane == 0) bo[n] = b[n] + acc;
    }
}

// ---------------- raw concat(x,f) -> half ----------------
__global__ __launch_bounds__(256)
void prep_xf_kernel(const float* __restrict__ x, const float* __restrict__ f,
                    __half* __restrict__ xf) {
    size_t idx = ((size_t)blockIdx.x * 256 + threadIdx.x) * 8;   // 8 halves
    int r = (int)(idx / INCC);
    int c = (int)(idx % INCC);
    const float* src = (c < 512) ? (x + (size_t)r * 512 + c)
                                 : (f + (size_t)r * 128 + (c - 512));
    float4 a = *(const float4*)src;
    float4 b = *(const float4*)(src + 4);
    uint4 o;
    o.x = h2b(a.x, a.y); o.y = h2b(a.z, a.w);
    o.z = h2b(b.x, b.y); o.w = h2b(b.z, b.w);
    *(uint4*)(xf + idx) = o;
}

// ---------------- fused LN: stats + normalize + half convert (warp/row) ----------------
template<int K>
__global__ __launch_bounds__(256)
void ln_norm_kernel(const float* __restrict__ X, __half* __restrict__ Xn) {
    const int NSEG = K / 128;
    int row = blockIdx.x * 8 + (threadIdx.x >> 5);
    int lane = threadIdx.x & 31;
    const float* xr = X + (size_t)row * K;
    float4 v[NSEG];
    float s = 0.f, ss = 0.f;
    #pragma unroll
    for (int i = 0; i < NSEG; i++) {
        v[i] = *(const float4*)(xr + lane * 4 + i * 128);
        s  += v[i].x + v[i].y + v[i].z + v[i].w;
        ss += v[i].x * v[i].x + v[i].y * v[i].y + v[i].z * v[i].z + v[i].w * v[i].w;
    }
    #pragma unroll
    for (int o = 16; o; o >>= 1) {
        s  += __shfl_xor_sync(0xffffffffu, s, o);
        ss += __shfl_xor_sync(0xffffffffu, ss, o);
    }
    float mean = s / K;
    float rstd = rsqrtf(ss / K - mean * mean + 1e-5f);
    __half* xo = Xn + (size_t)row * K;
    #pragma unroll
    for (int i = 0; i < NSEG; i++) {
        uint2 o;
        o.x = h2b((v[i].x - mean) * rstd, (v[i].y - mean) * rstd);
        o.y = h2b((v[i].z - mean) * rstd, (v[i].w - mean) * rstd);
        *(uint2*)(xo + lane * 4 + i * 128) = o;
    }
}

// ---------------- depthwise 8x8 stride-8 conv (fp32) ----------------
__global__ __launch_bounds__(256)
void dwconv_kernel(const float* __restrict__ X, const float* __restrict__ Wc,
                   const float* __restrict__ bc, float* __restrict__ out, int C) {
    int bw = blockIdx.x;
    int b = bw >> 6;
    int g = bw & 63;
    int gh = g >> 3, gw = g & 7;
    const float* xb = X + (size_t)b * NPIX * C;
    for (int c = threadIdx.x; c < C; c += 256) {
        float s = bc[c];
        #pragma unroll
        for (int i = 0; i < 8; i++)
            #pragma unroll
            for (int j = 0; j < 8; j++)
                s += xb[(size_t)((gh * 8 + i) * 64 + (gw * 8 + j)) * C + c]
                     * Wc[c * 64 + i * 8 + j];
        out[(size_t)bw * C + c] = s;
    }
}

// ---------------- fp16 mma GEMM, pure cp.async mainloop ----------------
// C = A[M,K](half, pre-processed) @ W[N,K]^T ; CTA 128x128, K-chunks of 64 halves.
// MODE 0: out = raw * sigmoid(acc+bias), fp32 -> Cf  (raw from Xraw|Fraw)
// MODE 1: +bias -> half, output row = win_map, split cols [0,512)->Ch,[512,1024)->Ch2
// MODE 2: +bias -> half Ch, identity rows
// MODE 3: A rows gathered via win_map; +bias -> fp32 Cf (final output)
#define GS 72
template<int MODE, int SPLIT>
__global__ __launch_bounds__(256)
void mma_gemm(const __half* __restrict__ A, const __half* __restrict__ W,
              const float* __restrict__ bias,
              const float* __restrict__ Xraw, const float* __restrict__ Fraw,
              float* __restrict__ Cf, __half* __restrict__ Ch, __half* __restrict__ Ch2,
              int M, int N, int K, int ldc) {
    extern __shared__ __half sh[];
    __half* As = sh;                    // [2][128*GS]
    __half* Bs = sh + 2 * 128 * GS;     // [2][128*GS]

    const int tid = threadIdx.x;
    const int m0 = blockIdx.y * 128;
    const int n0 = blockIdx.x * 128;
    const int q = tid & 7;
    const int lrow = tid >> 3;
    const int lane = tid & 31, grp = lane >> 2, tig = lane & 3;
    const int w = tid >> 5, mblk = (w & 3) * 32, nblk = (w >> 2) * 64;
    const int NC = K >> 6;

    const uint32_t as_s = (uint32_t)__cvta_generic_to_shared(As);
    const uint32_t bs_s = (uint32_t)__cvta_generic_to_shared(Bs);

    const uint32_t aoff0 = (uint32_t)(((mblk + (lane & 15)) * GS + (lane >> 4) * 8) * 2);
    const uint32_t aoff1 = aoff0 + (uint32_t)(16 * GS * 2);
    const uint32_t boff  = (uint32_t)(((nblk + (lane & 7) + ((lane & 16) ? 8 : 0)) * GS
                                       + ((lane & 8) ? 8 : 0)) * 2);

    int arow[4];
    #pragma unroll
    for (int i = 0; i < 4; i++) {
        int r = m0 + lrow + i * 32;
        arow[i] = (MODE == 3) ? win_map(r) : r;
    }

    float acc[2][8][4];
    #pragma unroll
    for (int mt = 0; mt < 2; mt++)
        #pragma unroll
        for (int nt = 0; nt < 8; nt++)
            #pragma unroll
            for (int e = 0; e < 4; e++) acc[mt][nt][e] = 0.f;

    auto issue = [&](int ch, int buf) {
        int gk = (ch << 6) + q * 8;
        #pragma unroll
        for (int i = 0; i < 4; i++) {
            int r = lrow + i * 32;
            CP_ASYNC16(as_s + (uint32_t)(((buf * 128 + r) * GS + q * 8) * 2),
                       A + (size_t)arow[i] * K + gk);
            CP_ASYNC16(bs_s + (uint32_t)(((buf * 128 + r) * GS + q * 8) * 2),
                       W + (size_t)(n0 + r) * K + gk);
        }
        CP_COMMIT();
    };
    auto compute = [&](int buf) {
        uint32_t abase = as_s + (uint32_t)(buf * 128 * GS * 2);
        uint32_t bbase = bs_s + (uint32_t)(buf * 128 * GS * 2);
        #pragma unroll
        for (int k16 = 0; k16 < 4; k16++) {
            uint32_t kb = (uint32_t)(k16 * 32);
            uint32_t af0[4], af1[4];
            ldsm_x4(af0, abase + aoff0 + kb);
            ldsm_x4(af1, abase + aoff1 + kb);
            #pragma unroll
            for (int p = 0; p < 4; p++) {
                uint32_t bf[4];
                ldsm_x4(bf, bbase + boff + (uint32_t)(p * 16 * GS * 2) + kb);
                mma_f16(acc[0][2 * p],     af0, bf);
                mma_f16(acc[1][2 * p],     af1, bf);
                mma_f16(acc[0][2 * p + 1], af0, bf + 2);
                mma_f16(acc[1][2 * p + 1], af1, bf + 2);
            }
        }
    };

    issue(0, 0);
    CP_WAIT0();
    __syncthreads();

    for (int ch = 0; ch < NC; ch++) {
        int buf = ch & 1;
        int nx = ch + 1;
        if (nx < NC) issue(nx, buf ^ 1);
        compute(buf);
        if (nx < NC) CP_WAIT0();
        __syncthreads();
    }

    // epilogue
    #pragma unroll
    for (int mt = 0; mt < 2; mt++) {
        #pragma unroll
        for (int hr = 0; hr < 2; hr++) {
            int r = m0 + mblk + mt * 16 + grp + hr * 8;
            size_t orow = (MODE == 1) ? (size_t)win_map(r) : (size_t)r;
            #pragma unroll
            for (int nt = 0; nt < 8; nt++) {
                int c = n0 + nblk + nt * 8 + 2 * tig;
                float y0 = acc[mt][nt][hr * 2 + 0] + bias[c];
                float y1 = acc[mt][nt][hr * 2 + 1] + bias[c + 1];
                if (MODE == 0) {
                    float a0 = (c < 512) ? Xraw[(size_t)r * 512 + c]
                                         : Fraw[(size_t)r * 128 + (c - 512)];
                    float a1 = (c + 1 < 512) ? Xraw[(size_t)r * 512 + c + 1]
                                             : Fraw[(size_t)r * 128 + (c + 1 - 512)];
                    y0 = a0 / (1.f + __expf(-y0));
                    y1 = a1 / (1.f + __expf(-y1));
                    *(float2*)(Cf + orow * (size_t)ldc + c) = make_float2(y0, y1);
                } else if (MODE == 3) {
                    *(float2*)(Cf + orow * (size_t)ldc + c) = make_float2(y0, y1);
                } else {
                    __half* base = Ch;
                    int cc = c;
                    if (SPLIT) { base = (c < 512) ? Ch : Ch2; cc = c & 511; }
                    *(__half2*)(base + orow * (size_t)ldc + cc) = __floats2half2_rn(y0, y1);
                }
            }
        }
    }
}

// ---------------- attention: fp16 in/out, cp.async loads ----------------
#define AQ_STR 72
#define AV_STR 136
#define ATTN_SMEM_BYTES (64*AQ_STR*2 + 128*AQ_STR*2 + 64*AV_STR*2 + 64*AV_STR*2 + 64*132*4)

__global__ __launch_bounds__(256)
void attn_kernel(const __half* __restrict__ Q, const __half* __restrict__ Kl,
                 const __half* __restrict__ Kg, const __half* __restrict__ Vl,
                 const __half* __restrict__ Vg, __half* __restrict__ O) {
    extern __shared__ char smraw[];
    __half* Qs = (__half*)smraw;                    // [64][72]
    __half* Ks = Qs + 64 * AQ_STR;                  // [128][72]
    __half* Vt = Ks + 128 * AQ_STR;                 // [64][136] (d, key)
    __half* Ps = Vt + 64 * AV_STR;                  // [64][136]
    float*  Sf = (float*)(Ps + 64 * AV_STR);        // [64][132]

    int bid = blockIdx.x;
    int b = bid >> 9;
    int rem = bid & 511;
    int g = rem >> 3;
    int h = rem & 7;

    size_t wbase = ((size_t)(b * GG + g) * NWIN) * DD + (size_t)h * DHH;
    size_t gbase = ((size_t)b * NGLOB) * DD + (size_t)h * DHH;
    const __half* Qp  = Q  + wbase;
    const __half* Klp = Kl + wbase;
    const __half* Vlp = Vl + wbase;
    const __half* Kgp = Kg + gbase;
    const __half* Vgp = Vg + gbase;
    __half* Op = O + wbase;

    int tid = threadIdx.x;
    const uint32_t qs_s = (uint32_t)__cvta_generic_to_shared(Qs);
    const uint32_t ks_s = (uint32_t)__cvta_generic_to_shared(Ks);
    const uint32_t vt_s = (uint32_t)__cvta_generic_to_shared(Vt);
    const uint32_t ps_s = (uint32_t)__cvta_generic_to_shared(Ps);

    // Q, K via cp.async (16B = 8 halves per task)
    for (int e = tid; e < 64 * 8; e += 256) {
        int m = e >> 3, sg = e & 7;
        CP_ASYNC16(qs_s + (uint32_t)((m * AQ_STR + sg * 8) * 2), Qp + (size_t)m * DD + sg * 8);
    }
    for (int e = tid; e < 128 * 8; e += 256) {
        int kk = e >> 3, sg = e & 7;
        const __half* ksrc = (kk < 64) ? (Klp + (size_t)kk * DD)
                                       : (Kgp + (size_t)(kk - 64) * DD);
        CP_ASYNC16(ks_s + (uint32_t)((kk * AQ_STR + sg * 8) * 2), ksrc + sg * 8);
    }
    CP_COMMIT();
    // V transposed via registers
    for (int e = tid; e < 128 * 8; e += 256) {
        int kk = e >> 3, sg = e & 7;
        const __half* vsrc = (kk < 64) ? (Vlp + (size_t)kk * DD)
                                       : (Vgp + (size_t)(kk - 64) * DD);
        uint4 pv = *(const uint4*)(vsrc + sg * 8);
        const __half* ph = (const __half*)&pv;
        #pragma unroll
        for (int j = 0; j < 8; j++)
            Vt[(sg * 8 + j) * AV_STR + kk] = ph[j];
    }
    CP_WAIT0();
    __syncthreads();

    int w = tid >> 5, lane = tid & 31, grp = lane >> 2, tig = lane & 3;
    int mrow = (w & 3) * 16;

    // S = Q @ K^T * 1/8 : per warp m16 x n64, k64
    {
        int nb0 = (w >> 2) * 64;
        const uint32_t aoff = qs_s +
            (uint32_t)(((mrow + (lane & 15)) * AQ_STR + (lane >> 4) * 8) * 2);
        const uint32_t boff = ks_s +
            (uint32_t)(((nb0 + (lane & 7) + ((lane & 16) ? 8 : 0)) * AQ_STR
                        + ((lane & 8) ? 8 : 0)) * 2);
        float acc[8][4];
        #pragma unroll
        for (int nt = 0; nt < 8; nt++)
            #pragma unroll
            for (int e = 0; e < 4; e++) acc[nt][e] = 0.f;
        #pragma unroll
        for (int k16 = 0; k16 < 4; k16++) {
            uint32_t kb = (uint32_t)(k16 * 32);
            uint32_t af[4];
            ldsm_x4(af, aoff + kb);
            #pragma unroll
            for (int p = 0; p < 4; p++) {
                uint32_t bf[4];
                ldsm_x4(bf, boff + (uint32_t)(p * 16 * AQ_STR * 2) + kb);
                mma_f16(acc[2 * p],     af, bf);
                mma_f16(acc[2 * p + 1], af, bf + 2);
            }
        }
        #pragma unroll
        for (int nt = 0; nt < 8; nt++) {
            int c = nb0 + nt * 8 + 2 * tig;
            Sf[(mrow + grp)     * 132 + c]     = acc[nt][0] * 0.125f;
            Sf[(mrow + grp)     * 132 + c + 1] = acc[nt][1] * 0.125f;
            Sf[(mrow + grp + 8) * 132 + c]     = acc[nt][2] * 0.125f;
            Sf[(mrow + grp + 8) * 132 + c + 1] = acc[nt][3] * 0.125f;
        }
    }
    __syncthreads();

    // softmax (fp32) -> Ps (fp16)
    for (int m = w; m < 64; m += 8) {
        float* sr = &Sf[m * 132];
        float v0 = sr[lane], v1 = sr[lane + 32], v2 = sr[lane + 64], v3 = sr[lane + 96];
        float mx = fmaxf(fmaxf(v0, v1), fmaxf(v2, v3));
        #pragma unroll
        for (int o = 16; o; o >>= 1) mx = fmaxf(mx, __shfl_xor_sync(0xffffffffu, mx, o));
        float e0 = __expf(v0 - mx), e1 = __expf(v1 - mx);
        float e2 = __expf(v2 - mx), e3 = __expf(v3 - mx);
        float s = e0 + e1 + e2 + e3;
        #pragma unroll
        for (int o = 16; o; o >>= 1) s += __shfl_xor_sync(0xffffffffu, s, o);
        float inv = 1.f / s;
        __half* pr = &Ps[m * AV_STR];
        pr[lane]      = __float2half(e0 * inv);
        pr[lane + 32] = __float2half(e1 * inv);
        pr[lane + 64] = __float2half(e2 * inv);
        pr[lane + 96] = __float2half(e3 * inv);
    }
    __syncthreads();

    // out = P @ V : per warp m16 x n32, k128
    {
        int db0 = (w >> 2) * 32;
        const uint32_t aoff = ps_s +
            (uint32_t)(((mrow + (lane & 15)) * AV_STR + (lane >> 4) * 8) * 2);
        const uint32_t boff = vt_s +
            (uint32_t)(((db0 + (lane & 7) + ((lane & 16) ? 8 : 0)) * AV_STR
                        + ((lane & 8) ? 8 : 0)) * 2);
        float acc[4][4];
        #pragma unroll
        for (int nt = 0; nt < 4; nt++)
            #pragma unroll
            for (int e = 0; e < 4; e++) acc[nt][e] = 0.f;
        #pragma unroll
        for (int k16 = 0; k16 < 8; k16++) {
            uint32_t kb = (uint32_t)(k16 * 32);
            uint32_t af[4];
            ldsm_x4(af, aoff + kb);
            #pragma unroll
            for (int p = 0; p < 2; p++) {
                uint32_t bf[4];
                ldsm_x4(bf, boff + (uint32_t)(p * 16 * AV_STR * 2) + kb);
                mma_f16(acc[2 * p],     af, bf);
                mma_f16(acc[2 * p + 1], af, bf + 2);
            }
        }
        #pragma unroll
        for (int nt = 0; nt < 4; nt++) {
            int c = db0 + nt * 8 + 2 * tig;
            *(__half2*)(Op + (size_t)(mrow + grp) * DD + c) =
                __floats2half2_rn(acc[nt][0], acc[nt][1]);
            *(__half2*)(Op + (size_t)(mrow + grp + 8) * DD + c) =
                __floats2half2_rn(acc[nt][2], acc[nt][3]);
        }
    }
}

// ---------------- launch ----------------
#define SMEM_GEMM (4 * 128 * GS * 2)   // 73728

extern "C" void kernel_launch(void* const* d_in, const int* in_sizes, int n_in,
                              void* d_out, int out_size) {
    const float* x       = (const float*)d_in[0];
    const float* f       = (const float*)d_in[1];
    const float* wq      = (const float*)d_in[2];
    const float* bq      = (const float*)d_in[3];
    const float* wk      = (const float*)d_in[4];
    const float* bk      = (const float*)d_in[5];
    const float* wv      = (const float*)d_in[6];
    const float* bv      = (const float*)d_in[7];
    const float* wo      = (const float*)d_in[8];
    const float* bo      = (const float*)d_in[9];
    const float* rw_w    = (const float*)d_in[10];
    const float* rw_b    = (const float*)d_in[11];
    const float* convk_w = (const float*)d_in[12];
    const float* convk_b = (const float*)d_in[13];
    const float* convv_w = (const float*)d_in[14];
    const float* convv_b = (const float*)d_in[15];
    const float* qn_g    = (const float*)d_in[16];
    const float* qn_b    = (const float*)d_in[17];
    const float* kn_g    = (const float*)d_in[18];
    const float* kn_b    = (const float*)d_in[19];
    const float* vn_g    = (const float*)d_in[20];
    const float* vn_b    = (const float*)d_in[21];
    float* out = (float*)d_out;

    float *qk, *kg, *vg, *fbqk, *fbv;
    __half *xf, *qkn, *xn, *kgn, *vgn, *Q, *Kl, *Vl, *Kg, *Vg, *O;
    __half *fwqk, *fwv, *fwo, *frw;
    cudaGetSymbolAddress((void**)&qk,   g_qk);
    cudaGetSymbolAddress((void**)&kg,   g_kg);
    cudaGetSymbolAddress((void**)&vg,   g_vg);
    cudaGetSymbolAddress((void**)&xf,   g_xf);
    cudaGetSymbolAddress((void**)&qkn,  g_qkn);
    cudaGetSymbolAddress((void**)&xn,   g_xn);
    cudaGetSymbolAddress((void**)&kgn,  g_kgn);
    cudaGetSymbolAddress((void**)&vgn,  g_vgn);
    cudaGetSymbolAddress((void**)&Q,    g_Q);
    cudaGetSymbolAddress((void**)&Kl,   g_Kl);
    cudaGetSymbolAddress((void**)&Vl,   g_Vl);
    cudaGetSymbolAddress((void**)&Kg,   g_Kg);
    cudaGetSymbolAddress((void**)&Vg,   g_Vg);
    cudaGetSymbolAddress((void**)&O,    g_O);
    cudaGetSymbolAddress((void**)&fwqk, g_fwqk);
    cudaGetSymbolAddress((void**)&fbqk, g_fbqk);
    cudaGetSymbolAddress((void**)&fwv,  g_fwv);
    cudaGetSymbolAddress((void**)&fwo,  g_fwo);
    cudaGetSymbolAddress((void**)&frw,  g_frw);
    cudaGetSymbolAddress((void**)&fbv,  g_fbv);

    cudaFuncSetAttribute(attn_kernel, cudaFuncAttributeMaxDynamicSharedMemorySize,
                         ATTN_SMEM_BYTES);
    cudaFuncSetAttribute(mma_gemm<0,0>, cudaFuncAttributeMaxDynamicSharedMemorySize, SMEM_GEMM);
    cudaFuncSetAttribute(mma_gemm<1,1>, cudaFuncAttributeMaxDynamicSharedMemorySize, SMEM_GEMM);
    cudaFuncSetAttribute(mma_gemm<1,0>, cudaFuncAttributeMaxDynamicSharedMemorySize, SMEM_GEMM);
    cudaFuncSetAttribute(mma_gemm<2,0>, cudaFuncAttributeMaxDynamicSharedMemorySize, SMEM_GEMM);
    cudaFuncSetAttribute(mma_gemm<3,0>, cudaFuncAttributeMaxDynamicSharedMemorySize, SMEM_GEMM);

    // 0) weight folds + raw concat->half
    fold_w_kernel<<<64, 256>>>(wq, qn_g, qn_b, bq, fwqk, fbqk, DD, INCC);
    fold_w_kernel<<<64, 256>>>(wk, kn_g, kn_b, bk, fwqk + (size_t)DD * INCC, fbqk + DD, DD, INCC);
    fold_w_kernel<<<64, 256>>>(wv, vn_g, vn_b, bv, fwv, fbv, DD, DD);
    fold_w_kernel<<<64, 256>>>(wo, nullptr, nullptr, nullptr, fwo, nullptr, DD, DD);
    fold_w_kernel<<<80, 256>>>(rw_w, nullptr, nullptr, nullptr, frw, nullptr, INCC, INCC);
    prep_xf_kernel<<<MTOK * INCC / 2048, 256>>>(x, f, xf);

    // x-side (independent of reweight)
    ln_norm_kernel<512><<<MTOK / 8, 256>>>(x, xn);
    dwconv_kernel<<<BT * GG, 256>>>(x, convv_w, convv_b, vg, DD);
    ln_norm_kernel<512><<<(BT * NGLOB) / 8, 256>>>(vg, vgn);

    // 1) reweight: qk = concat * sigmoid(concat @ rw_w^T + rw_b)
    mma_gemm<0,0><<<dim3(5, 256), 256, SMEM_GEMM>>>(
        xf, frw, rw_b, x, f, qk, nullptr, nullptr, MTOK, INCC, INCC, INCC);
    // qk-side
    ln_norm_kernel<640><<<MTOK / 8, 256>>>(qk, qkn);
    dwconv_kernel<<<BT * GG, 256>>>(qk, convk_w, convk_b, kg, INCC);
    ln_norm_kernel<640><<<(BT * NGLOB) / 8, 256>>>(kg, kgn);

    // 2) projections
    mma_gemm<1,1><<<dim3(8, 256), 256, SMEM_GEMM>>>(
        qkn, fwqk, fbqk, nullptr, nullptr, nullptr, Q, Kl, MTOK, 2 * DD, INCC, DD);
    mma_gemm<2,0><<<dim3(4, 4), 256, SMEM_GEMM>>>(
        kgn, fwqk + (size_t)DD * INCC, fbqk + DD, nullptr, nullptr, nullptr, Kg, nullptr,
        BT * NGLOB, DD, INCC, DD);
    mma_gemm<1,0><<<dim3(4, 256), 256, SMEM_GEMM>>>(
        xn, fwv, fbv, nullptr, nullptr, nullptr, Vl, nullptr, MTOK, DD, DD, DD);
    mma_gemm<2,0><<<dim3(4, 4), 256, SMEM_GEMM>>>(
        vgn, fwv, fbv, nullptr, nullptr, nullptr, Vg, nullptr, BT * NGLOB, DD, DD, DD);

    // 3) attention
    attn_kernel<<<BT * GG * NHEAD, 256, ATTN_SMEM_BYTES>>>(Q, Kl, Kg, Vl, Vg, O);

    // 4) out projection (window-reverse gather, fp32 final output)
    mma_gemm<3,0><<<dim3(4, 256), 256, SMEM_GEMM>>>(
        O, fwo, bo, nullptr, nullptr, out, nullptr, nullptr, MTOK, DD, DD, DD);
}

// round 9
// speedup vs baseline: 2.2274x; 1.0927x over previous
#include <cuda_runtime.h>
#include <cuda_fp16.h>
#include <cstdint>

// ---------------- problem constants ----------------
#define BT     8
#define NPIX   4096
#define DD     512
#define CFF    128
#define INCC   640
#define GG     64
#define NWIN   64
#define NGLOB  64
#define NHEAD  8
#define DHH    64
#define MTOK   32768

// ---------------- scratch ----------------
__device__ float  g_qk [MTOK*INCC];
__device__ float  g_kg [BT*NGLOB*INCC];
__device__ float  g_vg [BT*NGLOB*DD];
__device__ __half g_xf [MTOK*INCC];
__device__ __half g_qkn[MTOK*INCC];
__device__ __half g_xn [MTOK*DD];
__device__ __half g_kgn[BT*NGLOB*INCC];
__device__ __half g_vgn[BT*NGLOB*DD];
__device__ __half g_Q  [MTOK*DD];
__device__ __half g_Kl [MTOK*DD];
__device__ __half g_Vl [MTOK*DD];
__device__ __half g_Kg [BT*NGLOB*DD];
__device__ __half g_Vg [BT*NGLOB*DD];
__device__ __half g_O  [MTOK*DD];
__device__ __half g_fwqk[2*DD*INCC];
__device__ float  g_fbqk[2*DD];
__device__ __half g_fwv[DD*DD];
__device__ __half g_fwo[DD*DD];
__device__ __half g_frw[INCC*INCC];
__device__ float  g_fbv[DD];

// ---------------- helpers ----------------
__device__ __forceinline__ int win_map(int r) {
    int b = r >> 12;
    int p = r & 4095;
    int h = p >> 6, w = p & 63;
    int g = ((h >> 3) << 3) | (w >> 3);
    int n = ((h & 7) << 3) | (w & 7);
    return (((b << 6) | g) << 6) | n;
}

__device__ __forceinline__ uint32_t h2b(float a, float b) {
    __half2 h = __floats2half2_rn(a, b);
    return *(uint32_t*)&h;
}

__device__ __forceinline__ void mma_f16(float* d, const uint32_t* a, const uint32_t* b) {
    asm volatile(
        "mma.sync.aligned.m16n8k16.row.col.f32.f16.f16.f32 "
        "{%0,%1,%2,%3}, {%4,%5,%6,%7}, {%8,%9}, {%0,%1,%2,%3};"
        : "+f"(d[0]), "+f"(d[1]), "+f"(d[2]), "+f"(d[3])
        : "r"(a[0]), "r"(a[1]), "r"(a[2]), "r"(a[3]), "r"(b[0]), "r"(b[1]));
}

__device__ __forceinline__ void ldsm_x4(uint32_t* r, uint32_t addr) {
    asm volatile("ldmatrix.sync.aligned.m8n8.x4.shared.b16 {%0,%1,%2,%3}, [%4];"
                 : "=r"(r[0]), "=r"(r[1]), "=r"(r[2]), "=r"(r[3]) : "r"(addr));
}

#define CP_ASYNC16(dst, src) \
    asm volatile("cp.async.ca.shared.global [%0], [%1], 16;" :: "r"(dst), "l"(src))
#define CP_COMMIT() asm volatile("cp.async.commit_group;" ::: "memory")
#define CP_WAIT0()  asm volatile("cp.async.wait_group 0;" ::: "memory")

// ---------------- weight fold ----------------
__global__ __launch_bounds__(256)
void fold_w_kernel(const float* __restrict__ W, const float* __restrict__ gamma,
                   const float* __restrict__ beta, const float* __restrict__ b,
                   __half* __restrict__ Wo, float* __restrict__ bo, int N, int K) {
    int n = blockIdx.x * 8 + (threadIdx.x >> 5);
    if (n >= N) return;
    int lane = threadIdx.x & 31;
    const float* wr = W + (size_t)n * K;
    __half* wor = Wo + (size_t)n * K;
    float acc = 0.f;
    for (int k = lane; k < K; k += 32) {
        float w = wr[k];
        if (beta) acc += beta[k] * w;
        wor[k] = __float2half(gamma ? w * gamma[k] : w);
    }
    if (beta) {
        #pragma unroll
        for (int o = 16; o; o >>= 1) acc += __shfl_xor_sync(0xffffffffu, acc, o);
        if (lane == 0) bo[n] = b[n] + acc;
    }
}

// ---------------- raw concat(x,f) -> half ----------------
__global__ __launch_bounds__(256)
void prep_xf_kernel(const float* __restrict__ x, const float* __restrict__ f,
                    __half* __restrict__ xf) {
    size_t idx = ((size_t)blockIdx.x * 256 + threadIdx.x) * 8;
    int r = (int)(idx / INCC);
    int c = (int)(idx % INCC);
    const float* src = (c < 512) ? (x + (size_t)r * 512 + c)
                                 : (f + (size_t)r * 128 + (c - 512));
    float4 a = *(const float4*)src;
    float4 b = *(const float4*)(src + 4);
    uint4 o;
    o.x = h2b(a.x, a.y); o.y = h2b(a.z, a.w);
    o.z = h2b(b.x, b.y); o.w = h2b(b.z, b.w);
    *(uint4*)(xf + idx) = o;
}

// ---------------- fused LN: stats + normalize + half convert ----------------
template<int K>
__global__ __launch_bounds__(256)
void ln_norm_kernel(const float* __restrict__ X, __half* __restrict__ Xn) {
    const int NSEG = K / 128;
    int row = blockIdx.x * 8 + (threadIdx.x >> 5);
    int lane = threadIdx.x & 31;
    const float* xr = X + (size_t)row * K;
    float4 v[NSEG];
    float s = 0.f, ss = 0.f;
    #pragma unroll
    for (int i = 0; i < NSEG; i++) {
        v[i] = *(const float4*)(xr + lane * 4 + i * 128);
        s  += v[i].x + v[i].y + v[i].z + v[i].w;
        ss += v[i].x * v[i].x + v[i].y * v[i].y + v[i].z * v[i].z + v[i].w * v[i].w;
    }
    #pragma unroll
    for (int o = 16; o; o >>= 1) {
        s  += __shfl_xor_sync(0xffffffffu, s, o);
        ss += __shfl_xor_sync(0xffffffffu, ss, o);
    }
    float mean = s / K;
    float rstd = rsqrtf(ss / K - mean * mean + 1e-5f);
    __half* xo = Xn + (size_t)row * K;
    #pragma unroll
    for (int i = 0; i < NSEG; i++) {
        uint2 o;
        o.x = h2b((v[i].x - mean) * rstd, (v[i].y - mean) * rstd);
        o.y = h2b((v[i].z - mean) * rstd, (v[i].w - mean) * rstd);
        *(uint2*)(xo + lane * 4 + i * 128) = o;
    }
}

// ---------------- depthwise 8x8 stride-8 conv ----------------
__global__ __launch_bounds__(256)
void dwconv_kernel(const float* __restrict__ X, const float* __restrict__ Wc,
                   const float* __restrict__ bc, float* __restrict__ out, int C) {
    int bw = blockIdx.x;
    int b = bw >> 6;
    int g = bw & 63;
    int gh = g >> 3, gw = g & 7;
    const float* xb = X + (size_t)b * NPIX * C;
    for (int c = threadIdx.x; c < C; c += 256) {
        float s = bc[c];
        #pragma unroll
        for (int i = 0; i < 8; i++)
            #pragma unroll
            for (int j = 0; j < 8; j++)
                s += xb[(size_t)((gh * 8 + i) * 64 + (gw * 8 + j)) * C + c]
                     * Wc[c * 64 + i * 8 + j];
        out[(size_t)bw * C + c] = s;
    }
}

// ---------------- fp16 mma GEMM, pure cp.async mainloop ----------------
#define GS 72
template<int MODE, int SPLIT>
__global__ __launch_bounds__(256)
void mma_gemm(const __half* __restrict__ A, const __half* __restrict__ W,
              const float* __restrict__ bias,
              const float* __restrict__ Xraw, const float* __restrict__ Fraw,
              float* __restrict__ Cf, __half* __restrict__ Ch, __half* __restrict__ Ch2,
              int M, int N, int K, int ldc) {
    extern __shared__ __half sh[];
    __half* As = sh;
    __half* Bs = sh + 2 * 128 * GS;

    const int tid = threadIdx.x;
    const int m0 = blockIdx.y * 128;
    const int n0 = blockIdx.x * 128;
    const int q = tid & 7;
    const int lrow = tid >> 3;
    const int lane = tid & 31, grp = lane >> 2, tig = lane & 3;
    const int w = tid >> 5, mblk = (w & 3) * 32, nblk = (w >> 2) * 64;
    const int NC = K >> 6;

    const uint32_t as_s = (uint32_t)__cvta_generic_to_shared(As);
    const uint32_t bs_s = (uint32_t)__cvta_generic_to_shared(Bs);

    const uint32_t aoff0 = (uint32_t)(((mblk + (lane & 15)) * GS + (lane >> 4) * 8) * 2);
    const uint32_t aoff1 = aoff0 + (uint32_t)(16 * GS * 2);
    const uint32_t boff  = (uint32_t)(((nblk + (lane & 7) + ((lane & 16) ? 8 : 0)) * GS
                                       + ((lane & 8) ? 8 : 0)) * 2);

    int arow[4];
    #pragma unroll
    for (int i = 0; i < 4; i++) {
        int r = m0 + lrow + i * 32;
        arow[i] = (MODE == 3) ? win_map(r) : r;
    }

    float acc[2][8][4];
    #pragma unroll
    for (int mt = 0; mt < 2; mt++)
        #pragma unroll
        for (int nt = 0; nt < 8; nt++)
            #pragma unroll
            for (int e = 0; e < 4; e++) acc[mt][nt][e] = 0.f;

    auto issue = [&](int ch, int buf) {
        int gk = (ch << 6) + q * 8;
        #pragma unroll
        for (int i = 0; i < 4; i++) {
            int r = lrow + i * 32;
            CP_ASYNC16(as_s + (uint32_t)(((buf * 128 + r) * GS + q * 8) * 2),
                       A + (size_t)arow[i] * K + gk);
            CP_ASYNC16(bs_s + (uint32_t)(((buf * 128 + r) * GS + q * 8) * 2),
                       W + (size_t)(n0 + r) * K + gk);
        }
        CP_COMMIT();
    };
    auto compute = [&](int buf) {
        uint32_t abase = as_s + (uint32_t)(buf * 128 * GS * 2);
        uint32_t bbase = bs_s + (uint32_t)(buf * 128 * GS * 2);
        #pragma unroll
        for (int k16 = 0; k16 < 4; k16++) {
            uint32_t kb = (uint32_t)(k16 * 32);
            uint32_t af0[4], af1[4];
            ldsm_x4(af0, abase + aoff0 + kb);
            ldsm_x4(af1, abase + aoff1 + kb);
            #pragma unroll
            for (int p = 0; p < 4; p++) {
                uint32_t bf[4];
                ldsm_x4(bf, bbase + boff + (uint32_t)(p * 16 * GS * 2) + kb);
                mma_f16(acc[0][2 * p],     af0, bf);
                mma_f16(acc[1][2 * p],     af1, bf);
                mma_f16(acc[0][2 * p + 1], af0, bf + 2);
                mma_f16(acc[1][2 * p + 1], af1, bf + 2);
            }
        }
    };

    issue(0, 0);
    CP_WAIT0();
    __syncthreads();

    for (int ch = 0; ch < NC; ch++) {
        int buf = ch & 1;
        int nx = ch + 1;
        if (nx < NC) issue(nx, buf ^ 1);
        compute(buf);
        if (nx < NC) CP_WAIT0();
        __syncthreads();
    }

    #pragma unroll
    for (int mt = 0; mt < 2; mt++) {
        #pragma unroll
        for (int hr = 0; hr < 2; hr++) {
            int r = m0 + mblk + mt * 16 + grp + hr * 8;
            size_t orow = (MODE == 1) ? (size_t)win_map(r) : (size_t)r;
            #pragma unroll
            for (int nt = 0; nt < 8; nt++) {
                int c = n0 + nblk + nt * 8 + 2 * tig;
                float y0 = acc[mt][nt][hr * 2 + 0] + bias[c];
                float y1 = acc[mt][nt][hr * 2 + 1] + bias[c + 1];
                if (MODE == 0) {
                    float a0 = (c < 512) ? Xraw[(size_t)r * 512 + c]
                                         : Fraw[(size_t)r * 128 + (c - 512)];
                    float a1 = (c + 1 < 512) ? Xraw[(size_t)r * 512 + c + 1]
                                             : Fraw[(size_t)r * 128 + (c + 1 - 512)];
                    y0 = a0 / (1.f + __expf(-y0));
                    y1 = a1 / (1.f + __expf(-y1));
                    *(float2*)(Cf + orow * (size_t)ldc + c) = make_float2(y0, y1);
                } else if (MODE == 3) {
                    *(float2*)(Cf + orow * (size_t)ldc + c) = make_float2(y0, y1);
                } else {
                    __half* base = Ch;
                    int cc = c;
                    if (SPLIT) { base = (c < 512) ? Ch : Ch2; cc = c & 511; }
                    *(__half2*)(base + orow * (size_t)ldc + cc) = __floats2half2_rn(y0, y1);
                }
            }
        }
    }
}

// ---------------- attention ----------------
#define AQ_STR 72
#define AV_STR 136
#define ATTN_SMEM_BYTES (64*AQ_STR*2 + 128*AQ_STR*2 + 64*AV_STR*2 + 64*AV_STR*2 + 64*132*4)

__global__ __launch_bounds__(256)
void attn_kernel(const __half* __restrict__ Q, const __half* __restrict__ Kl,
                 const __half* __restrict__ Kg, const __half* __restrict__ Vl,
                 const __half* __restrict__ Vg, __half* __restrict__ O) {
    extern __shared__ char smraw[];
    __half* Qs = (__half*)smraw;
    __half* Ks = Qs + 64 * AQ_STR;
    __half* Vt = Ks + 128 * AQ_STR;
    __half* Ps = Vt + 64 * AV_STR;
    float*  Sf = (float*)(Ps + 64 * AV_STR);

    int bid = blockIdx.x;
    int b = bid >> 9;
    int rem = bid & 511;
    int g = rem >> 3;
    int h = rem & 7;

    size_t wbase = ((size_t)(b * GG + g) * NWIN) * DD + (size_t)h * DHH;
    size_t gbase = ((size_t)b * NGLOB) * DD + (size_t)h * DHH;
    const __half* Qp  = Q  + wbase;
    const __half* Klp = Kl + wbase;
    const __half* Vlp = Vl + wbase;
    const __half* Kgp = Kg + gbase;
    const __half* Vgp = Vg + gbase;
    __half* Op = O + wbase;

    int tid = threadIdx.x;
    const uint32_t qs_s = (uint32_t)__cvta_generic_to_shared(Qs);
    const uint32_t ks_s = (uint32_t)__cvta_generic_to_shared(Ks);
    const uint32_t vt_s = (uint32_t)__cvta_generic_to_shared(Vt);
    const uint32_t ps_s = (uint32_t)__cvta_generic_to_shared(Ps);

    for (int e = tid; e < 64 * 8; e += 256) {
        int m = e >> 3, sg = e & 7;
        CP_ASYNC16(qs_s + (uint32_t)((m * AQ_STR + sg * 8) * 2), Qp + (size_t)m * DD + sg * 8);
    }
    for (int e = tid; e < 128 * 8; e += 256) {
        int kk = e >> 3, sg = e & 7;
        const __half* ksrc = (kk < 64) ? (Klp + (size_t)kk * DD)
                                       : (Kgp + (size_t)(kk - 64) * DD);
        CP_ASYNC16(ks_s + (uint32_t)((kk * AQ_STR + sg * 8) * 2), ksrc + sg * 8);
    }
    CP_COMMIT();
    for (int e = tid; e < 128 * 8; e += 256) {
        int kk = e >> 3, sg = e & 7;
        const __half* vsrc = (kk < 64) ? (Vlp + (size_t)kk * DD)
                                       : (Vgp + (size_t)(kk - 64) * DD);
        uint4 pv = *(const uint4*)(vsrc + sg * 8);
        const __half* ph = (const __half*)&pv;
        #pragma unroll
        for (int j = 0; j < 8; j++)
            Vt[(sg * 8 + j) * AV_STR + kk] = ph[j];
    }
    CP_WAIT0();
    __syncthreads();

    int w = tid >> 5, lane = tid & 31, grp = lane >> 2, tig = lane & 3;
    int mrow = (w & 3) * 16;

    {
        int nb0 = (w >> 2) * 64;
        const uint32_t aoff = qs_s +
            (uint32_t)(((mrow + (lane & 15)) * AQ_STR + (lane >> 4) * 8) * 2);
        const uint32_t boff = ks_s +
            (uint32_t)(((nb0 + (lane & 7) + ((lane & 16) ? 8 : 0)) * AQ_STR
                        + ((lane & 8) ? 8 : 0)) * 2);
        float acc[8][4];
        #pragma unroll
        for (int nt = 0; nt < 8; nt++)
            #pragma unroll
            for (int e = 0; e < 4; e++) acc[nt][e] = 0.f;
        #pragma unroll
        for (int k16 = 0; k16 < 4; k16++) {
            uint32_t kb = (uint32_t)(k16 * 32);
            uint32_t af[4];
            ldsm_x4(af, aoff + kb);
            #pragma unroll
            for (int p = 0; p < 4; p++) {
                uint32_t bf[4];
                ldsm_x4(bf, boff + (uint32_t)(p * 16 * AQ_STR * 2) + kb);
                mma_f16(acc[2 * p],     af, bf);
                mma_f16(acc[2 * p + 1], af, bf + 2);
            }
        }
        #pragma unroll
        for (int nt = 0; nt < 8; nt++) {
            int c = nb0 + nt * 8 + 2 * tig;
            Sf[(mrow + grp)     * 132 + c]     = acc[nt][0] * 0.125f;
            Sf[(mrow + grp)     * 132 + c + 1] = acc[nt][1] * 0.125f;
            Sf[(mrow + grp + 8) * 132 + c]     = acc[nt][2] * 0.125f;
            Sf[(mrow + grp + 8) * 132 + c + 1] = acc[nt][3] * 0.125f;
        }
    }
    __syncthreads();

    for (int m = w; m < 64; m += 8) {
        float* sr = &Sf[m * 132];
        float v0 = sr[lane], v1 = sr[lane + 32], v2 = sr[lane + 64], v3 = sr[lane + 96];
        float mx = fmaxf(fmaxf(v0, v1), fmaxf(v2, v3));
        #pragma unroll
        for (int o = 16; o; o >>= 1) mx = fmaxf(mx, __shfl_xor_sync(0xffffffffu, mx, o));
        float e0 = __expf(v0 - mx), e1 = __expf(v1 - mx);
        float e2 = __expf(v2 - mx), e3 = __expf(v3 - mx);
        float s = e0 + e1 + e2 + e3;
        #pragma unroll
        for (int o = 16; o; o >>= 1) s += __shfl_xor_sync(0xffffffffu, s, o);
        float inv = 1.f / s;
        __half* pr = &Ps[m * AV_STR];
        pr[lane]      = __float2half(e0 * inv);
        pr[lane + 32] = __float2half(e1 * inv);
        pr[lane + 64] = __float2half(e2 * inv);
        pr[lane + 96] = __float2half(e3 * inv);
    }
    __syncthreads();

    {
        int db0 = (w >> 2) * 32;
        const uint32_t aoff = ps_s +
            (uint32_t)(((mrow + (lane & 15)) * AV_STR + (lane >> 4) * 8) * 2);
        const uint32_t boff = vt_s +
            (uint32_t)(((db0 + (lane & 7) + ((lane & 16) ? 8 : 0)) * AV_STR
                        + ((lane & 8) ? 8 : 0)) * 2);
        float acc[4][4];
        #pragma unroll
        for (int nt = 0; nt < 4; nt++)
            #pragma unroll
            for (int e = 0; e < 4; e++) acc[nt][e] = 0.f;
        #pragma unroll
        for (int k16 = 0; k16 < 8; k16++) {
            uint32_t kb = (uint32_t)(k16 * 32);
            uint32_t af[4];
            ldsm_x4(af, aoff + kb);
            #pragma unroll
            for (int p = 0; p < 2; p++) {
                uint32_t bf[4];
                ldsm_x4(bf, boff + (uint32_t)(p * 16 * AV_STR * 2) + kb);
                mma_f16(acc[2 * p],     af, bf);
                mma_f16(acc[2 * p + 1], af, bf + 2);
            }
        }
        #pragma unroll
        for (int nt = 0; nt < 4; nt++) {
            int c = db0 + nt * 8 + 2 * tig;
            *(__half2*)(Op + (size_t)(mrow + grp) * DD + c) =
                __floats2half2_rn(acc[nt][0], acc[nt][1]);
            *(__half2*)(Op + (size_t)(mrow + grp + 8) * DD + c) =
                __floats2half2_rn(acc[nt][2], acc[nt][3]);
        }
    }
}

// ---------------- launch ----------------
#define SMEM_GEMM (4 * 128 * GS * 2)

extern "C" void kernel_launch(void* const* d_in, const int* in_sizes, int n_in,
                              void* d_out, int out_size) {
    const float* x       = (const float*)d_in[0];
    const float* f       = (const float*)d_in[1];
    const float* wq      = (const float*)d_in[2];
    const float* bq      = (const float*)d_in[3];
    const float* wk      = (const float*)d_in[4];
    const float* bk      = (const float*)d_in[5];
    const float* wv      = (const float*)d_in[6];
    const float* bv      = (const float*)d_in[7];
    const float* wo      = (const float*)d_in[8];
    const float* bo      = (const float*)d_in[9];
    const float* rw_w    = (const float*)d_in[10];
    const float* rw_b    = (const float*)d_in[11];
    const float* convk_w = (const float*)d_in[12];
    const float* convk_b = (const float*)d_in[13];
    const float* convv_w = (const float*)d_in[14];
    const float* convv_b = (const float*)d_in[15];
    const float* qn_g    = (const float*)d_in[16];
    const float* qn_b    = (const float*)d_in[17];
    const float* kn_g    = (const float*)d_in[18];
    const float* kn_b    = (const float*)d_in[19];
    const float* vn_g    = (const float*)d_in[20];
    const float* vn_b    = (const float*)d_in[21];
    float* out = (float*)d_out;

    float *qk, *kg, *vg, *fbqk, *fbv;
    __half *xf, *qkn, *xn, *kgn, *vgn, *Q, *Kl, *Vl, *Kg, *Vg, *O;
    __half *fwqk, *fwv, *fwo, *frw;
    cudaGetSymbolAddress((void**)&qk,   g_qk);
    cudaGetSymbolAddress((void**)&kg,   g_kg);
    cudaGetSymbolAddress((void**)&vg,   g_vg);
    cudaGetSymbolAddress((void**)&xf,   g_xf);
    cudaGetSymbolAddress((void**)&qkn,  g_qkn);
    cudaGetSymbolAddress((void**)&xn,   g_xn);
    cudaGetSymbolAddress((void**)&kgn,  g_kgn);
    cudaGetSymbolAddress((void**)&vgn,  g_vgn);
    cudaGetSymbolAddress((void**)&Q,    g_Q);
    cudaGetSymbolAddress((void**)&Kl,   g_Kl);
    cudaGetSymbolAddress((void**)&Vl,   g_Vl);
    cudaGetSymbolAddress((void**)&Kg,   g_Kg);
    cudaGetSymbolAddress((void**)&Vg,   g_Vg);
    cudaGetSymbolAddress((void**)&O,    g_O);
    cudaGetSymbolAddress((void**)&fwqk, g_fwqk);
    cudaGetSymbolAddress((void**)&fbqk, g_fbqk);
    cudaGetSymbolAddress((void**)&fwv,  g_fwv);
    cudaGetSymbolAddress((void**)&fwo,  g_fwo);
    cudaGetSymbolAddress((void**)&frw,  g_frw);
    cudaGetSymbolAddress((void**)&fbv,  g_fbv);

    cudaFuncSetAttribute(attn_kernel, cudaFuncAttributeMaxDynamicSharedMemorySize,
                         ATTN_SMEM_BYTES);
    cudaFuncSetAttribute(mma_gemm<0,0>, cudaFuncAttributeMaxDynamicSharedMemorySize, SMEM_GEMM);
    cudaFuncSetAttribute(mma_gemm<1,1>, cudaFuncAttributeMaxDynamicSharedMemorySize, SMEM_GEMM);
    cudaFuncSetAttribute(mma_gemm<1,0>, cudaFuncAttributeMaxDynamicSharedMemorySize, SMEM_GEMM);
    cudaFuncSetAttribute(mma_gemm<2,0>, cudaFuncAttributeMaxDynamicSharedMemorySize, SMEM_GEMM);
    cudaFuncSetAttribute(mma_gemm<3,0>, cudaFuncAttributeMaxDynamicSharedMemorySize, SMEM_GEMM);

    // ---- forked-stream graph: s1 carries the x-side chain ----
    cudaStream_t s1;
    cudaStreamCreateWithFlags(&s1, cudaStreamNonBlocking);
    cudaEvent_t evFork, evJoin;
    cudaEventCreateWithFlags(&evFork, cudaEventDisableTiming);
    cudaEventCreateWithFlags(&evJoin, cudaEventDisableTiming);

    cudaEventRecord(evFork, 0);
    cudaStreamWaitEvent(s1, evFork, 0);

    // ---- stream s1: x-side (independent of the reweight chain) ----
    fold_w_kernel<<<64, 256, 0, s1>>>(wv, vn_g, vn_b, bv, fwv, fbv, DD, DD);
    fold_w_kernel<<<64, 256, 0, s1>>>(wo, nullptr, nullptr, nullptr, fwo, nullptr, DD, DD);
    ln_norm_kernel<512><<<MTOK / 8, 256, 0, s1>>>(x, xn);
    dwconv_kernel<<<BT * GG, 256, 0, s1>>>(x, convv_w, convv_b, vg, DD);
    ln_norm_kernel<512><<<(BT * NGLOB) / 8, 256, 0, s1>>>(vg, vgn);
    mma_gemm<1,0><<<dim3(4, 256), 256, SMEM_GEMM, s1>>>(
        xn, fwv, fbv, nullptr, nullptr, nullptr, Vl, nullptr, MTOK, DD, DD, DD);
    mma_gemm<2,0><<<dim3(4, 4), 256, SMEM_GEMM, s1>>>(
        vgn, fwv, fbv, nullptr, nullptr, nullptr, Vg, nullptr, BT * NGLOB, DD, DD, DD);
    cudaEventRecord(evJoin, s1);

    // ---- default stream: qk chain (critical path) ----
    fold_w_kernel<<<80, 256>>>(rw_w, nullptr, nullptr, nullptr, frw, nullptr, INCC, INCC);
    fold_w_kernel<<<64, 256>>>(wq, qn_g, qn_b, bq, fwqk, fbqk, DD, INCC);
    fold_w_kernel<<<64, 256>>>(wk, kn_g, kn_b, bk, fwqk + (size_t)DD * INCC, fbqk + DD, DD, INCC);
    prep_xf_kernel<<<MTOK * INCC / 2048, 256>>>(x, f, xf);

    mma_gemm<0,0><<<dim3(5, 256), 256, SMEM_GEMM>>>(
        xf, frw, rw_b, x, f, qk, nullptr, nullptr, MTOK, INCC, INCC, INCC);
    ln_norm_kernel<640><<<MTOK / 8, 256>>>(qk, qkn);
    dwconv_kernel<<<BT * GG, 256>>>(qk, convk_w, convk_b, kg, INCC);
    ln_norm_kernel<640><<<(BT * NGLOB) / 8, 256>>>(kg, kgn);

    mma_gemm<1,1><<<dim3(8, 256), 256, SMEM_GEMM>>>(
        qkn, fwqk, fbqk, nullptr, nullptr, nullptr, Q, Kl, MTOK, 2 * DD, INCC, DD);
    mma_gemm<2,0><<<dim3(4, 4), 256, SMEM_GEMM>>>(
        kgn, fwqk + (size_t)DD * INCC, fbqk + DD, nullptr, nullptr, nullptr, Kg, nullptr,
        BT * NGLOB, DD, INCC, DD);

    // ---- join: attention needs Vl/Vg from s1 ----
    cudaStreamWaitEvent(0, evJoin, 0);
    attn_kernel<<<BT * GG * NHEAD, 256, ATTN_SMEM_BYTES>>>(Q, Kl, Kg, Vl, Vg, O);
    mma_gemm<3,0><<<dim3(4, 256), 256, SMEM_GEMM>>>(
        O, fwo, bo, nullptr, nullptr, out, nullptr, nullptr, MTOK, DD, DD, DD);

    cudaEventDestroy(evFork);
    cudaEventDestroy(evJoin);
    cudaStreamDestroy(s1);
}

// round 10
// speedup vs baseline: 2.3147x; 1.0392x over previous
#include <cuda_runtime.h>
#include <cuda_fp16.h>
#include <cstdint>

// ---------------- problem constants ----------------
#define BT     8
#define NPIX   4096
#define DD     512
#define CFF    128
#define INCC   640
#define GG     64
#define NWIN   64
#define NGLOB  64
#define NHEAD  8
#define DHH    64
#define MTOK   32768

// ---------------- scratch ----------------
__device__ float  g_qk [MTOK*INCC];
__device__ float  g_kg [BT*NGLOB*INCC];
__device__ float  g_vg [BT*NGLOB*DD];
__device__ __half g_xf [MTOK*INCC];
__device__ __half g_qkn[MTOK*INCC];
__device__ __half g_xn [MTOK*DD];
__device__ __half g_kgn[BT*NGLOB*INCC];
__device__ __half g_vgn[BT*NGLOB*DD];
__device__ __half g_Q  [MTOK*DD];
__device__ __half g_Kl [MTOK*DD];
__device__ __half g_Vl [MTOK*DD];
__device__ __half g_Kg [BT*NGLOB*DD];
__device__ __half g_Vg [BT*NGLOB*DD];
__device__ __half g_O  [MTOK*DD];
__device__ __half g_fwqk[2*DD*INCC];
__device__ float  g_fbqk[2*DD];
__device__ __half g_fwv[DD*DD];
__device__ __half g_fwo[DD*DD];
__device__ __half g_frw[INCC*INCC];
__device__ float  g_fbv[DD];

// ---------------- helpers ----------------
__device__ __forceinline__ int win_map(int r) {
    int b = r >> 12;
    int p = r & 4095;
    int h = p >> 6, w = p & 63;
    int g = ((h >> 3) << 3) | (w >> 3);
    int n = ((h & 7) << 3) | (w & 7);
    return (((b << 6) | g) << 6) | n;
}

__device__ __forceinline__ uint32_t h2b(float a, float b) {
    __half2 h = __floats2half2_rn(a, b);
    return *(uint32_t*)&h;
}

__device__ __forceinline__ void mma_f16(float* d, const uint32_t* a, const uint32_t* b) {
    asm volatile(
        "mma.sync.aligned.m16n8k16.row.col.f32.f16.f16.f32 "
        "{%0,%1,%2,%3}, {%4,%5,%6,%7}, {%8,%9}, {%0,%1,%2,%3};"
        : "+f"(d[0]), "+f"(d[1]), "+f"(d[2]), "+f"(d[3])
        : "r"(a[0]), "r"(a[1]), "r"(a[2]), "r"(a[3]), "r"(b[0]), "r"(b[1]));
}

__device__ __forceinline__ void ldsm_x4(uint32_t* r, uint32_t addr) {
    asm volatile("ldmatrix.sync.aligned.m8n8.x4.shared.b16 {%0,%1,%2,%3}, [%4];"
                 : "=r"(r[0]), "=r"(r[1]), "=r"(r[2]), "=r"(r[3]) : "r"(addr));
}

#define CP_ASYNC16(dst, src) \
    asm volatile("cp.async.ca.shared.global [%0], [%1], 16;" :: "r"(dst), "l"(src))
#define CP_COMMIT() asm volatile("cp.async.commit_group;" ::: "memory")
#define CP_WAIT0()  asm volatile("cp.async.wait_group 0;" ::: "memory")

// ---------------- weight fold ----------------
__global__ __launch_bounds__(256)
void fold_w_kernel(const float* __restrict__ W, const float* __restrict__ gamma,
                   const float* __restrict__ beta, const float* __restrict__ b,
                   __half* __restrict__ Wo, float* __restrict__ bo, int N, int K) {
    int n = blockIdx.x * 8 + (threadIdx.x >> 5);
    if (n >= N) return;
    int lane = threadIdx.x & 31;
    const float* wr = W + (size_t)n * K;
    __half* wor = Wo + (size_t)n * K;
    float acc = 0.f;
    for (int k = lane; k < K; k += 32) {
        float w = wr[k];
        if (beta) acc += beta[k] * w;
        wor[k] = __float2half(gamma ? w * gamma[k] : w);
    }
    if (beta) {
        #pragma unroll
        for (int o = 16; o; o >>= 1) acc += __shfl_xor_sync(0xffffffffu, acc, o);
        if (lane == 0) bo[n] = b[n] + acc;
    }
}

// ---------------- raw concat(x,f) -> half ----------------
__global__ __launch_bounds__(256)
void prep_xf_kernel(const float* __restrict__ x, const float* __restrict__ f,
                    __half* __restrict__ xf) {
    size_t idx = ((size_t)blockIdx.x * 256 + threadIdx.x) * 8;
    int r = (int)(idx / INCC);
    int c = (int)(idx % INCC);
    const float* src = (c < 512) ? (x + (size_t)r * 512 + c)
                                 : (f + (size_t)r * 128 + (c - 512));
    float4 a = *(const float4*)src;
    float4 b = *(const float4*)(src + 4);
    uint4 o;
    o.x = h2b(a.x, a.y); o.y = h2b(a.z, a.w);
    o.z = h2b(b.x, b.y); o.w = h2b(b.z, b.w);
    *(uint4*)(xf + idx) = o;
}

// ---------------- fused LN: stats + normalize + half convert ----------------
template<int K>
__global__ __launch_bounds__(256)
void ln_norm_kernel(const float* __restrict__ X, __half* __restrict__ Xn) {
    const int NSEG = K / 128;
    int row = blockIdx.x * 8 + (threadIdx.x >> 5);
    int lane = threadIdx.x & 31;
    const float* xr = X + (size_t)row * K;
    float4 v[NSEG];
    float s = 0.f, ss = 0.f;
    #pragma unroll
    for (int i = 0; i < NSEG; i++) {
        v[i] = *(const float4*)(xr + lane * 4 + i * 128);
        s  += v[i].x + v[i].y + v[i].z + v[i].w;
        ss += v[i].x * v[i].x + v[i].y * v[i].y + v[i].z * v[i].z + v[i].w * v[i].w;
    }
    #pragma unroll
    for (int o = 16; o; o >>= 1) {
        s  += __shfl_xor_sync(0xffffffffu, s, o);
        ss += __shfl_xor_sync(0xffffffffu, ss, o);
    }
    float mean = s / K;
    float rstd = rsqrtf(ss / K - mean * mean + 1e-5f);
    __half* xo = Xn + (size_t)row * K;
    #pragma unroll
    for (int i = 0; i < NSEG; i++) {
        uint2 o;
        o.x = h2b((v[i].x - mean) * rstd, (v[i].y - mean) * rstd);
        o.y = h2b((v[i].z - mean) * rstd, (v[i].w - mean) * rstd);
        *(uint2*)(xo + lane * 4 + i * 128) = o;
    }
}

// ---------------- depthwise 8x8 stride-8 conv, high-parallelism ----------------
// grid (C/128, BT*GG), 128 threads; one channel per thread, 64 unrolled loads.
template<int C>
__global__ __launch_bounds__(128)
void dwconv_kernel(const float* __restrict__ X, const float* __restrict__ Wc,
                   const float* __restrict__ bc, float* __restrict__ out) {
    int bw = blockIdx.y;
    int c = blockIdx.x * 128 + threadIdx.x;
    int b = bw >> 6;
    int g = bw & 63;
    int gh = g >> 3, gw = g & 7;
    const float* xb = X + ((size_t)b * NPIX + (size_t)(gh * 8) * 64 + gw * 8) * C + c;
    const float* wc = Wc + c * 64;
    float s = bc[c];
    #pragma unroll
    for (int i = 0; i < 8; i++)
        #pragma unroll
        for (int j = 0; j < 8; j++)
            s += xb[(size_t)(i * 64 + j) * C] * wc[i * 8 + j];
    out[(size_t)bw * C + c] = s;
}

// ---------------- fp16 mma GEMM, pure cp.async mainloop ----------------
#define GS 72
template<int MODE, int SPLIT>
__global__ __launch_bounds__(256)
void mma_gemm(const __half* __restrict__ A, const __half* __restrict__ W,
              const float* __restrict__ bias,
              const float* __restrict__ Xraw, const float* __restrict__ Fraw,
              float* __restrict__ Cf, __half* __restrict__ Ch, __half* __restrict__ Ch2,
              int M, int N, int K, int ldc) {
    extern __shared__ __half sh[];
    __half* As = sh;
    __half* Bs = sh + 2 * 128 * GS;

    const int tid = threadIdx.x;
    const int m0 = blockIdx.y * 128;
    const int n0 = blockIdx.x * 128;
    const int q = tid & 7;
    const int lrow = tid >> 3;
    const int lane = tid & 31, grp = lane >> 2, tig = lane & 3;
    const int w = tid >> 5, mblk = (w & 3) * 32, nblk = (w >> 2) * 64;
    const int NC = K >> 6;

    const uint32_t as_s = (uint32_t)__cvta_generic_to_shared(As);
    const uint32_t bs_s = (uint32_t)__cvta_generic_to_shared(Bs);

    const uint32_t aoff0 = (uint32_t)(((mblk + (lane & 15)) * GS + (lane >> 4) * 8) * 2);
    const uint32_t aoff1 = aoff0 + (uint32_t)(16 * GS * 2);
    const uint32_t boff  = (uint32_t)(((nblk + (lane & 7) + ((lane & 16) ? 8 : 0)) * GS
                                       + ((lane & 8) ? 8 : 0)) * 2);

    int arow[4];
    #pragma unroll
    for (int i = 0; i < 4; i++) {
        int r = m0 + lrow + i * 32;
        arow[i] = (MODE == 3) ? win_map(r) : r;
    }

    float acc[2][8][4];
    #pragma unroll
    for (int mt = 0; mt < 2; mt++)
        #pragma unroll
        for (int nt = 0; nt < 8; nt++)
            #pragma unroll
            for (int e = 0; e < 4; e++) acc[mt][nt][e] = 0.f;

    auto issue = [&](int ch, int buf) {
        int gk = (ch << 6) + q * 8;
        #pragma unroll
        for (int i = 0; i < 4; i++) {
            int r = lrow + i * 32;
            CP_ASYNC16(as_s + (uint32_t)(((buf * 128 + r) * GS + q * 8) * 2),
                       A + (size_t)arow[i] * K + gk);
            CP_ASYNC16(bs_s + (uint32_t)(((buf * 128 + r) * GS + q * 8) * 2),
                       W + (size_t)(n0 + r) * K + gk);
        }
        CP_COMMIT();
    };
    auto compute = [&](int buf) {
        uint32_t abase = as_s + (uint32_t)(buf * 128 * GS * 2);
        uint32_t bbase = bs_s + (uint32_t)(buf * 128 * GS * 2);
        #pragma unroll
        for (int k16 = 0; k16 < 4; k16++) {
            uint32_t kb = (uint32_t)(k16 * 32);
            uint32_t af0[4], af1[4];
            ldsm_x4(af0, abase + aoff0 + kb);
            ldsm_x4(af1, abase + aoff1 + kb);
            #pragma unroll
            for (int p = 0; p < 4; p++) {
                uint32_t bf[4];
                ldsm_x4(bf, bbase + boff + (uint32_t)(p * 16 * GS * 2) + kb);
                mma_f16(acc[0][2 * p],     af0, bf);
                mma_f16(acc[1][2 * p],     af1, bf);
                mma_f16(acc[0][2 * p + 1], af0, bf + 2);
                mma_f16(acc[1][2 * p + 1], af1, bf + 2);
            }
        }
    };

    issue(0, 0);
    CP_WAIT0();
    __syncthreads();

    for (int ch = 0; ch < NC; ch++) {
        int buf = ch & 1;
        int nx = ch + 1;
        if (nx < NC) issue(nx, buf ^ 1);
        compute(buf);
        if (nx < NC) CP_WAIT0();
        __syncthreads();
    }

    #pragma unroll
    for (int mt = 0; mt < 2; mt++) {
        #pragma unroll
        for (int hr = 0; hr < 2; hr++) {
            int r = m0 + mblk + mt * 16 + grp + hr * 8;
            size_t orow = (MODE == 1) ? (size_t)win_map(r) : (size_t)r;
            #pragma unroll
            for (int nt = 0; nt < 8; nt++) {
                int c = n0 + nblk + nt * 8 + 2 * tig;
                float y0 = acc[mt][nt][hr * 2 + 0] + bias[c];
                float y1 = acc[mt][nt][hr * 2 + 1] + bias[c + 1];
                if (MODE == 0) {
                    float a0 = (c < 512) ? Xraw[(size_t)r * 512 + c]
                                         : Fraw[(size_t)r * 128 + (c - 512)];
                    float a1 = (c + 1 < 512) ? Xraw[(size_t)r * 512 + c + 1]
                                             : Fraw[(size_t)r * 128 + (c + 1 - 512)];
                    y0 = a0 / (1.f + __expf(-y0));
                    y1 = a1 / (1.f + __expf(-y1));
                    *(float2*)(Cf + orow * (size_t)ldc + c) = make_float2(y0, y1);
                } else if (MODE == 3) {
                    *(float2*)(Cf + orow * (size_t)ldc + c) = make_float2(y0, y1);
                } else {
                    __half* base = Ch;
                    int cc = c;
                    if (SPLIT) { base = (c < 512) ? Ch : Ch2; cc = c & 511; }
                    *(__half2*)(base + orow * (size_t)ldc + cc) = __floats2half2_rn(y0, y1);
                }
            }
        }
    }
}

// ---------------- attention ----------------
#define AQ_STR 72
#define AV_STR 136
#define ATTN_SMEM_BYTES (64*AQ_STR*2 + 128*AQ_STR*2 + 64*AV_STR*2 + 64*AV_STR*2 + 64*132*4)

__global__ __launch_bounds__(256)
void attn_kernel(const __half* __restrict__ Q, const __half* __restrict__ Kl,
                 const __half* __restrict__ Kg, const __half* __restrict__ Vl,
                 const __half* __restrict__ Vg, __half* __restrict__ O) {
    extern __shared__ char smraw[];
    __half* Qs = (__half*)smraw;
    __half* Ks = Qs + 64 * AQ_STR;
    __half* Vt = Ks + 128 * AQ_STR;
    __half* Ps = Vt + 64 * AV_STR;
    float*  Sf = (float*)(Ps + 64 * AV_STR);

    int bid = blockIdx.x;
    int b = bid >> 9;
    int rem = bid & 511;
    int g = rem >> 3;
    int h = rem & 7;

    size_t wbase = ((size_t)(b * GG + g) * NWIN) * DD + (size_t)h * DHH;
    size_t gbase = ((size_t)b * NGLOB) * DD + (size_t)h * DHH;
    const __half* Qp  = Q  + wbase;
    const __half* Klp = Kl + wbase;
    const __half* Vlp = Vl + wbase;
    const __half* Kgp = Kg + gbase;
    const __half* Vgp = Vg + gbase;
    __half* Op = O + wbase;

    int tid = threadIdx.x;
    const uint32_t qs_s = (uint32_t)__cvta_generic_to_shared(Qs);
    const uint32_t ks_s = (uint32_t)__cvta_generic_to_shared(Ks);
    const uint32_t vt_s = (uint32_t)__cvta_generic_to_shared(Vt);
    const uint32_t ps_s = (uint32_t)__cvta_generic_to_shared(Ps);

    for (int e = tid; e < 64 * 8; e += 256) {
        int m = e >> 3, sg = e & 7;
        CP_ASYNC16(qs_s + (uint32_t)((m * AQ_STR + sg * 8) * 2), Qp + (size_t)m * DD + sg * 8);
    }
    for (int e = tid; e < 128 * 8; e += 256) {
        int kk = e >> 3, sg = e & 7;
        const __half* ksrc = (kk < 64) ? (Klp + (size_t)kk * DD)
                                       : (Kgp + (size_t)(kk - 64) * DD);
        CP_ASYNC16(ks_s + (uint32_t)((kk * AQ_STR + sg * 8) * 2), ksrc + sg * 8);
    }
    CP_COMMIT();
    for (int e = tid; e < 128 * 8; e += 256) {
        int kk = e >> 3, sg = e & 7;
        const __half* vsrc = (kk < 64) ? (Vlp + (size_t)kk * DD)
                                       : (Vgp + (size_t)(kk - 64) * DD);
        uint4 pv = *(const uint4*)(vsrc + sg * 8);
        const __half* ph = (const __half*)&pv;
        #pragma unroll
        for (int j = 0; j < 8; j++)
            Vt[(sg * 8 + j) * AV_STR + kk] = ph[j];
    }
    CP_WAIT0();
    __syncthreads();

    int w = tid >> 5, lane = tid & 31, grp = lane >> 2, tig = lane & 3;
    int mrow = (w & 3) * 16;

    {
        int nb0 = (w >> 2) * 64;
        const uint32_t aoff = qs_s +
            (uint32_t)(((mrow + (lane & 15)) * AQ_STR + (lane >> 4) * 8) * 2);
        const uint32_t boff = ks_s +
            (uint32_t)(((nb0 + (lane & 7) + ((lane & 16) ? 8 : 0)) * AQ_STR
                        + ((lane & 8) ? 8 : 0)) * 2);
        float acc[8][4];
        #pragma unroll
        for (int nt = 0; nt < 8; nt++)
            #pragma unroll
            for (int e = 0; e < 4; e++) acc[nt][e] = 0.f;
        #pragma unroll
        for (int k16 = 0; k16 < 4; k16++) {
            uint32_t kb = (uint32_t)(k16 * 32);
            uint32_t af[4];
            ldsm_x4(af, aoff + kb);
            #pragma unroll
            for (int p = 0; p < 4; p++) {
                uint32_t bf[4];
                ldsm_x4(bf, boff + (uint32_t)(p * 16 * AQ_STR * 2) + kb);
                mma_f16(acc[2 * p],     af, bf);
                mma_f16(acc[2 * p + 1], af, bf + 2);
            }
        }
        #pragma unroll
        for (int nt = 0; nt < 8; nt++) {
            int c = nb0 + nt * 8 + 2 * tig;
            Sf[(mrow + grp)     * 132 + c]     = acc[nt][0] * 0.125f;
            Sf[(mrow + grp)     * 132 + c + 1] = acc[nt][1] * 0.125f;
            Sf[(mrow + grp + 8) * 132 + c]     = acc[nt][2] * 0.125f;
            Sf[(mrow + grp + 8) * 132 + c + 1] = acc[nt][3] * 0.125f;
        }
    }
    __syncthreads();

    for (int m = w; m < 64; m += 8) {
        float* sr = &Sf[m * 132];
        float v0 = sr[lane], v1 = sr[lane + 32], v2 = sr[lane + 64], v3 = sr[lane + 96];
        float mx = fmaxf(fmaxf(v0, v1), fmaxf(v2, v3));
        #pragma unroll
        for (int o = 16; o; o >>= 1) mx = fmaxf(mx, __shfl_xor_sync(0xffffffffu, mx, o));
        float e0 = __expf(v0 - mx), e1 = __expf(v1 - mx);
        float e2 = __expf(v2 - mx), e3 = __expf(v3 - mx);
        float s = e0 + e1 + e2 + e3;
        #pragma unroll
        for (int o = 16; o; o >>= 1) s += __shfl_xor_sync(0xffffffffu, s, o);
        float inv = 1.f / s;
        __half* pr = &Ps[m * AV_STR];
        pr[lane]      = __float2half(e0 * inv);
        pr[lane + 32] = __float2half(e1 * inv);
        pr[lane + 64] = __float2half(e2 * inv);
        pr[lane + 96] = __float2half(e3 * inv);
    }
    __syncthreads();

    {
        int db0 = (w >> 2) * 32;
        const uint32_t aoff = ps_s +
            (uint32_t)(((mrow + (lane & 15)) * AV_STR + (lane >> 4) * 8) * 2);
        const uint32_t boff = vt_s +
            (uint32_t)(((db0 + (lane & 7) + ((lane & 16) ? 8 : 0)) * AV_STR
                        + ((lane & 8) ? 8 : 0)) * 2);
        float acc[4][4];
        #pragma unroll
        for (int nt = 0; nt < 4; nt++)
            #pragma unroll
            for (int e = 0; e < 4; e++) acc[nt][e] = 0.f;
        #pragma unroll
        for (int k16 = 0; k16 < 8; k16++) {
            uint32_t kb = (uint32_t)(k16 * 32);
            uint32_t af[4];
            ldsm_x4(af, aoff + kb);
            #pragma unroll
            for (int p = 0; p < 2; p++) {
                uint32_t bf[4];
                ldsm_x4(bf, boff + (uint32_t)(p * 16 * AV_STR * 2) + kb);
                mma_f16(acc[2 * p],     af, bf);
                mma_f16(acc[2 * p + 1], af, bf + 2);
            }
        }
        #pragma unroll
        for (int nt = 0; nt < 4; nt++) {
            int c = db0 + nt * 8 + 2 * tig;
            *(__half2*)(Op + (size_t)(mrow + grp) * DD + c) =
                __floats2half2_rn(acc[nt][0], acc[nt][1]);
            *(__half2*)(Op + (size_t)(mrow + grp + 8) * DD + c) =
                __floats2half2_rn(acc[nt][2], acc[nt][3]);
        }
    }
}

// ---------------- launch ----------------
#define SMEM_GEMM (4 * 128 * GS * 2)

extern "C" void kernel_launch(void* const* d_in, const int* in_sizes, int n_in,
                              void* d_out, int out_size) {
    const float* x       = (const float*)d_in[0];
    const float* f       = (const float*)d_in[1];
    const float* wq      = (const float*)d_in[2];
    const float* bq      = (const float*)d_in[3];
    const float* wk      = (const float*)d_in[4];
    const float* bk      = (const float*)d_in[5];
    const float* wv      = (const float*)d_in[6];
    const float* bv      = (const float*)d_in[7];
    const float* wo      = (const float*)d_in[8];
    const float* bo      = (const float*)d_in[9];
    const float* rw_w    = (const float*)d_in[10];
    const float* rw_b    = (const float*)d_in[11];
    const float* convk_w = (const float*)d_in[12];
    const float* convk_b = (const float*)d_in[13];
    const float* convv_w = (const float*)d_in[14];
    const float* convv_b = (const float*)d_in[15];
    const float* qn_g    = (const float*)d_in[16];
    const float* qn_b    = (const float*)d_in[17];
    const float* kn_g    = (const float*)d_in[18];
    const float* kn_b    = (const float*)d_in[19];
    const float* vn_g    = (const float*)d_in[20];
    const float* vn_b    = (const float*)d_in[21];
    float* out = (float*)d_out;

    float *qk, *kg, *vg, *fbqk, *fbv;
    __half *xf, *qkn, *xn, *kgn, *vgn, *Q, *Kl, *Vl, *Kg, *Vg, *O;
    __half *fwqk, *fwv, *fwo, *frw;
    cudaGetSymbolAddress((void**)&qk,   g_qk);
    cudaGetSymbolAddress((void**)&kg,   g_kg);
    cudaGetSymbolAddress((void**)&vg,   g_vg);
    cudaGetSymbolAddress((void**)&xf,   g_xf);
    cudaGetSymbolAddress((void**)&qkn,  g_qkn);
    cudaGetSymbolAddress((void**)&xn,   g_xn);
    cudaGetSymbolAddress((void**)&kgn,  g_kgn);
    cudaGetSymbolAddress((void**)&vgn,  g_vgn);
    cudaGetSymbolAddress((void**)&Q,    g_Q);
    cudaGetSymbolAddress((void**)&Kl,   g_Kl);
    cudaGetSymbolAddress((void**)&Vl,   g_Vl);
    cudaGetSymbolAddress((void**)&Kg,   g_Kg);
    cudaGetSymbolAddress((void**)&Vg,   g_Vg);
    cudaGetSymbolAddress((void**)&O,    g_O);
    cudaGetSymbolAddress((void**)&fwqk, g_fwqk);
    cudaGetSymbolAddress((void**)&fbqk, g_fbqk);
    cudaGetSymbolAddress((void**)&fwv,  g_fwv);
    cudaGetSymbolAddress((void**)&fwo,  g_fwo);
    cudaGetSymbolAddress((void**)&frw,  g_frw);
    cudaGetSymbolAddress((void**)&fbv,  g_fbv);

    cudaFuncSetAttribute(attn_kernel, cudaFuncAttributeMaxDynamicSharedMemorySize,
                         ATTN_SMEM_BYTES);
    cudaFuncSetAttribute(mma_gemm<0,0>, cudaFuncAttributeMaxDynamicSharedMemorySize, SMEM_GEMM);
    cudaFuncSetAttribute(mma_gemm<1,1>, cudaFuncAttributeMaxDynamicSharedMemorySize, SMEM_GEMM);
    cudaFuncSetAttribute(mma_gemm<1,0>, cudaFuncAttributeMaxDynamicSharedMemorySize, SMEM_GEMM);
    cudaFuncSetAttribute(mma_gemm<2,0>, cudaFuncAttributeMaxDynamicSharedMemorySize, SMEM_GEMM);
    cudaFuncSetAttribute(mma_gemm<3,0>, cudaFuncAttributeMaxDynamicSharedMemorySize, SMEM_GEMM);

    cudaStream_t s1;
    cudaStreamCreateWithFlags(&s1, cudaStreamNonBlocking);
    cudaEvent_t evFork, evJoinV, evRW, evJoinKG;
    cudaEventCreateWithFlags(&evFork,   cudaEventDisableTiming);
    cudaEventCreateWithFlags(&evJoinV,  cudaEventDisableTiming);
    cudaEventCreateWithFlags(&evRW,     cudaEventDisableTiming);
    cudaEventCreateWithFlags(&evJoinKG, cudaEventDisableTiming);

    cudaEventRecord(evFork, 0);
    cudaStreamWaitEvent(s1, evFork, 0);

    // ---- s1: x-side chain ----
    fold_w_kernel<<<64, 256, 0, s1>>>(wv, vn_g, vn_b, bv, fwv, fbv, DD, DD);
    fold_w_kernel<<<64, 256, 0, s1>>>(wo, nullptr, nullptr, nullptr, fwo, nullptr, DD, DD);
    ln_norm_kernel<512><<<MTOK / 8, 256, 0, s1>>>(x, xn);
    dwconv_kernel<512><<<dim3(4, BT * GG), 128, 0, s1>>>(x, convv_w, convv_b, vg);
    ln_norm_kernel<512><<<(BT * NGLOB) / 8, 256, 0, s1>>>(vg, vgn);
    mma_gemm<1,0><<<dim3(4, 256), 256, SMEM_GEMM, s1>>>(
        xn, fwv, fbv, nullptr, nullptr, nullptr, Vl, nullptr, MTOK, DD, DD, DD);
    mma_gemm<2,0><<<dim3(4, 4), 256, SMEM_GEMM, s1>>>(
        vgn, fwv, fbv, nullptr, nullptr, nullptr, Vg, nullptr, BT * NGLOB, DD, DD, DD);
    cudaEventRecord(evJoinV, s1);

    // ---- default stream: qk chain ----
    fold_w_kernel<<<80, 256>>>(rw_w, nullptr, nullptr, nullptr, frw, nullptr, INCC, INCC);
    fold_w_kernel<<<64, 256>>>(wq, qn_g, qn_b, bq, fwqk, fbqk, DD, INCC);
    fold_w_kernel<<<64, 256>>>(wk, kn_g, kn_b, bk, fwqk + (size_t)DD * INCC, fbqk + DD, DD, INCC);
    prep_xf_kernel<<<MTOK * INCC / 2048, 256>>>(x, f, xf);

    mma_gemm<0,0><<<dim3(5, 256), 256, SMEM_GEMM>>>(
        xf, frw, rw_b, x, f, qk, nullptr, nullptr, MTOK, INCC, INCC, INCC);
    cudaEventRecord(evRW, 0);

    // ---- s1 (after its V work): kg chain, overlaps QK projection ----
    cudaStreamWaitEvent(s1, evRW, 0);
    dwconv_kernel<640><<<dim3(5, BT * GG), 128, 0, s1>>>(qk, convk_w, convk_b, kg);
    ln_norm_kernel<640><<<(BT * NGLOB) / 8, 256, 0, s1>>>(kg, kgn);
    mma_gemm<2,0><<<dim3(4, 4), 256, SMEM_GEMM, s1>>>(
        kgn, fwqk + (size_t)DD * INCC, fbqk + DD, nullptr, nullptr, nullptr, Kg, nullptr,
        BT * NGLOB, DD, INCC, DD);
    cudaEventRecord(evJoinKG, s1);

    // ---- default stream continues: LN(qk) + big QK projection ----
    ln_norm_kernel<640><<<MTOK / 8, 256>>>(qk, qkn);
    mma_gemm<1,1><<<dim3(8, 256), 256, SMEM_GEMM>>>(
        qkn, fwqk, fbqk, nullptr, nullptr, nullptr, Q, Kl, MTOK, 2 * DD, INCC, DD);

    // ---- join & finish ----
    cudaStreamWaitEvent(0, evJoinV, 0);
    cudaStreamWaitEvent(0, evJoinKG, 0);
    attn_kernel<<<BT * GG * NHEAD, 256, ATTN_SMEM_BYTES>>>(Q, Kl, Kg, Vl, Vg, O);
    mma_gemm<3,0><<<dim3(4, 256), 256, SMEM_GEMM>>>(
        O, fwo, bo, nullptr, nullptr, out, nullptr, nullptr, MTOK, DD, DD, DD);

    cudaEventDestroy(evFork);
    cudaEventDestroy(evJoinV);
    cudaEventDestroy(evRW);
    cudaEventDestroy(evJoinKG);
    cudaStreamDestroy(s1);
}

// round 11
// speedup vs baseline: 2.6485x; 1.1442x over previous
#include <cuda_runtime.h>
#include <cuda_fp16.h>
#include <cstdint>

// ---------------- problem constants ----------------
#define BT     8
#define NPIX   4096
#define DD     512
#define CFF    128
#define INCC   640
#define GG     64
#define NWIN   64
#define NGLOB  64
#define NHEAD  8
#define DHH    64
#define MTOK   32768

// ---------------- scratch ----------------
__device__ float  g_qk [MTOK*INCC];
__device__ float  g_kg [BT*NGLOB*INCC];
__device__ float  g_vg [BT*NGLOB*DD];
__device__ __half g_xf [MTOK*INCC];
__device__ __half g_qkn[MTOK*INCC];
__device__ __half g_xn [MTOK*DD];
__device__ __half g_kgn[BT*NGLOB*INCC];
__device__ __half g_vgn[BT*NGLOB*DD];
__device__ __half g_Q  [MTOK*DD];
__device__ __half g_Kl [MTOK*DD];
__device__ __half g_Vl [MTOK*DD];
__device__ __half g_Kg [BT*NGLOB*DD];
__device__ __half g_Vg [BT*NGLOB*DD];
__device__ __half g_O  [MTOK*DD];
__device__ __half g_fwqk[2*DD*INCC];
__device__ float  g_fbqk[2*DD];
__device__ __half g_fwv[DD*DD];
__device__ __half g_fwo[DD*DD];
__device__ __half g_frw[INCC*INCC];
__device__ float  g_fbv[DD];
__device__ float  g_cvT[64*DD];     // transposed convv weights [k][c]
__device__ float  g_ckT[64*INCC];   // transposed convk weights [k][c]

// ---------------- helpers ----------------
__device__ __forceinline__ int win_map(int r) {
    int b = r >> 12;
    int p = r & 4095;
    int h = p >> 6, w = p & 63;
    int g = ((h >> 3) << 3) | (w >> 3);
    int n = ((h & 7) << 3) | (w & 7);
    return (((b << 6) | g) << 6) | n;
}

__device__ __forceinline__ uint32_t h2b(float a, float b) {
    __half2 h = __floats2half2_rn(a, b);
    return *(uint32_t*)&h;
}

__device__ __forceinline__ void mma_f16(float* d, const uint32_t* a, const uint32_t* b) {
    asm volatile(
        "mma.sync.aligned.m16n8k16.row.col.f32.f16.f16.f32 "
        "{%0,%1,%2,%3}, {%4,%5,%6,%7}, {%8,%9}, {%0,%1,%2,%3};"
        : "+f"(d[0]), "+f"(d[1]), "+f"(d[2]), "+f"(d[3])
        : "r"(a[0]), "r"(a[1]), "r"(a[2]), "r"(a[3]), "r"(b[0]), "r"(b[1]));
}

__device__ __forceinline__ void ldsm_x4(uint32_t* r, uint32_t addr) {
    asm volatile("ldmatrix.sync.aligned.m8n8.x4.shared.b16 {%0,%1,%2,%3}, [%4];"
                 : "=r"(r[0]), "=r"(r[1]), "=r"(r[2]), "=r"(r[3]) : "r"(addr));
}

#define CP_ASYNC16(dst, src) \
    asm volatile("cp.async.ca.shared.global [%0], [%1], 16;" :: "r"(dst), "l"(src))
#define CP_COMMIT() asm volatile("cp.async.commit_group;" ::: "memory")
#define CP_WAIT0()  asm volatile("cp.async.wait_group 0;" ::: "memory")

// ---------------- weight fold ----------------
__global__ __launch_bounds__(256)
void fold_w_kernel(const float* __restrict__ W, const float* __restrict__ gamma,
                   const float* __restrict__ beta, const float* __restrict__ b,
                   __half* __restrict__ Wo, float* __restrict__ bo, int N, int K) {
    int n = blockIdx.x * 8 + (threadIdx.x >> 5);
    if (n >= N) return;
    int lane = threadIdx.x & 31;
    const float* wr = W + (size_t)n * K;
    __half* wor = Wo + (size_t)n * K;
    float acc = 0.f;
    for (int k = lane; k < K; k += 32) {
        float w = wr[k];
        if (beta) acc += beta[k] * w;
        wor[k] = __float2half(gamma ? w * gamma[k] : w);
    }
    if (beta) {
        #pragma unroll
        for (int o = 16; o; o >>= 1) acc += __shfl_xor_sync(0xffffffffu, acc, o);
        if (lane == 0) bo[n] = b[n] + acc;
    }
}

// ---------------- conv weight transpose: Wt[k][c] = W[c*64+k] ----------------
__global__ __launch_bounds__(256)
void convT_kernel(const float* __restrict__ W, float* __restrict__ Wt, int C) {
    int idx = blockIdx.x * 256 + threadIdx.x;
    if (idx >= C * 64) return;
    int c = idx >> 6, k = idx & 63;
    Wt[k * C + c] = W[idx];
}

// ---------------- raw concat(x,f) -> half ----------------
__global__ __launch_bounds__(256)
void prep_xf_kernel(const float* __restrict__ x, const float* __restrict__ f,
                    __half* __restrict__ xf) {
    size_t idx = ((size_t)blockIdx.x * 256 + threadIdx.x) * 8;
    int r = (int)(idx / INCC);
    int c = (int)(idx % INCC);
    const float* src = (c < 512) ? (x + (size_t)r * 512 + c)
                                 : (f + (size_t)r * 128 + (c - 512));
    float4 a = *(const float4*)src;
    float4 b = *(const float4*)(src + 4);
    uint4 o;
    o.x = h2b(a.x, a.y); o.y = h2b(a.z, a.w);
    o.z = h2b(b.x, b.y); o.w = h2b(b.z, b.w);
    *(uint4*)(xf + idx) = o;
}

// ---------------- fused LN: stats + normalize + half convert ----------------
template<int K>
__global__ __launch_bounds__(256)
void ln_norm_kernel(const float* __restrict__ X, __half* __restrict__ Xn) {
    const int NSEG = K / 128;
    int row = blockIdx.x * 8 + (threadIdx.x >> 5);
    int lane = threadIdx.x & 31;
    const float* xr = X + (size_t)row * K;
    float4 v[NSEG];
    float s = 0.f, ss = 0.f;
    #pragma unroll
    for (int i = 0; i < NSEG; i++) {
        v[i] = *(const float4*)(xr + lane * 4 + i * 128);
        s  += v[i].x + v[i].y + v[i].z + v[i].w;
        ss += v[i].x * v[i].x + v[i].y * v[i].y + v[i].z * v[i].z + v[i].w * v[i].w;
    }
    #pragma unroll
    for (int o = 16; o; o >>= 1) {
        s  += __shfl_xor_sync(0xffffffffu, s, o);
        ss += __shfl_xor_sync(0xffffffffu, ss, o);
    }
    float mean = s / K;
    float rstd = rsqrtf(ss / K - mean * mean + 1e-5f);
    __half* xo = Xn + (size_t)row * K;
    #pragma unroll
    for (int i = 0; i < NSEG; i++) {
        uint2 o;
        o.x = h2b((v[i].x - mean) * rstd, (v[i].y - mean) * rstd);
        o.y = h2b((v[i].z - mean) * rstd, (v[i].w - mean) * rstd);
        *(uint2*)(xo + lane * 4 + i * 128) = o;
    }
}

// ---------------- depthwise conv, transposed (coalesced) weights ----------------
// grid (C/128, BT*GG), 128 threads; weights from Wt[k][c] (coalesced in c).
template<int C>
__global__ __launch_bounds__(128)
void dwconv_kernel(const float* __restrict__ X, const float* __restrict__ Wt,
                   const float* __restrict__ bc, float* __restrict__ out) {
    int bw = blockIdx.y;
    int c = blockIdx.x * 128 + threadIdx.x;
    int b = bw >> 6;
    int g = bw & 63;
    int gh = g >> 3, gw = g & 7;
    const float* xb = X + ((size_t)b * NPIX + (size_t)(gh * 8) * 64 + gw * 8) * C + c;
    float s = bc[c];
    #pragma unroll
    for (int i = 0; i < 8; i++)
        #pragma unroll
        for (int j = 0; j < 8; j++)
            s += xb[(size_t)(i * 64 + j) * C] * Wt[(i * 8 + j) * C + c];
    out[(size_t)bw * C + c] = s;
}

// ---------------- fp16 mma GEMM, pure cp.async mainloop ----------------
#define GS 72
template<int MODE, int SPLIT>
__global__ __launch_bounds__(256)
void mma_gemm(const __half* __restrict__ A, const __half* __restrict__ W,
              const float* __restrict__ bias,
              const float* __restrict__ Xraw, const float* __restrict__ Fraw,
              float* __restrict__ Cf, __half* __restrict__ Ch, __half* __restrict__ Ch2,
              int M, int N, int K, int ldc) {
    extern __shared__ __half sh[];
    __half* As = sh;
    __half* Bs = sh + 2 * 128 * GS;

    const int tid = threadIdx.x;
    const int m0 = blockIdx.y * 128;
    const int n0 = blockIdx.x * 128;
    const int q = tid & 7;
    const int lrow = tid >> 3;
    const int lane = tid & 31, grp = lane >> 2, tig = lane & 3;
    const int w = tid >> 5, mblk = (w & 3) * 32, nblk = (w >> 2) * 64;
    const int NC = K >> 6;

    const uint32_t as_s = (uint32_t)__cvta_generic_to_shared(As);
    const uint32_t bs_s = (uint32_t)__cvta_generic_to_shared(Bs);

    const uint32_t aoff0 = (uint32_t)(((mblk + (lane & 15)) * GS + (lane >> 4) * 8) * 2);
    const uint32_t aoff1 = aoff0 + (uint32_t)(16 * GS * 2);
    const uint32_t boff  = (uint32_t)(((nblk + (lane & 7) + ((lane & 16) ? 8 : 0)) * GS
                                       + ((lane & 8) ? 8 : 0)) * 2);

    int arow[4];
    #pragma unroll
    for (int i = 0; i < 4; i++) {
        int r = m0 + lrow + i * 32;
        arow[i] = (MODE == 3) ? win_map(r) : r;
    }

    float acc[2][8][4];
    #pragma unroll
    for (int mt = 0; mt < 2; mt++)
        #pragma unroll
        for (int nt = 0; nt < 8; nt++)
            #pragma unroll
            for (int e = 0; e < 4; e++) acc[mt][nt][e] = 0.f;

    auto issue = [&](int ch, int buf) {
        int gk = (ch << 6) + q * 8;
        #pragma unroll
        for (int i = 0; i < 4; i++) {
            int r = lrow + i * 32;
            CP_ASYNC16(as_s + (uint32_t)(((buf * 128 + r) * GS + q * 8) * 2),
                       A + (size_t)arow[i] * K + gk);
            CP_ASYNC16(bs_s + (uint32_t)(((buf * 128 + r) * GS + q * 8) * 2),
                       W + (size_t)(n0 + r) * K + gk);
        }
        CP_COMMIT();
    };
    auto compute = [&](int buf) {
        uint32_t abase = as_s + (uint32_t)(buf * 128 * GS * 2);
        uint32_t bbase = bs_s + (uint32_t)(buf * 128 * GS * 2);
        #pragma unroll
        for (int k16 = 0; k16 < 4; k16++) {
            uint32_t kb = (uint32_t)(k16 * 32);
            uint32_t af0[4], af1[4];
            ldsm_x4(af0, abase + aoff0 + kb);
            ldsm_x4(af1, abase + aoff1 + kb);
            #pragma unroll
            for (int p = 0; p < 4; p++) {
                uint32_t bf[4];
                ldsm_x4(bf, bbase + boff + (uint32_t)(p * 16 * GS * 2) + kb);
                mma_f16(acc[0][2 * p],     af0, bf);
                mma_f16(acc[1][2 * p],     af1, bf);
                mma_f16(acc[0][2 * p + 1], af0, bf + 2);
                mma_f16(acc[1][2 * p + 1], af1, bf + 2);
            }
        }
    };

    issue(0, 0);
    CP_WAIT0();
    __syncthreads();

    for (int ch = 0; ch < NC; ch++) {
        int buf = ch & 1;
        int nx = ch + 1;
        if (nx < NC) issue(nx, buf ^ 1);
        compute(buf);
        if (nx < NC) CP_WAIT0();
        __syncthreads();
    }

    #pragma unroll
    for (int mt = 0; mt < 2; mt++) {
        #pragma unroll
        for (int hr = 0; hr < 2; hr++) {
            int r = m0 + mblk + mt * 16 + grp + hr * 8;
            size_t orow = (MODE == 1) ? (size_t)win_map(r) : (size_t)r;
            #pragma unroll
            for (int nt = 0; nt < 8; nt++) {
                int c = n0 + nblk + nt * 8 + 2 * tig;
                float y0 = acc[mt][nt][hr * 2 + 0] + bias[c];
                float y1 = acc[mt][nt][hr * 2 + 1] + bias[c + 1];
                if (MODE == 0) {
                    float a0 = (c < 512) ? Xraw[(size_t)r * 512 + c]
                                         : Fraw[(size_t)r * 128 + (c - 512)];
                    float a1 = (c + 1 < 512) ? Xraw[(size_t)r * 512 + c + 1]
                                             : Fraw[(size_t)r * 128 + (c + 1 - 512)];
                    y0 = a0 / (1.f + __expf(-y0));
                    y1 = a1 / (1.f + __expf(-y1));
                    *(float2*)(Cf + orow * (size_t)ldc + c) = make_float2(y0, y1);
                } else if (MODE == 3) {
                    *(float2*)(Cf + orow * (size_t)ldc + c) = make_float2(y0, y1);
                } else {
                    __half* base = Ch;
                    int cc = c;
                    if (SPLIT) { base = (c < 512) ? Ch : Ch2; cc = c & 511; }
                    *(__half2*)(base + orow * (size_t)ldc + cc) = __floats2half2_rn(y0, y1);
                }
            }
        }
    }
}

// ---------------- attention ----------------
#define AQ_STR 72
#define AV_STR 136
#define ATTN_SMEM_BYTES (64*AQ_STR*2 + 128*AQ_STR*2 + 64*AV_STR*2 + 64*AV_STR*2 + 64*132*4)

__global__ __launch_bounds__(256)
void attn_kernel(const __half* __restrict__ Q, const __half* __restrict__ Kl,
                 const __half* __restrict__ Kg, const __half* __restrict__ Vl,
                 const __half* __restrict__ Vg, __half* __restrict__ O) {
    extern __shared__ char smraw[];
    __half* Qs = (__half*)smraw;
    __half* Ks = Qs + 64 * AQ_STR;
    __half* Vt = Ks + 128 * AQ_STR;
    __half* Ps = Vt + 64 * AV_STR;
    float*  Sf = (float*)(Ps + 64 * AV_STR);

    int bid = blockIdx.x;
    int b = bid >> 9;
    int rem = bid & 511;
    int g = rem >> 3;
    int h = rem & 7;

    size_t wbase = ((size_t)(b * GG + g) * NWIN) * DD + (size_t)h * DHH;
    size_t gbase = ((size_t)b * NGLOB) * DD + (size_t)h * DHH;
    const __half* Qp  = Q  + wbase;
    const __half* Klp = Kl + wbase;
    const __half* Vlp = Vl + wbase;
    const __half* Kgp = Kg + gbase;
    const __half* Vgp = Vg + gbase;
    __half* Op = O + wbase;

    int tid = threadIdx.x;
    const uint32_t qs_s = (uint32_t)__cvta_generic_to_shared(Qs);
    const uint32_t ks_s = (uint32_t)__cvta_generic_to_shared(Ks);
    const uint32_t vt_s = (uint32_t)__cvta_generic_to_shared(Vt);
    const uint32_t ps_s = (uint32_t)__cvta_generic_to_shared(Ps);

    for (int e = tid; e < 64 * 8; e += 256) {
        int m = e >> 3, sg = e & 7;
        CP_ASYNC16(qs_s + (uint32_t)((m * AQ_STR + sg * 8) * 2), Qp + (size_t)m * DD + sg * 8);
    }
    for (int e = tid; e < 128 * 8; e += 256) {
        int kk = e >> 3, sg = e & 7;
        const __half* ksrc = (kk < 64) ? (Klp + (size_t)kk * DD)
                                       : (Kgp + (size_t)(kk - 64) * DD);
        CP_ASYNC16(ks_s + (uint32_t)((kk * AQ_STR + sg * 8) * 2), ksrc + sg * 8);
    }
    CP_COMMIT();
    for (int e = tid; e < 128 * 8; e += 256) {
        int kk = e >> 3, sg = e & 7;
        const __half* vsrc = (kk < 64) ? (Vlp + (size_t)kk * DD)
                                       : (Vgp + (size_t)(kk - 64) * DD);
        uint4 pv = *(const uint4*)(vsrc + sg * 8);
        const __half* ph = (const __half*)&pv;
        #pragma unroll
        for (int j = 0; j < 8; j++)
            Vt[(sg * 8 + j) * AV_STR + kk] = ph[j];
    }
    CP_WAIT0();
    __syncthreads();

    int w = tid >> 5, lane = tid & 31, grp = lane >> 2, tig = lane & 3;
    int mrow = (w & 3) * 16;

    {
        int nb0 = (w >> 2) * 64;
        const uint32_t aoff = qs_s +
            (uint32_t)(((mrow + (lane & 15)) * AQ_STR + (lane >> 4) * 8) * 2);
        const uint32_t boff = ks_s +
            (uint32_t)(((nb0 + (lane & 7) + ((lane & 16) ? 8 : 0)) * AQ_STR
                        + ((lane & 8) ? 8 : 0)) * 2);
        float acc[8][4];
        #pragma unroll
        for (int nt = 0; nt < 8; nt++)
            #pragma unroll
            for (int e = 0; e < 4; e++) acc[nt][e] = 0.f;
        #pragma unroll
        for (int k16 = 0; k16 < 4; k16++) {
            uint32_t kb = (uint32_t)(k16 * 32);
            uint32_t af[4];
            ldsm_x4(af, aoff + kb);
            #pragma unroll
            for (int p = 0; p < 4; p++) {
                uint32_t bf[4];
                ldsm_x4(bf, boff + (uint32_t)(p * 16 * AQ_STR * 2) + kb);
                mma_f16(acc[2 * p],     af, bf);
                mma_f16(acc[2 * p + 1], af, bf + 2);
            }
        }
        #pragma unroll
        for (int nt = 0; nt < 8; nt++) {
            int c = nb0 + nt * 8 + 2 * tig;
            Sf[(mrow + grp)     * 132 + c]     = acc[nt][0] * 0.125f;
            Sf[(mrow + grp)     * 132 + c + 1] = acc[nt][1] * 0.125f;
            Sf[(mrow + grp + 8) * 132 + c]     = acc[nt][2] * 0.125f;
            Sf[(mrow + grp + 8) * 132 + c + 1] = acc[nt][3] * 0.125f;
        }
    }
    __syncthreads();

    for (int m = w; m < 64; m += 8) {
        float* sr = &Sf[m * 132];
        float v0 = sr[lane], v1 = sr[lane + 32], v2 = sr[lane + 64], v3 = sr[lane + 96];
        float mx = fmaxf(fmaxf(v0, v1), fmaxf(v2, v3));
        #pragma unroll
        for (int o = 16; o; o >>= 1) mx = fmaxf(mx, __shfl_xor_sync(0xffffffffu, mx, o));
        float e0 = __expf(v0 - mx), e1 = __expf(v1 - mx);
        float e2 = __expf(v2 - mx), e3 = __expf(v3 - mx);
        float s = e0 + e1 + e2 + e3;
        #pragma unroll
        for (int o = 16; o; o >>= 1) s += __shfl_xor_sync(0xffffffffu, s, o);
        float inv = 1.f / s;
        __half* pr = &Ps[m * AV_STR];
        pr[lane]      = __float2half(e0 * inv);
        pr[lane + 32] = __float2half(e1 * inv);
        pr[lane + 64] = __float2half(e2 * inv);
        pr[lane + 96] = __float2half(e3 * inv);
    }
    __syncthreads();

    {
        int db0 = (w >> 2) * 32;
        const uint32_t aoff = ps_s +
            (uint32_t)(((mrow + (lane & 15)) * AV_STR + (lane >> 4) * 8) * 2);
        const uint32_t boff = vt_s +
            (uint32_t)(((db0 + (lane & 7) + ((lane & 16) ? 8 : 0)) * AV_STR
                        + ((lane & 8) ? 8 : 0)) * 2);
        float acc[4][4];
        #pragma unroll
        for (int nt = 0; nt < 4; nt++)
            #pragma unroll
            for (int e = 0; e < 4; e++) acc[nt][e] = 0.f;
        #pragma unroll
        for (int k16 = 0; k16 < 8; k16++) {
            uint32_t kb = (uint32_t)(k16 * 32);
            uint32_t af[4];
            ldsm_x4(af, aoff + kb);
            #pragma unroll
            for (int p = 0; p < 2; p++) {
                uint32_t bf[4];
                ldsm_x4(bf, boff + (uint32_t)(p * 16 * AV_STR * 2) + kb);
                mma_f16(acc[2 * p],     af, bf);
                mma_f16(acc[2 * p + 1], af, bf + 2);
            }
        }
        #pragma unroll
        for (int nt = 0; nt < 4; nt++) {
            int c = db0 + nt * 8 + 2 * tig;
            *(__half2*)(Op + (size_t)(mrow + grp) * DD + c) =
                __floats2half2_rn(acc[nt][0], acc[nt][1]);
            *(__half2*)(Op + (size_t)(mrow + grp + 8) * DD + c) =
                __floats2half2_rn(acc[nt][2], acc[nt][3]);
        }
    }
}

// ---------------- launch ----------------
#define SMEM_GEMM (4 * 128 * GS * 2)

extern "C" void kernel_launch(void* const* d_in, const int* in_sizes, int n_in,
                              void* d_out, int out_size) {
    const float* x       = (const float*)d_in[0];
    const float* f       = (const float*)d_in[1];
    const float* wq      = (const float*)d_in[2];
    const float* bq      = (const float*)d_in[3];
    const float* wk      = (const float*)d_in[4];
    const float* bk      = (const float*)d_in[5];
    const float* wv      = (const float*)d_in[6];
    const float* bv      = (const float*)d_in[7];
    const float* wo      = (const float*)d_in[8];
    const float* bo      = (const float*)d_in[9];
    const float* rw_w    = (const float*)d_in[10];
    const float* rw_b    = (const float*)d_in[11];
    const float* convk_w = (const float*)d_in[12];
    const float* convk_b = (const float*)d_in[13];
    const float* convv_w = (const float*)d_in[14];
    const float* convv_b = (const float*)d_in[15];
    const float* qn_g    = (const float*)d_in[16];
    const float* qn_b    = (const float*)d_in[17];
    const float* kn_g    = (const float*)d_in[18];
    const float* kn_b    = (const float*)d_in[19];
    const float* vn_g    = (const float*)d_in[20];
    const float* vn_b    = (const float*)d_in[21];
    float* out = (float*)d_out;

    float *qk, *kg, *vg, *fbqk, *fbv, *cvT, *ckT;
    __half *xf, *qkn, *xn, *kgn, *vgn, *Q, *Kl, *Vl, *Kg, *Vg, *O;
    __half *fwqk, *fwv, *fwo, *frw;
    cudaGetSymbolAddress((void**)&qk,   g_qk);
    cudaGetSymbolAddress((void**)&kg,   g_kg);
    cudaGetSymbolAddress((void**)&vg,   g_vg);
    cudaGetSymbolAddress((void**)&xf,   g_xf);
    cudaGetSymbolAddress((void**)&qkn,  g_qkn);
    cudaGetSymbolAddress((void**)&xn,   g_xn);
    cudaGetSymbolAddress((void**)&kgn,  g_kgn);
    cudaGetSymbolAddress((void**)&vgn,  g_vgn);
    cudaGetSymbolAddress((void**)&Q,    g_Q);
    cudaGetSymbolAddress((void**)&Kl,   g_Kl);
    cudaGetSymbolAddress((void**)&Vl,   g_Vl);
    cudaGetSymbolAddress((void**)&Kg,   g_Kg);
    cudaGetSymbolAddress((void**)&Vg,   g_Vg);
    cudaGetSymbolAddress((void**)&O,    g_O);
    cudaGetSymbolAddress((void**)&fwqk, g_fwqk);
    cudaGetSymbolAddress((void**)&fbqk, g_fbqk);
    cudaGetSymbolAddress((void**)&fwv,  g_fwv);
    cudaGetSymbolAddress((void**)&fwo,  g_fwo);
    cudaGetSymbolAddress((void**)&frw,  g_frw);
    cudaGetSymbolAddress((void**)&fbv,  g_fbv);
    cudaGetSymbolAddress((void**)&cvT,  g_cvT);
    cudaGetSymbolAddress((void**)&ckT,  g_ckT);

    cudaFuncSetAttribute(attn_kernel, cudaFuncAttributeMaxDynamicSharedMemorySize,
                         ATTN_SMEM_BYTES);
    cudaFuncSetAttribute(mma_gemm<0,0>, cudaFuncAttributeMaxDynamicSharedMemorySize, SMEM_GEMM);
    cudaFuncSetAttribute(mma_gemm<1,1>, cudaFuncAttributeMaxDynamicSharedMemorySize, SMEM_GEMM);
    cudaFuncSetAttribute(mma_gemm<1,0>, cudaFuncAttributeMaxDynamicSharedMemorySize, SMEM_GEMM);
    cudaFuncSetAttribute(mma_gemm<2,0>, cudaFuncAttributeMaxDynamicSharedMemorySize, SMEM_GEMM);
    cudaFuncSetAttribute(mma_gemm<3,0>, cudaFuncAttributeMaxDynamicSharedMemorySize, SMEM_GEMM);

    cudaStream_t s1;
    cudaStreamCreateWithFlags(&s1, cudaStreamNonBlocking);
    cudaEvent_t evFork, evJoinV, evRW, evJoinKG;
    cudaEventCreateWithFlags(&evFork,   cudaEventDisableTiming);
    cudaEventCreateWithFlags(&evJoinV,  cudaEventDisableTiming);
    cudaEventCreateWithFlags(&evRW,     cudaEventDisableTiming);
    cudaEventCreateWithFlags(&evJoinKG, cudaEventDisableTiming);

    cudaEventRecord(evFork, 0);
    cudaStreamWaitEvent(s1, evFork, 0);

    // ---- s1: x-side chain + folds not needed before reweight ----
    fold_w_kernel<<<64, 256, 0, s1>>>(wv, vn_g, vn_b, bv, fwv, fbv, DD, DD);
    fold_w_kernel<<<64, 256, 0, s1>>>(wo, nullptr, nullptr, nullptr, fwo, nullptr, DD, DD);
    fold_w_kernel<<<64, 256, 0, s1>>>(wq, qn_g, qn_b, bq, fwqk, fbqk, DD, INCC);
    fold_w_kernel<<<64, 256, 0, s1>>>(wk, kn_g, kn_b, bk, fwqk + (size_t)DD * INCC, fbqk + DD, DD, INCC);
    convT_kernel<<<(DD * 64) / 256, 256, 0, s1>>>(convv_w, cvT, DD);
    convT_kernel<<<(INCC * 64) / 256, 256, 0, s1>>>(convk_w, ckT, INCC);
    ln_norm_kernel<512><<<MTOK / 8, 256, 0, s1>>>(x, xn);
    dwconv_kernel<512><<<dim3(4, BT * GG), 128, 0, s1>>>(x, cvT, convv_b, vg);
    ln_norm_kernel<512><<<(BT * NGLOB) / 8, 256, 0, s1>>>(vg, vgn);
    mma_gemm<1,0><<<dim3(4, 256), 256, SMEM_GEMM, s1>>>(
        xn, fwv, fbv, nullptr, nullptr, nullptr, Vl, nullptr, MTOK, DD, DD, DD);
    mma_gemm<2,0><<<dim3(4, 4), 256, SMEM_GEMM, s1>>>(
        vgn, fwv, fbv, nullptr, nullptr, nullptr, Vg, nullptr, BT * NGLOB, DD, DD, DD);
    cudaEventRecord(evJoinV, s1);

    // ---- default stream: qk critical path ----
    fold_w_kernel<<<80, 256>>>(rw_w, nullptr, nullptr, nullptr, frw, nullptr, INCC, INCC);
    prep_xf_kernel<<<MTOK * INCC / 2048, 256>>>(x, f, xf);

    mma_gemm<0,0><<<dim3(5, 256), 256, SMEM_GEMM>>>(
        xf, frw, rw_b, x, f, qk, nullptr, nullptr, MTOK, INCC, INCC, INCC);
    cudaEventRecord(evRW, 0);

    // ---- s1 (after its V work): kg chain, overlaps QK projection ----
    cudaStreamWaitEvent(s1, evRW, 0);
    dwconv_kernel<640><<<dim3(5, BT * GG), 128, 0, s1>>>(qk, ckT, convk_b, kg);
    ln_norm_kernel<640><<<(BT * NGLOB) / 8, 256, 0, s1>>>(kg, kgn);
    mma_gemm<2,0><<<dim3(4, 4), 256, SMEM_GEMM, s1>>>(
        kgn, fwqk + (size_t)DD * INCC, fbqk + DD, nullptr, nullptr, nullptr, Kg, nullptr,
        BT * NGLOB, DD, INCC, DD);
    cudaEventRecord(evJoinKG, s1);

    // ---- default stream: LN(qk) + big QK projection ----
    ln_norm_kernel<640><<<MTOK / 8, 256>>>(qk, qkn);
    mma_gemm<1,1><<<dim3(8, 256), 256, SMEM_GEMM>>>(
        qkn, fwqk, fbqk, nullptr, nullptr, nullptr, Q, Kl, MTOK, 2 * DD, INCC, DD);

    // ---- join & finish ----
    cudaStreamWaitEvent(0, evJoinV, 0);
    cudaStreamWaitEvent(0, evJoinKG, 0);
    attn_kernel<<<BT * GG * NHEAD, 256, ATTN_SMEM_BYTES>>>(Q, Kl, Kg, Vl, Vg, O);
    mma_gemm<3,0><<<dim3(4, 256), 256, SMEM_GEMM>>>(
        O, fwo, bo, nullptr, nullptr, out, nullptr, nullptr, MTOK, DD, DD, DD);

    cudaEventDestroy(evFork);
    cudaEventDestroy(evJoinV);
    cudaEventDestroy(evRW);
    cudaEventDestroy(evJoinKG);
    cudaStreamDestroy(s1);
}

// round 12
// speedup vs baseline: 2.9641x; 1.1192x over previous
#include <cuda_runtime.h>
#include <cuda_fp16.h>
#include <cstdint>

// ---------------- problem constants ----------------
#define BT     8
#define NPIX   4096
#define DD     512
#define CFF    128
#define INCC   640
#define GG     64
#define NWIN   64
#define NGLOB  64
#define NHEAD  8
#define DHH    64
#define MTOK   32768

// ---------------- scratch ----------------
__device__ float  g_qk [MTOK*INCC];
__device__ float  g_kg [BT*NGLOB*INCC];
__device__ float  g_vg [BT*NGLOB*DD];
__device__ __half g_xf [MTOK*INCC];
__device__ __half g_qkn[MTOK*INCC];
__device__ __half g_xn [MTOK*DD];
__device__ __half g_kgn[BT*NGLOB*INCC];
__device__ __half g_vgn[BT*NGLOB*DD];
__device__ __half g_Q  [MTOK*DD];
__device__ __half g_Kl [MTOK*DD];
__device__ __half g_Vl [MTOK*DD];
__device__ __half g_Kg [BT*NGLOB*DD];
__device__ __half g_Vg [BT*NGLOB*DD];
__device__ __half g_O  [MTOK*DD];
__device__ __half g_fwqk[2*DD*INCC];
__device__ float  g_fbqk[2*DD];
__device__ __half g_fwv[DD*DD];
__device__ __half g_fwo[DD*DD];
__device__ __half g_frw[INCC*INCC];
__device__ float  g_fbv[DD];
__device__ float  g_cvT[64*DD];
__device__ float  g_ckT[64*INCC];

// ---------------- helpers ----------------
__device__ __forceinline__ int win_map(int r) {
    int b = r >> 12;
    int p = r & 4095;
    int h = p >> 6, w = p & 63;
    int g = ((h >> 3) << 3) | (w >> 3);
    int n = ((h & 7) << 3) | (w & 7);
    return (((b << 6) | g) << 6) | n;
}

__device__ __forceinline__ uint32_t h2b(float a, float b) {
    __half2 h = __floats2half2_rn(a, b);
    return *(uint32_t*)&h;
}

__device__ __forceinline__ void mma_f16(float* d, const uint32_t* a, const uint32_t* b) {
    asm volatile(
        "mma.sync.aligned.m16n8k16.row.col.f32.f16.f16.f32 "
        "{%0,%1,%2,%3}, {%4,%5,%6,%7}, {%8,%9}, {%0,%1,%2,%3};"
        : "+f"(d[0]), "+f"(d[1]), "+f"(d[2]), "+f"(d[3])
        : "r"(a[0]), "r"(a[1]), "r"(a[2]), "r"(a[3]), "r"(b[0]), "r"(b[1]));
}

__device__ __forceinline__ void ldsm_x4(uint32_t* r, uint32_t addr) {
    asm volatile("ldmatrix.sync.aligned.m8n8.x4.shared.b16 {%0,%1,%2,%3}, [%4];"
                 : "=r"(r[0]), "=r"(r[1]), "=r"(r[2]), "=r"(r[3]) : "r"(addr));
}
__device__ __forceinline__ void ldsm_x4_t(uint32_t* r, uint32_t addr) {
    asm volatile("ldmatrix.sync.aligned.m8n8.x4.trans.shared.b16 {%0,%1,%2,%3}, [%4];"
                 : "=r"(r[0]), "=r"(r[1]), "=r"(r[2]), "=r"(r[3]) : "r"(addr));
}

#define CP_ASYNC16(dst, src) \
    asm volatile("cp.async.ca.shared.global [%0], [%1], 16;" :: "r"(dst), "l"(src))
#define CP_COMMIT() asm volatile("cp.async.commit_group;" ::: "memory")
#define CP_WAIT0()  asm volatile("cp.async.wait_group 0;" ::: "memory")

// ---------------- weight fold ----------------
__global__ __launch_bounds__(256)
void fold_w_kernel(const float* __restrict__ W, const float* __restrict__ gamma,
                   const float* __restrict__ beta, const float* __restrict__ b,
                   __half* __restrict__ Wo, float* __restrict__ bo, int N, int K) {
    int n = blockIdx.x * 8 + (threadIdx.x >> 5);
    if (n >= N) return;
    int lane = threadIdx.x & 31;
    const float* wr = W + (size_t)n * K;
    __half* wor = Wo + (size_t)n * K;
    float acc = 0.f;
    for (int k = lane; k < K; k += 32) {
        float w = wr[k];
        if (beta) acc += beta[k] * w;
        wor[k] = __float2half(gamma ? w * gamma[k] : w);
    }
    if (beta) {
        #pragma unroll
        for (int o = 16; o; o >>= 1) acc += __shfl_xor_sync(0xffffffffu, acc, o);
        if (lane == 0) bo[n] = b[n] + acc;
    }
}

// ---------------- conv weight transpose ----------------
__global__ __launch_bounds__(256)
void convT_kernel(const float* __restrict__ W, float* __restrict__ Wt, int C) {
    int idx = blockIdx.x * 256 + threadIdx.x;
    if (idx >= C * 64) return;
    int c = idx >> 6, k = idx & 63;
    Wt[k * C + c] = W[idx];
}

// ---------------- raw concat(x,f) -> half ----------------
__global__ __launch_bounds__(256)
void prep_xf_kernel(const float* __restrict__ x, const float* __restrict__ f,
                    __half* __restrict__ xf) {
    size_t idx = ((size_t)blockIdx.x * 256 + threadIdx.x) * 8;
    int r = (int)(idx / INCC);
    int c = (int)(idx % INCC);
    const float* src = (c < 512) ? (x + (size_t)r * 512 + c)
                                 : (f + (size_t)r * 128 + (c - 512));
    float4 a = *(const float4*)src;
    float4 b = *(const float4*)(src + 4);
    uint4 o;
    o.x = h2b(a.x, a.y); o.y = h2b(a.z, a.w);
    o.z = h2b(b.x, b.y); o.w = h2b(b.z, b.w);
    *(uint4*)(xf + idx) = o;
}

// ---------------- fused LN ----------------
template<int K>
__global__ __launch_bounds__(256)
void ln_norm_kernel(const float* __restrict__ X, __half* __restrict__ Xn) {
    const int NSEG = K / 128;
    int row = blockIdx.x * 8 + (threadIdx.x >> 5);
    int lane = threadIdx.x & 31;
    const float* xr = X + (size_t)row * K;
    float4 v[NSEG];
    float s = 0.f, ss = 0.f;
    #pragma unroll
    for (int i = 0; i < NSEG; i++) {
        v[i] = *(const float4*)(xr + lane * 4 + i * 128);
        s  += v[i].x + v[i].y + v[i].z + v[i].w;
        ss += v[i].x * v[i].x + v[i].y * v[i].y + v[i].z * v[i].z + v[i].w * v[i].w;
    }
    #pragma unroll
    for (int o = 16; o; o >>= 1) {
        s  += __shfl_xor_sync(0xffffffffu, s, o);
        ss += __shfl_xor_sync(0xffffffffu, ss, o);
    }
    float mean = s / K;
    float rstd = rsqrtf(ss / K - mean * mean + 1e-5f);
    __half* xo = Xn + (size_t)row * K;
    #pragma unroll
    for (int i = 0; i < NSEG; i++) {
        uint2 o;
        o.x = h2b((v[i].x - mean) * rstd, (v[i].y - mean) * rstd);
        o.y = h2b((v[i].z - mean) * rstd, (v[i].w - mean) * rstd);
        *(uint2*)(xo + lane * 4 + i * 128) = o;
    }
}

// ---------------- depthwise conv (coalesced weights) ----------------
template<int C>
__global__ __launch_bounds__(128)
void dwconv_kernel(const float* __restrict__ X, const float* __restrict__ Wt,
                   const float* __restrict__ bc, float* __restrict__ out) {
    int bw = blockIdx.y;
    int c = blockIdx.x * 128 + threadIdx.x;
    int b = bw >> 6;
    int g = bw & 63;
    int gh = g >> 3, gw = g & 7;
    const float* xb = X + ((size_t)b * NPIX + (size_t)(gh * 8) * 64 + gw * 8) * C + c;
    float s = bc[c];
    #pragma unroll
    for (int i = 0; i < 8; i++)
        #pragma unroll
        for (int j = 0; j < 8; j++)
            s += xb[(size_t)(i * 64 + j) * C] * Wt[(i * 8 + j) * C + c];
    out[(size_t)bw * C + c] = s;
}

// ---------------- fp16 mma GEMM ----------------
#define GS 72
template<int MODE, int SPLIT>
__global__ __launch_bounds__(256)
void mma_gemm(const __half* __restrict__ A, const __half* __restrict__ W,
              const float* __restrict__ bias,
              const float* __restrict__ Xraw, const float* __restrict__ Fraw,
              float* __restrict__ Cf, __half* __restrict__ Ch, __half* __restrict__ Ch2,
              int M, int N, int K, int ldc) {
    extern __shared__ __half sh[];
    __half* As = sh;
    __half* Bs = sh + 2 * 128 * GS;

    const int tid = threadIdx.x;
    const int m0 = blockIdx.y * 128;
    const int n0 = blockIdx.x * 128;
    const int q = tid & 7;
    const int lrow = tid >> 3;
    const int lane = tid & 31, grp = lane >> 2, tig = lane & 3;
    const int w = tid >> 5, mblk = (w & 3) * 32, nblk = (w >> 2) * 64;
    const int NC = K >> 6;

    const uint32_t as_s = (uint32_t)__cvta_generic_to_shared(As);
    const uint32_t bs_s = (uint32_t)__cvta_generic_to_shared(Bs);

    const uint32_t aoff0 = (uint32_t)(((mblk + (lane & 15)) * GS + (lane >> 4) * 8) * 2);
    const uint32_t aoff1 = aoff0 + (uint32_t)(16 * GS * 2);
    const uint32_t boff  = (uint32_t)(((nblk + (lane & 7) + ((lane & 16) ? 8 : 0)) * GS
                                       + ((lane & 8) ? 8 : 0)) * 2);

    int arow[4];
    #pragma unroll
    for (int i = 0; i < 4; i++) {
        int r = m0 + lrow + i * 32;
        arow[i] = (MODE == 3) ? win_map(r) : r;
    }

    float acc[2][8][4];
    #pragma unroll
    for (int mt = 0; mt < 2; mt++)
        #pragma unroll
        for (int nt = 0; nt < 8; nt++)
            #pragma unroll
            for (int e = 0; e < 4; e++) acc[mt][nt][e] = 0.f;

    auto issue = [&](int ch, int buf) {
        int gk = (ch << 6) + q * 8;
        #pragma unroll
        for (int i = 0; i < 4; i++) {
            int r = lrow + i * 32;
            CP_ASYNC16(as_s + (uint32_t)(((buf * 128 + r) * GS + q * 8) * 2),
                       A + (size_t)arow[i] * K + gk);
            CP_ASYNC16(bs_s + (uint32_t)(((buf * 128 + r) * GS + q * 8) * 2),
                       W + (size_t)(n0 + r) * K + gk);
        }
        CP_COMMIT();
    };
    auto compute = [&](int buf) {
        uint32_t abase = as_s + (uint32_t)(buf * 128 * GS * 2);
        uint32_t bbase = bs_s + (uint32_t)(buf * 128 * GS * 2);
        #pragma unroll
        for (int k16 = 0; k16 < 4; k16++) {
            uint32_t kb = (uint32_t)(k16 * 32);
            uint32_t af0[4], af1[4];
            ldsm_x4(af0, abase + aoff0 + kb);
            ldsm_x4(af1, abase + aoff1 + kb);
            #pragma unroll
            for (int p = 0; p < 4; p++) {
                uint32_t bf[4];
                ldsm_x4(bf, bbase + boff + (uint32_t)(p * 16 * GS * 2) + kb);
                mma_f16(acc[0][2 * p],     af0, bf);
                mma_f16(acc[1][2 * p],     af1, bf);
                mma_f16(acc[0][2 * p + 1], af0, bf + 2);
                mma_f16(acc[1][2 * p + 1], af1, bf + 2);
            }
        }
    };

    issue(0, 0);
    CP_WAIT0();
    __syncthreads();

    for (int ch = 0; ch < NC; ch++) {
        int buf = ch & 1;
        int nx = ch + 1;
        if (nx < NC) issue(nx, buf ^ 1);
        compute(buf);
        if (nx < NC) CP_WAIT0();
        __syncthreads();
    }

    #pragma unroll
    for (int mt = 0; mt < 2; mt++) {
        #pragma unroll
        for (int hr = 0; hr < 2; hr++) {
            int r = m0 + mblk + mt * 16 + grp + hr * 8;
            size_t orow = (MODE == 1) ? (size_t)win_map(r) : (size_t)r;
            #pragma unroll
            for (int nt = 0; nt < 8; nt++) {
                int c = n0 + nblk + nt * 8 + 2 * tig;
                float y0 = acc[mt][nt][hr * 2 + 0] + bias[c];
                float y1 = acc[mt][nt][hr * 2 + 1] + bias[c + 1];
                if (MODE == 0) {
                    float a0 = (c < 512) ? Xraw[(size_t)r * 512 + c]
                                         : Fraw[(size_t)r * 128 + (c - 512)];
                    float a1 = (c + 1 < 512) ? Xraw[(size_t)r * 512 + c + 1]
                                             : Fraw[(size_t)r * 128 + (c + 1 - 512)];
                    y0 = a0 / (1.f + __expf(-y0));
                    y1 = a1 / (1.f + __expf(-y1));
                    *(float2*)(Cf + orow * (size_t)ldc + c) = make_float2(y0, y1);
                } else if (MODE == 3) {
                    *(float2*)(Cf + orow * (size_t)ldc + c) = make_float2(y0, y1);
                } else {
                    __half* base = Ch;
                    int cc = c;
                    if (SPLIT) { base = (c < 512) ? Ch : Ch2; cc = c & 511; }
                    *(__half2*)(base + orow * (size_t)ldc + cc) = __floats2half2_rn(y0, y1);
                }
            }
        }
    }
}

// ---------------- attention: register softmax + trans-ldmatrix PV ----------------
#define AQ_STR 72
#define PS_STR 136
// Qs 64*72 + Ks 128*72 + Vs 128*72 + Ps 64*136 halves + Rmax/Rsum 2*128 floats
#define ATTN_SMEM_BYTES ((64*AQ_STR + 128*AQ_STR + 128*AQ_STR + 64*PS_STR) * 2 + 2 * 128 * 4)

__global__ __launch_bounds__(256)
void attn_kernel(const __half* __restrict__ Q, const __half* __restrict__ Kl,
                 const __half* __restrict__ Kg, const __half* __restrict__ Vl,
                 const __half* __restrict__ Vg, __half* __restrict__ O) {
    extern __shared__ char smraw[];
    __half* Qs = (__half*)smraw;                 // [64][72]
    __half* Ks = Qs + 64 * AQ_STR;               // [128][72]
    __half* Vs = Ks + 128 * AQ_STR;              // [128][72]  (key, d) natural
    __half* Ps = Vs + 128 * AQ_STR;              // [64][136]  unnormalized exp
    float* Rmax = (float*)(Ps + 64 * PS_STR);    // [2][64]
    float* Rsum = Rmax + 128;                    // [2][64]

    int bid = blockIdx.x;
    int b = bid >> 9;
    int rem = bid & 511;
    int g = rem >> 3;
    int h = rem & 7;

    size_t wbase = ((size_t)(b * GG + g) * NWIN) * DD + (size_t)h * DHH;
    size_t gbase = ((size_t)b * NGLOB) * DD + (size_t)h * DHH;
    const __half* Qp  = Q  + wbase;
    const __half* Klp = Kl + wbase;
    const __half* Vlp = Vl + wbase;
    const __half* Kgp = Kg + gbase;
    const __half* Vgp = Vg + gbase;
    __half* Op = O + wbase;

    int tid = threadIdx.x;
    const uint32_t qs_s = (uint32_t)__cvta_generic_to_shared(Qs);
    const uint32_t ks_s = (uint32_t)__cvta_generic_to_shared(Ks);
    const uint32_t vs_s = (uint32_t)__cvta_generic_to_shared(Vs);
    const uint32_t ps_s = (uint32_t)__cvta_generic_to_shared(Ps);

    // Q, K, V via cp.async
    for (int e = tid; e < 64 * 8; e += 256) {
        int m = e >> 3, sg = e & 7;
        CP_ASYNC16(qs_s + (uint32_t)((m * AQ_STR + sg * 8) * 2), Qp + (size_t)m * DD + sg * 8);
    }
    for (int e = tid; e < 128 * 8; e += 256) {
        int kk = e >> 3, sg = e & 7;
        const __half* ksrc = (kk < 64) ? (Klp + (size_t)kk * DD)
                                       : (Kgp + (size_t)(kk - 64) * DD);
        CP_ASYNC16(ks_s + (uint32_t)((kk * AQ_STR + sg * 8) * 2), ksrc + sg * 8);
        const __half* vsrc = (kk < 64) ? (Vlp + (size_t)kk * DD)
                                       : (Vgp + (size_t)(kk - 64) * DD);
        CP_ASYNC16(vs_s + (uint32_t)((kk * AQ_STR + sg * 8) * 2), vsrc + sg * 8);
    }
    CP_COMMIT();
    CP_WAIT0();
    __syncthreads();

    int w = tid >> 5, lane = tid & 31, grp = lane >> 2, tig = lane & 3;
    int mrow = (w & 3) * 16;
    int hh = w >> 2;               // key/d half index
    int nb0 = hh * 64;             // key range for QK
    int r0 = mrow + grp, r1 = r0 + 8;

    // ---- QK: per warp m16 x n64, k64 ----
    float acc[8][4];
    {
        const uint32_t aoff = qs_s +
            (uint32_t)(((mrow + (lane & 15)) * AQ_STR + (lane >> 4) * 8) * 2);
        const uint32_t boff = ks_s +
            (uint32_t)(((nb0 + (lane & 7) + ((lane & 16) ? 8 : 0)) * AQ_STR
                        + ((lane & 8) ? 8 : 0)) * 2);
        #pragma unroll
        for (int nt = 0; nt < 8; nt++)
            #pragma unroll
            for (int e = 0; e < 4; e++) acc[nt][e] = 0.f;
        #pragma unroll
        for (int k16 = 0; k16 < 4; k16++) {
            uint32_t kb = (uint32_t)(k16 * 32);
            uint32_t af[4];
            ldsm_x4(af, aoff + kb);
            #pragma unroll
            for (int p = 0; p < 4; p++) {
                uint32_t bf[4];
                ldsm_x4(bf, boff + (uint32_t)(p * 16 * AQ_STR * 2) + kb);
                mma_f16(acc[2 * p],     af, bf);
                mma_f16(acc[2 * p + 1], af, bf + 2);
            }
        }
    }

    // ---- softmax stats in registers ----
    float m0 = -1e30f, m1 = -1e30f;
    #pragma unroll
    for (int nt = 0; nt < 8; nt++) {
        m0 = fmaxf(m0, fmaxf(acc[nt][0], acc[nt][1]));
        m1 = fmaxf(m1, fmaxf(acc[nt][2], acc[nt][3]));
    }
    m0 = fmaxf(m0, __shfl_xor_sync(0xffffffffu, m0, 1));
    m0 = fmaxf(m0, __shfl_xor_sync(0xffffffffu, m0, 2));
    m1 = fmaxf(m1, __shfl_xor_sync(0xffffffffu, m1, 1));
    m1 = fmaxf(m1, __shfl_xor_sync(0xffffffffu, m1, 2));
    if (tig == 0) {
        Rmax[hh * 64 + r0] = m0;
        Rmax[hh * 64 + r1] = m1;
    }
    __syncthreads();
    float M0 = fmaxf(Rmax[r0], Rmax[64 + r0]) * 0.125f;
    float M1 = fmaxf(Rmax[r1], Rmax[64 + r1]) * 0.125f;

    float s0 = 0.f, s1 = 0.f;
    #pragma unroll
    for (int nt = 0; nt < 8; nt++) {
        float e0 = __expf(acc[nt][0] * 0.125f - M0);
        float e1 = __expf(acc[nt][1] * 0.125f - M0);
        float e2 = __expf(acc[nt][2] * 0.125f - M1);
        float e3 = __expf(acc[nt][3] * 0.125f - M1);
        s0 += e0 + e1;
        s1 += e2 + e3;
        int c = nb0 + nt * 8 + 2 * tig;
        *(__half2*)&Ps[r0 * PS_STR + c] = __floats2half2_rn(e0, e1);
        *(__half2*)&Ps[r1 * PS_STR + c] = __floats2half2_rn(e2, e3);
    }
    s0 += __shfl_xor_sync(0xffffffffu, s0, 1);
    s0 += __shfl_xor_sync(0xffffffffu, s0, 2);
    s1 += __shfl_xor_sync(0xffffffffu, s1, 1);
    s1 += __shfl_xor_sync(0xffffffffu, s1, 2);
    if (tig == 0) {
        Rsum[hh * 64 + r0] = s0;
        Rsum[hh * 64 + r1] = s1;
    }
    __syncthreads();
    float inv0 = 1.f / (Rsum[r0] + Rsum[64 + r0]);
    float inv1 = 1.f / (Rsum[r1] + Rsum[64 + r1]);

    // ---- PV: per warp m16 x n32, k128; B via trans ldmatrix on natural Vs ----
    {
        int db0 = hh * 32;
        const uint32_t aoff = ps_s +
            (uint32_t)(((mrow + (lane & 15)) * PS_STR + (lane >> 4) * 8) * 2);
        const uint32_t bvoff = vs_s +
            (uint32_t)((((lane & 7) + ((lane & 8) ? 8 : 0)) * AQ_STR
                        + db0 + ((lane & 16) ? 8 : 0)) * 2);
        float pac[4][4];
        #pragma unroll
        for (int nt = 0; nt < 4; nt++)
            #pragma unroll
            for (int e = 0; e < 4; e++) pac[nt][e] = 0.f;
        #pragma unroll
        for (int k16 = 0; k16 < 8; k16++) {
            uint32_t kba = (uint32_t)(k16 * 32);                    // Ps: 16 halves
            uint32_t kbb = (uint32_t)(k16 * 16 * AQ_STR * 2);       // Vs: 16 rows
            uint32_t af[4];
            ldsm_x4(af, aoff + kba);
            #pragma unroll
            for (int p = 0; p < 2; p++) {
                uint32_t bf[4];
                ldsm_x4_t(bf, bvoff + (uint32_t)(p * 16 * 2) + kbb);
                mma_f16(pac[2 * p],     af, bf);
                mma_f16(pac[2 * p + 1], af, bf + 2);
            }
        }
        #pragma unroll
        for (int nt = 0; nt < 4; nt++) {
            int c = db0 + nt * 8 + 2 * tig;
            *(__half2*)(Op + (size_t)r0 * DD + c) =
                __floats2half2_rn(pac[nt][0] * inv0, pac[nt][1] * inv0);
            *(__half2*)(Op + (size_t)r1 * DD + c) =
                __floats2half2_rn(pac[nt][2] * inv1, pac[nt][3] * inv1);
        }
    }
}

// ---------------- launch ----------------
#define SMEM_GEMM (4 * 128 * GS * 2)

extern "C" void kernel_launch(void* const* d_in, const int* in_sizes, int n_in,
                              void* d_out, int out_size) {
    const float* x       = (const float*)d_in[0];
    const float* f       = (const float*)d_in[1];
    const float* wq      = (const float*)d_in[2];
    const float* bq      = (const float*)d_in[3];
    const float* wk      = (const float*)d_in[4];
    const float* bk      = (const float*)d_in[5];
    const float* wv      = (const float*)d_in[6];
    const float* bv      = (const float*)d_in[7];
    const float* wo      = (const float*)d_in[8];
    const float* bo      = (const float*)d_in[9];
    const float* rw_w    = (const float*)d_in[10];
    const float* rw_b    = (const float*)d_in[11];
    const float* convk_w = (const float*)d_in[12];
    const float* convk_b = (const float*)d_in[13];
    const float* convv_w = (const float*)d_in[14];
    const float* convv_b = (const float*)d_in[15];
    const float* qn_g    = (const float*)d_in[16];
    const float* qn_b    = (const float*)d_in[17];
    const float* kn_g    = (const float*)d_in[18];
    const float* kn_b    = (const float*)d_in[19];
    const float* vn_g    = (const float*)d_in[20];
    const float* vn_b    = (const float*)d_in[21];
    float* out = (float*)d_out;

    float *qk, *kg, *vg, *fbqk, *fbv, *cvT, *ckT;
    __half *xf, *qkn, *xn, *kgn, *vgn, *Q, *Kl, *Vl, *Kg, *Vg, *O;
    __half *fwqk, *fwv, *fwo, *frw;
    cudaGetSymbolAddress((void**)&qk,   g_qk);
    cudaGetSymbolAddress((void**)&kg,   g_kg);
    cudaGetSymbolAddress((void**)&vg,   g_vg);
    cudaGetSymbolAddress((void**)&xf,   g_xf);
    cudaGetSymbolAddress((void**)&qkn,  g_qkn);
    cudaGetSymbolAddress((void**)&xn,   g_xn);
    cudaGetSymbolAddress((void**)&kgn,  g_kgn);
    cudaGetSymbolAddress((void**)&vgn,  g_vgn);
    cudaGetSymbolAddress((void**)&Q,    g_Q);
    cudaGetSymbolAddress((void**)&Kl,   g_Kl);
    cudaGetSymbolAddress((void**)&Vl,   g_Vl);
    cudaGetSymbolAddress((void**)&Kg,   g_Kg);
    cudaGetSymbolAddress((void**)&Vg,   g_Vg);
    cudaGetSymbolAddress((void**)&O,    g_O);
    cudaGetSymbolAddress((void**)&fwqk, g_fwqk);
    cudaGetSymbolAddress((void**)&fbqk, g_fbqk);
    cudaGetSymbolAddress((void**)&fwv,  g_fwv);
    cudaGetSymbolAddress((void**)&fwo,  g_fwo);
    cudaGetSymbolAddress((void**)&frw,  g_frw);
    cudaGetSymbolAddress((void**)&fbv,  g_fbv);
    cudaGetSymbolAddress((void**)&cvT,  g_cvT);
    cudaGetSymbolAddress((void**)&ckT,  g_ckT);

    cudaFuncSetAttribute(attn_kernel, cudaFuncAttributeMaxDynamicSharedMemorySize,
                         ATTN_SMEM_BYTES);
    cudaFuncSetAttribute(mma_gemm<0,0>, cudaFuncAttributeMaxDynamicSharedMemorySize, SMEM_GEMM);
    cudaFuncSetAttribute(mma_gemm<1,1>, cudaFuncAttributeMaxDynamicSharedMemorySize, SMEM_GEMM);
    cudaFuncSetAttribute(mma_gemm<1,0>, cudaFuncAttributeMaxDynamicSharedMemorySize, SMEM_GEMM);
    cudaFuncSetAttribute(mma_gemm<2,0>, cudaFuncAttributeMaxDynamicSharedMemorySize, SMEM_GEMM);
    cudaFuncSetAttribute(mma_gemm<3,0>, cudaFuncAttributeMaxDynamicSharedMemorySize, SMEM_GEMM);

    cudaStream_t s1;
    cudaStreamCreateWithFlags(&s1, cudaStreamNonBlocking);
    cudaEvent_t evFork, evJoinV, evRW, evJoinKG;
    cudaEventCreateWithFlags(&evFork,   cudaEventDisableTiming);
    cudaEventCreateWithFlags(&evJoinV,  cudaEventDisableTiming);
    cudaEventCreateWithFlags(&evRW,     cudaEventDisableTiming);
    cudaEventCreateWithFlags(&evJoinKG, cudaEventDisableTiming);

    cudaEventRecord(evFork, 0);
    cudaStreamWaitEvent(s1, evFork, 0);

    // ---- s1: x-side chain + off-critical folds ----
    fold_w_kernel<<<64, 256, 0, s1>>>(wv, vn_g, vn_b, bv, fwv, fbv, DD, DD);
    fold_w_kernel<<<64, 256, 0, s1>>>(wo, nullptr, nullptr, nullptr, fwo, nullptr, DD, DD);
    fold_w_kernel<<<64, 256, 0, s1>>>(wq, qn_g, qn_b, bq, fwqk, fbqk, DD, INCC);
    fold_w_kernel<<<64, 256, 0, s1>>>(wk, kn_g, kn_b, bk, fwqk + (size_t)DD * INCC, fbqk + DD, DD, INCC);
    convT_kernel<<<(DD * 64) / 256, 256, 0, s1>>>(convv_w, cvT, DD);
    convT_kernel<<<(INCC * 64) / 256, 256, 0, s1>>>(convk_w, ckT, INCC);
    ln_norm_kernel<512><<<MTOK / 8, 256, 0, s1>>>(x, xn);
    dwconv_kernel<512><<<dim3(4, BT * GG), 128, 0, s1>>>(x, cvT, convv_b, vg);
    ln_norm_kernel<512><<<(BT * NGLOB) / 8, 256, 0, s1>>>(vg, vgn);
    mma_gemm<1,0><<<dim3(4, 256), 256, SMEM_GEMM, s1>>>(
        xn, fwv, fbv, nullptr, nullptr, nullptr, Vl, nullptr, MTOK, DD, DD, DD);
    mma_gemm<2,0><<<dim3(4, 4), 256, SMEM_GEMM, s1>>>(
        vgn, fwv, fbv, nullptr, nullptr, nullptr, Vg, nullptr, BT * NGLOB, DD, DD, DD);
    cudaEventRecord(evJoinV, s1);

    // ---- default stream: qk critical path ----
    fold_w_kernel<<<80, 256>>>(rw_w, nullptr, nullptr, nullptr, frw, nullptr, INCC, INCC);
    prep_xf_kernel<<<MTOK * INCC / 2048, 256>>>(x, f, xf);

    mma_gemm<0,0><<<dim3(5, 256), 256, SMEM_GEMM>>>(
        xf, frw, rw_b, x, f, qk, nullptr, nullptr, MTOK, INCC, INCC, INCC);
    cudaEventRecord(evRW, 0);

    // ---- s1: kg chain overlapping QK projection ----
    cudaStreamWaitEvent(s1, evRW, 0);
    dwconv_kernel<640><<<dim3(5, BT * GG), 128, 0, s1>>>(qk, ckT, convk_b, kg);
    ln_norm_kernel<640><<<(BT * NGLOB) / 8, 256, 0, s1>>>(kg, kgn);
    mma_gemm<2,0><<<dim3(4, 4), 256, SMEM_GEMM, s1>>>(
        kgn, fwqk + (size_t)DD * INCC, fbqk + DD, nullptr, nullptr, nullptr, Kg, nullptr,
        BT * NGLOB, DD, INCC, DD);
    cudaEventRecord(evJoinKG, s1);

    // ---- default stream: LN(qk) + QK projection ----
    ln_norm_kernel<640><<<MTOK / 8, 256>>>(qk, qkn);
    mma_gemm<1,1><<<dim3(8, 256), 256, SMEM_GEMM>>>(
        qkn, fwqk, fbqk, nullptr, nullptr, nullptr, Q, Kl, MTOK, 2 * DD, INCC, DD);

    // ---- join & finish ----
    cudaStreamWaitEvent(0, evJoinV, 0);
    cudaStreamWaitEvent(0, evJoinKG, 0);
    attn_kernel<<<BT * GG * NHEAD, 256, ATTN_SMEM_BYTES>>>(Q, Kl, Kg, Vl, Vg, O);
    mma_gemm<3,0><<<dim3(4, 256), 256, SMEM_GEMM>>>(
        O, fwo, bo, nullptr, nullptr, out, nullptr, nullptr, MTOK, DD, DD, DD);

    cudaEventDestroy(evFork);
    cudaEventDestroy(evJoinV);
    cudaEventDestroy(evRW);
    cudaEventDestroy(evJoinKG);
    cudaStreamDestroy(s1);
}

// round 13
// speedup vs baseline: 3.1714x; 1.0699x over previous
#include <cuda_runtime.h>
#include <cuda_fp16.h>
#include <cstdint>

// ---------------- problem constants ----------------
#define BT     8
#define NPIX   4096
#define DD     512
#define CFF    128
#define INCC   640
#define GG     64
#define NWIN   64
#define NGLOB  64
#define NHEAD  8
#define DHH    64
#define MTOK   32768

// ---------------- scratch ----------------
__device__ float  g_kg [BT*NGLOB*INCC];
__device__ float  g_vg [BT*NGLOB*DD];
__device__ __half g_xf [MTOK*INCC];
__device__ __half g_qkh[MTOK*INCC];          // reweighted concat, half
__device__ __half g_qkn[MTOK*INCC];
__device__ __half g_xn [MTOK*DD];
__device__ __half g_kgn[BT*NGLOB*INCC];
__device__ __half g_vgn[BT*NGLOB*DD];
__device__ __half g_Q  [MTOK*DD];
__device__ __half g_Kl [MTOK*DD];
__device__ __half g_Vl [MTOK*DD];
__device__ __half g_Kg [BT*NGLOB*DD];
__device__ __half g_Vg [BT*NGLOB*DD];
__device__ __half g_O  [MTOK*DD];
__device__ __half g_fwqk[2*DD*INCC];
__device__ float  g_fbqk[2*DD];
__device__ __half g_fwv[DD*DD];
__device__ __half g_fwo[DD*DD];
__device__ __half g_frw[INCC*INCC];
__device__ float  g_fbv[DD];
__device__ float  g_cvT[64*DD];
__device__ float  g_ckT[64*INCC];

// ---------------- helpers ----------------
__device__ __forceinline__ int win_map(int r) {
    int b = r >> 12;
    int p = r & 4095;
    int h = p >> 6, w = p & 63;
    int g = ((h >> 3) << 3) | (w >> 3);
    int n = ((h & 7) << 3) | (w & 7);
    return (((b << 6) | g) << 6) | n;
}

__device__ __forceinline__ uint32_t h2b(float a, float b) {
    __half2 h = __floats2half2_rn(a, b);
    return *(uint32_t*)&h;
}

__device__ __forceinline__ void mma_f16(float* d, const uint32_t* a, const uint32_t* b) {
    asm volatile(
        "mma.sync.aligned.m16n8k16.row.col.f32.f16.f16.f32 "
        "{%0,%1,%2,%3}, {%4,%5,%6,%7}, {%8,%9}, {%0,%1,%2,%3};"
        : "+f"(d[0]), "+f"(d[1]), "+f"(d[2]), "+f"(d[3])
        : "r"(a[0]), "r"(a[1]), "r"(a[2]), "r"(a[3]), "r"(b[0]), "r"(b[1]));
}

__device__ __forceinline__ void ldsm_x4(uint32_t* r, uint32_t addr) {
    asm volatile("ldmatrix.sync.aligned.m8n8.x4.shared.b16 {%0,%1,%2,%3}, [%4];"
                 : "=r"(r[0]), "=r"(r[1]), "=r"(r[2]), "=r"(r[3]) : "r"(addr));
}
__device__ __forceinline__ void ldsm_x4_t(uint32_t* r, uint32_t addr) {
    asm volatile("ldmatrix.sync.aligned.m8n8.x4.trans.shared.b16 {%0,%1,%2,%3}, [%4];"
                 : "=r"(r[0]), "=r"(r[1]), "=r"(r[2]), "=r"(r[3]) : "r"(addr));
}

#define CP_ASYNC16(dst, src) \
    asm volatile("cp.async.ca.shared.global [%0], [%1], 16;" :: "r"(dst), "l"(src))
#define CP_COMMIT() asm volatile("cp.async.commit_group;" ::: "memory")
#define CP_WAIT0()  asm volatile("cp.async.wait_group 0;" ::: "memory")

// ---------------- weight fold ----------------
__global__ __launch_bounds__(256)
void fold_w_kernel(const float* __restrict__ W, const float* __restrict__ gamma,
                   const float* __restrict__ beta, const float* __restrict__ b,
                   __half* __restrict__ Wo, float* __restrict__ bo, int N, int K) {
    int n = blockIdx.x * 8 + (threadIdx.x >> 5);
    if (n >= N) return;
    int lane = threadIdx.x & 31;
    const float* wr = W + (size_t)n * K;
    __half* wor = Wo + (size_t)n * K;
    float acc = 0.f;
    for (int k = lane; k < K; k += 32) {
        float w = wr[k];
        if (beta) acc += beta[k] * w;
        wor[k] = __float2half(gamma ? w * gamma[k] : w);
    }
    if (beta) {
        #pragma unroll
        for (int o = 16; o; o >>= 1) acc += __shfl_xor_sync(0xffffffffu, acc, o);
        if (lane == 0) bo[n] = b[n] + acc;
    }
}

// ---------------- conv weight transpose ----------------
__global__ __launch_bounds__(256)
void convT_kernel(const float* __restrict__ W, float* __restrict__ Wt, int C) {
    int idx = blockIdx.x * 256 + threadIdx.x;
    if (idx >= C * 64) return;
    int c = idx >> 6, k = idx & 63;
    Wt[k * C + c] = W[idx];
}

// ---------------- raw concat(x,f) -> half ----------------
__global__ __launch_bounds__(256)
void prep_xf_kernel(const float* __restrict__ x, const float* __restrict__ f,
                    __half* __restrict__ xf) {
    size_t idx = ((size_t)blockIdx.x * 256 + threadIdx.x) * 8;
    int r = (int)(idx / INCC);
    int c = (int)(idx % INCC);
    const float* src = (c < 512) ? (x + (size_t)r * 512 + c)
                                 : (f + (size_t)r * 128 + (c - 512));
    float4 a = *(const float4*)src;
    float4 b = *(const float4*)(src + 4);
    uint4 o;
    o.x = h2b(a.x, a.y); o.y = h2b(a.z, a.w);
    o.z = h2b(b.x, b.y); o.w = h2b(b.z, b.w);
    *(uint4*)(xf + idx) = o;
}

// ---------------- fused LN (fp32 input) ----------------
template<int K>
__global__ __launch_bounds__(256)
void ln_norm_kernel(const float* __restrict__ X, __half* __restrict__ Xn) {
    const int NSEG = K / 128;
    int row = blockIdx.x * 8 + (threadIdx.x >> 5);
    int lane = threadIdx.x & 31;
    const float* xr = X + (size_t)row * K;
    float4 v[NSEG];
    float s = 0.f, ss = 0.f;
    #pragma unroll
    for (int i = 0; i < NSEG; i++) {
        v[i] = *(const float4*)(xr + lane * 4 + i * 128);
        s  += v[i].x + v[i].y + v[i].z + v[i].w;
        ss += v[i].x * v[i].x + v[i].y * v[i].y + v[i].z * v[i].z + v[i].w * v[i].w;
    }
    #pragma unroll
    for (int o = 16; o; o >>= 1) {
        s  += __shfl_xor_sync(0xffffffffu, s, o);
        ss += __shfl_xor_sync(0xffffffffu, ss, o);
    }
    float mean = s / K;
    float rstd = rsqrtf(ss / K - mean * mean + 1e-5f);
    __half* xo = Xn + (size_t)row * K;
    #pragma unroll
    for (int i = 0; i < NSEG; i++) {
        uint2 o;
        o.x = h2b((v[i].x - mean) * rstd, (v[i].y - mean) * rstd);
        o.y = h2b((v[i].z - mean) * rstd, (v[i].w - mean) * rstd);
        *(uint2*)(xo + lane * 4 + i * 128) = o;
    }
}

// ---------------- fused LN (half input) ----------------
template<int K>
__global__ __launch_bounds__(256)
void ln_norm_h_kernel(const __half* __restrict__ X, __half* __restrict__ Xn, int row0) {
    const int NSEG = K / 128;
    int row = row0 + blockIdx.x * 8 + (threadIdx.x >> 5);
    int lane = threadIdx.x & 31;
    const __half* xr = X + (size_t)row * K;
    float v[NSEG][4];
    float s = 0.f, ss = 0.f;
    #pragma unroll
    for (int i = 0; i < NSEG; i++) {
        uint2 p = *(const uint2*)(xr + lane * 4 + i * 128);
        __half2 h0 = *(__half2*)&p.x;
        __half2 h1 = *(__half2*)&p.y;
        v[i][0] = __half2float(h0.x); v[i][1] = __half2float(h0.y);
        v[i][2] = __half2float(h1.x); v[i][3] = __half2float(h1.y);
        #pragma unroll
        for (int j = 0; j < 4; j++) { s += v[i][j]; ss += v[i][j] * v[i][j]; }
    }
    #pragma unroll
    for (int o = 16; o; o >>= 1) {
        s  += __shfl_xor_sync(0xffffffffu, s, o);
        ss += __shfl_xor_sync(0xffffffffu, ss, o);
    }
    float mean = s / K;
    float rstd = rsqrtf(ss / K - mean * mean + 1e-5f);
    __half* xo = Xn + (size_t)row * K;
    #pragma unroll
    for (int i = 0; i < NSEG; i++) {
        uint2 o;
        o.x = h2b((v[i][0] - mean) * rstd, (v[i][1] - mean) * rstd);
        o.y = h2b((v[i][2] - mean) * rstd, (v[i][3] - mean) * rstd);
        *(uint2*)(xo + lane * 4 + i * 128) = o;
    }
}

// ---------------- depthwise conv (coalesced weights, generic input type) ----------------
template<int C, typename T>
__global__ __launch_bounds__(128)
void dwconv_kernel(const T* __restrict__ X, const float* __restrict__ Wt,
                   const float* __restrict__ bc, float* __restrict__ out) {
    int bw = blockIdx.y;
    int c = blockIdx.x * 128 + threadIdx.x;
    int b = bw >> 6;
    int g = bw & 63;
    int gh = g >> 3, gw = g & 7;
    const T* xb = X + ((size_t)b * NPIX + (size_t)(gh * 8) * 64 + gw * 8) * C + c;
    float s = bc[c];
    #pragma unroll
    for (int i = 0; i < 8; i++)
        #pragma unroll
        for (int j = 0; j < 8; j++)
            s += (float)xb[(size_t)(i * 64 + j) * C] * Wt[(i * 8 + j) * C + c];
    out[(size_t)bw * C + c] = s;
}

// ---------------- fp16 mma GEMM ----------------
// MODE 0: sigmoid-reweight epilogue (raw a from A), half out Ch
// MODE 1: +bias, half out, row=win_map, SPLIT cols -> Ch/Ch2
// MODE 2: +bias, half out, identity rows
// MODE 3: A gathered via win_map; +bias, fp32 out Cf
#define GS 72
template<int MODE, int SPLIT>
__global__ __launch_bounds__(256)
void mma_gemm(const __half* __restrict__ A, const __half* __restrict__ W,
              const float* __restrict__ bias,
              float* __restrict__ Cf, __half* __restrict__ Ch, __half* __restrict__ Ch2,
              int M, int N, int K, int ldc, int m_off) {
    extern __shared__ __half sh[];
    __half* As = sh;
    __half* Bs = sh + 2 * 128 * GS;

    const int tid = threadIdx.x;
    const int m0 = blockIdx.y * 128 + m_off;
    const int n0 = blockIdx.x * 128;
    const int q = tid & 7;
    const int lrow = tid >> 3;
    const int lane = tid & 31, grp = lane >> 2, tig = lane & 3;
    const int w = tid >> 5, mblk = (w & 3) * 32, nblk = (w >> 2) * 64;
    const int NC = K >> 6;

    const uint32_t as_s = (uint32_t)__cvta_generic_to_shared(As);
    const uint32_t bs_s = (uint32_t)__cvta_generic_to_shared(Bs);

    const uint32_t aoff0 = (uint32_t)(((mblk + (lane & 15)) * GS + (lane >> 4) * 8) * 2);
    const uint32_t aoff1 = aoff0 + (uint32_t)(16 * GS * 2);
    const uint32_t boff  = (uint32_t)(((nblk + (lane & 7) + ((lane & 16) ? 8 : 0)) * GS
                                       + ((lane & 8) ? 8 : 0)) * 2);

    int arow[4];
    #pragma unroll
    for (int i = 0; i < 4; i++) {
        int r = m0 + lrow + i * 32;
        arow[i] = (MODE == 3) ? win_map(r) : r;
    }

    float acc[2][8][4];
    #pragma unroll
    for (int mt = 0; mt < 2; mt++)
        #pragma unroll
        for (int nt = 0; nt < 8; nt++)
            #pragma unroll
            for (int e = 0; e < 4; e++) acc[mt][nt][e] = 0.f;

    auto issue = [&](int ch, int buf) {
        int gk = (ch << 6) + q * 8;
        #pragma unroll
        for (int i = 0; i < 4; i++) {
            int r = lrow + i * 32;
            CP_ASYNC16(as_s + (uint32_t)(((buf * 128 + r) * GS + q * 8) * 2),
                       A + (size_t)arow[i] * K + gk);
            CP_ASYNC16(bs_s + (uint32_t)(((buf * 128 + r) * GS + q * 8) * 2),
                       W + (size_t)(n0 + r) * K + gk);
        }
        CP_COMMIT();
    };
    auto compute = [&](int buf) {
        uint32_t abase = as_s + (uint32_t)(buf * 128 * GS * 2);
        uint32_t bbase = bs_s + (uint32_t)(buf * 128 * GS * 2);
        #pragma unroll
        for (int k16 = 0; k16 < 4; k16++) {
            uint32_t kb = (uint32_t)(k16 * 32);
            uint32_t af0[4], af1[4];
            ldsm_x4(af0, abase + aoff0 + kb);
            ldsm_x4(af1, abase + aoff1 + kb);
            #pragma unroll
            for (int p = 0; p < 4; p++) {
                uint32_t bf[4];
                ldsm_x4(bf, bbase + boff + (uint32_t)(p * 16 * GS * 2) + kb);
                mma_f16(acc[0][2 * p],     af0, bf);
                mma_f16(acc[1][2 * p],     af1, bf);
                mma_f16(acc[0][2 * p + 1], af0, bf + 2);
                mma_f16(acc[1][2 * p + 1], af1, bf + 2);
            }
        }
    };

    issue(0, 0);
    CP_WAIT0();
    __syncthreads();

    for (int ch = 0; ch < NC; ch++) {
        int buf = ch & 1;
        int nx = ch + 1;
        if (nx < NC) issue(nx, buf ^ 1);
        compute(buf);
        if (nx < NC) CP_WAIT0();
        __syncthreads();
    }

    #pragma unroll
    for (int mt = 0; mt < 2; mt++) {
        #pragma unroll
        for (int hr = 0; hr < 2; hr++) {
            int r = m0 + mblk + mt * 16 + grp + hr * 8;
            size_t orow = (MODE == 1) ? (size_t)win_map(r) : (size_t)r;
            #pragma unroll
            for (int nt = 0; nt < 8; nt++) {
                int c = n0 + nblk + nt * 8 + 2 * tig;
                float y0 = acc[mt][nt][hr * 2 + 0] + bias[c];
                float y1 = acc[mt][nt][hr * 2 + 1] + bias[c + 1];
                if (MODE == 0) {
                    __half2 a01 = *(const __half2*)(A + (size_t)r * K + c);
                    y0 = __half2float(a01.x) / (1.f + __expf(-y0));
                    y1 = __half2float(a01.y) / (1.f + __expf(-y1));
                    *(__half2*)(Ch + orow * (size_t)ldc + c) = __floats2half2_rn(y0, y1);
                } else if (MODE == 3) {
                    *(float2*)(Cf + orow * (size_t)ldc + c) = make_float2(y0, y1);
                } else {
                    __half* base = Ch;
                    int cc = c;
                    if (SPLIT) { base = (c < 512) ? Ch : Ch2; cc = c & 511; }
                    *(__half2*)(base + orow * (size_t)ldc + cc) = __floats2half2_rn(y0, y1);
                }
            }
        }
    }
}

// ---------------- attention: register softmax + trans-ldmatrix PV ----------------
#define AQ_STR 72
#define PS_STR 136
#define ATTN_SMEM_BYTES ((64*AQ_STR + 128*AQ_STR + 128*AQ_STR + 64*PS_STR) * 2 + 2 * 128 * 4)

__global__ __launch_bounds__(256)
void attn_kernel(const __half* __restrict__ Q, const __half* __restrict__ Kl,
                 const __half* __restrict__ Kg, const __half* __restrict__ Vl,
                 const __half* __restrict__ Vg, __half* __restrict__ O, int bid_off) {
    extern __shared__ char smraw[];
    __half* Qs = (__half*)smraw;
    __half* Ks = Qs + 64 * AQ_STR;
    __half* Vs = Ks + 128 * AQ_STR;
    __half* Ps = Vs + 128 * AQ_STR;
    float* Rmax = (float*)(Ps + 64 * PS_STR);
    float* Rsum = Rmax + 128;

    int bid = blockIdx.x + bid_off;
    int b = bid >> 9;
    int rem = bid & 511;
    int g = rem >> 3;
    int h = rem & 7;

    size_t wbase = ((size_t)(b * GG + g) * NWIN) * DD + (size_t)h * DHH;
    size_t gbase = ((size_t)b * NGLOB) * DD + (size_t)h * DHH;
    const __half* Qp  = Q  + wbase;
    const __half* Klp = Kl + wbase;
    const __half* Vlp = Vl + wbase;
    const __half* Kgp = Kg + gbase;
    const __half* Vgp = Vg + gbase;
    __half* Op = O + wbase;

    int tid = threadIdx.x;
    const uint32_t qs_s = (uint32_t)__cvta_generic_to_shared(Qs);
    const uint32_t ks_s = (uint32_t)__cvta_generic_to_shared(Ks);
    const uint32_t vs_s = (uint32_t)__cvta_generic_to_shared(Vs);
    const uint32_t ps_s = (uint32_t)__cvta_generic_to_shared(Ps);

    for (int e = tid; e < 64 * 8; e += 256) {
        int m = e >> 3, sg = e & 7;
        CP_ASYNC16(qs_s + (uint32_t)((m * AQ_STR + sg * 8) * 2), Qp + (size_t)m * DD + sg * 8);
    }
    for (int e = tid; e < 128 * 8; e += 256) {
        int kk = e >> 3, sg = e & 7;
        const __half* ksrc = (kk < 64) ? (Klp + (size_t)kk * DD)
                                       : (Kgp + (size_t)(kk - 64) * DD);
        CP_ASYNC16(ks_s + (uint32_t)((kk * AQ_STR + sg * 8) * 2), ksrc + sg * 8);
        const __half* vsrc = (kk < 64) ? (Vlp + (size_t)kk * DD)
                                       : (Vgp + (size_t)(kk - 64) * DD);
        CP_ASYNC16(vs_s + (uint32_t)((kk * AQ_STR + sg * 8) * 2), vsrc + sg * 8);
    }
    CP_COMMIT();
    CP_WAIT0();
    __syncthreads();

    int w = tid >> 5, lane = tid & 31, grp = lane >> 2, tig = lane & 3;
    int mrow = (w & 3) * 16;
    int hh = w >> 2;
    int nb0 = hh * 64;
    int r0 = mrow + grp, r1 = r0 + 8;

    float acc[8][4];
    {
        const uint32_t aoff = qs_s +
            (uint32_t)(((mrow + (lane & 15)) * AQ_STR + (lane >> 4) * 8) * 2);
        const uint32_t boff = ks_s +
            (uint32_t)(((nb0 + (lane & 7) + ((lane & 16) ? 8 : 0)) * AQ_STR
                        + ((lane & 8) ? 8 : 0)) * 2);
        #pragma unroll
        for (int nt = 0; nt < 8; nt++)
            #pragma unroll
            for (int e = 0; e < 4; e++) acc[nt][e] = 0.f;
        #pragma unroll
        for (int k16 = 0; k16 < 4; k16++) {
            uint32_t kb = (uint32_t)(k16 * 32);
            uint32_t af[4];
            ldsm_x4(af, aoff + kb);
            #pragma unroll
            for (int p = 0; p < 4; p++) {
                uint32_t bf[4];
                ldsm_x4(bf, boff + (uint32_t)(p * 16 * AQ_STR * 2) + kb);
                mma_f16(acc[2 * p],     af, bf);
                mma_f16(acc[2 * p + 1], af, bf + 2);
            }
        }
    }

    float m0 = -1e30f, m1 = -1e30f;
    #pragma unroll
    for (int nt = 0; nt < 8; nt++) {
        m0 = fmaxf(m0, fmaxf(acc[nt][0], acc[nt][1]));
        m1 = fmaxf(m1, fmaxf(acc[nt][2], acc[nt][3]));
    }
    m0 = fmaxf(m0, __shfl_xor_sync(0xffffffffu, m0, 1));
    m0 = fmaxf(m0, __shfl_xor_sync(0xffffffffu, m0, 2));
    m1 = fmaxf(m1, __shfl_xor_sync(0xffffffffu, m1, 1));
    m1 = fmaxf(m1, __shfl_xor_sync(0xffffffffu, m1, 2));
    if (tig == 0) {
        Rmax[hh * 64 + r0] = m0;
        Rmax[hh * 64 + r1] = m1;
    }
    __syncthreads();
    float M0 = fmaxf(Rmax[r0], Rmax[64 + r0]) * 0.125f;
    float M1 = fmaxf(Rmax[r1], Rmax[64 + r1]) * 0.125f;

    float s0 = 0.f, s1 = 0.f;
    #pragma unroll
    for (int nt = 0; nt < 8; nt++) {
        float e0 = __expf(acc[nt][0] * 0.125f - M0);
        float e1 = __expf(acc[nt][1] * 0.125f - M0);
        float e2 = __expf(acc[nt][2] * 0.125f - M1);
        float e3 = __expf(acc[nt][3] * 0.125f - M1);
        s0 += e0 + e1;
        s1 += e2 + e3;
        int c = nb0 + nt * 8 + 2 * tig;
        *(__half2*)&Ps[r0 * PS_STR + c] = __floats2half2_rn(e0, e1);
        *(__half2*)&Ps[r1 * PS_STR + c] = __floats2half2_rn(e2, e3);
    }
    s0 += __shfl_xor_sync(0xffffffffu, s0, 1);
    s0 += __shfl_xor_sync(0xffffffffu, s0, 2);
    s1 += __shfl_xor_sync(0xffffffffu, s1, 1);
    s1 += __shfl_xor_sync(0xffffffffu, s1, 2);
    if (tig == 0) {
        Rsum[hh * 64 + r0] = s0;
        Rsum[hh * 64 + r1] = s1;
    }
    __syncthreads();
    float inv0 = 1.f / (Rsum[r0] + Rsum[64 + r0]);
    float inv1 = 1.f / (Rsum[r1] + Rsum[64 + r1]);

    {
        int db0 = hh * 32;
        const uint32_t aoff = ps_s +
            (uint32_t)(((mrow + (lane & 15)) * PS_STR + (lane >> 4) * 8) * 2);
        const uint32_t bvoff = vs_s +
            (uint32_t)((((lane & 7) + ((lane & 8) ? 8 : 0)) * AQ_STR
                        + db0 + ((lane & 16) ? 8 : 0)) * 2);
        float pac[4][4];
        #pragma unroll
        for (int nt = 0; nt < 4; nt++)
            #pragma unroll
            for (int e = 0; e < 4; e++) pac[nt][e] = 0.f;
        #pragma unroll
        for (int k16 = 0; k16 < 8; k16++) {
            uint32_t kba = (uint32_t)(k16 * 32);
            uint32_t kbb = (uint32_t)(k16 * 16 * AQ_STR * 2);
            uint32_t af[4];
            ldsm_x4(af, aoff + kba);
            #pragma unroll
            for (int p = 0; p < 2; p++) {
                uint32_t bf[4];
                ldsm_x4_t(bf, bvoff + (uint32_t)(p * 16 * 2) + kbb);
                mma_f16(pac[2 * p],     af, bf);
                mma_f16(pac[2 * p + 1], af, bf + 2);
            }
        }
        #pragma unroll
        for (int nt = 0; nt < 4; nt++) {
            int c = db0 + nt * 8 + 2 * tig;
            *(__half2*)(Op + (size_t)r0 * DD + c) =
                __floats2half2_rn(pac[nt][0] * inv0, pac[nt][1] * inv0);
            *(__half2*)(Op + (size_t)r1 * DD + c) =
                __floats2half2_rn(pac[nt][2] * inv1, pac[nt][3] * inv1);
        }
    }
}

// ---------------- launch ----------------
#define SMEM_GEMM (4 * 128 * GS * 2)
#define MH (MTOK / 2)

extern "C" void kernel_launch(void* const* d_in, const int* in_sizes, int n_in,
                              void* d_out, int out_size) {
    const float* x       = (const float*)d_in[0];
    const float* f       = (const float*)d_in[1];
    const float* wq      = (const float*)d_in[2];
    const float* bq      = (const float*)d_in[3];
    const float* wk      = (const float*)d_in[4];
    const float* bk      = (const float*)d_in[5];
    const float* wv      = (const float*)d_in[6];
    const float* bv      = (const float*)d_in[7];
    const float* wo      = (const float*)d_in[8];
    const float* bo      = (const float*)d_in[9];
    const float* rw_w    = (const float*)d_in[10];
    const float* rw_b    = (const float*)d_in[11];
    const float* convk_w = (const float*)d_in[12];
    const float* convk_b = (const float*)d_in[13];
    const float* convv_w = (const float*)d_in[14];
    const float* convv_b = (const float*)d_in[15];
    const float* qn_g    = (const float*)d_in[16];
    const float* qn_b    = (const float*)d_in[17];
    const float* kn_g    = (const float*)d_in[18];
    const float* kn_b    = (const float*)d_in[19];
    const float* vn_g    = (const float*)d_in[20];
    const float* vn_b    = (const float*)d_in[21];
    float* out = (float*)d_out;

    float *kg, *vg, *fbqk, *fbv, *cvT, *ckT;
    __half *xf, *qkh, *qkn, *xn, *kgn, *vgn, *Q, *Kl, *Vl, *Kg, *Vg, *O;
    __half *fwqk, *fwv, *fwo, *frw;
    cudaGetSymbolAddress((void**)&kg,   g_kg);
    cudaGetSymbolAddress((void**)&vg,   g_vg);
    cudaGetSymbolAddress((void**)&xf,   g_xf);
    cudaGetSymbolAddress((void**)&qkh,  g_qkh);
    cudaGetSymbolAddress((void**)&qkn,  g_qkn);
    cudaGetSymbolAddress((void**)&xn,   g_xn);
    cudaGetSymbolAddress((void**)&kgn,  g_kgn);
    cudaGetSymbolAddress((void**)&vgn,  g_vgn);
    cudaGetSymbolAddress((void**)&Q,    g_Q);
    cudaGetSymbolAddress((void**)&Kl,   g_Kl);
    cudaGetSymbolAddress((void**)&Vl,   g_Vl);
    cudaGetSymbolAddress((void**)&Kg,   g_Kg);
    cudaGetSymbolAddress((void**)&Vg,   g_Vg);
    cudaGetSymbolAddress((void**)&O,    g_O);
    cudaGetSymbolAddress((void**)&fwqk, g_fwqk);
    cudaGetSymbolAddress((void**)&fbqk, g_fbqk);
    cudaGetSymbolAddress((void**)&fwv,  g_fwv);
    cudaGetSymbolAddress((void**)&fwo,  g_fwo);
    cudaGetSymbolAddress((void**)&frw,  g_frw);
    cudaGetSymbolAddress((void**)&fbv,  g_fbv);
    cudaGetSymbolAddress((void**)&cvT,  g_cvT);
    cudaGetSymbolAddress((void**)&ckT,  g_ckT);

    cudaFuncSetAttribute(attn_kernel, cudaFuncAttributeMaxDynamicSharedMemorySize,
                         ATTN_SMEM_BYTES);
    cudaFuncSetAttribute(mma_gemm<0,0>, cudaFuncAttributeMaxDynamicSharedMemorySize, SMEM_GEMM);
    cudaFuncSetAttribute(mma_gemm<1,1>, cudaFuncAttributeMaxDynamicSharedMemorySize, SMEM_GEMM);
    cudaFuncSetAttribute(mma_gemm<1,0>, cudaFuncAttributeMaxDynamicSharedMemorySize, SMEM_GEMM);
    cudaFuncSetAttribute(mma_gemm<2,0>, cudaFuncAttributeMaxDynamicSharedMemorySize, SMEM_GEMM);
    cudaFuncSetAttribute(mma_gemm<3,0>, cudaFuncAttributeMaxDynamicSharedMemorySize, SMEM_GEMM);

    cudaStream_t s1, s2;
    cudaStreamCreateWithFlags(&s1, cudaStreamNonBlocking);
    cudaStreamCreateWithFlags(&s2, cudaStreamNonBlocking);
    cudaEvent_t evFork, evJoinV, evPrep, evRW0, evRW1, evQK1, evJoinKG, evA0, evO0;
    cudaEventCreateWithFlags(&evFork,   cudaEventDisableTiming);
    cudaEventCreateWithFlags(&evJoinV,  cudaEventDisableTiming);
    cudaEventCreateWithFlags(&evPrep,   cudaEventDisableTiming);
    cudaEventCreateWithFlags(&evRW0,    cudaEventDisableTiming);
    cudaEventCreateWithFlags(&evRW1,    cudaEventDisableTiming);
    cudaEventCreateWithFlags(&evQK1,    cudaEventDisableTiming);
    cudaEventCreateWithFlags(&evJoinKG, cudaEventDisableTiming);
    cudaEventCreateWithFlags(&evA0,     cudaEventDisableTiming);
    cudaEventCreateWithFlags(&evO0,     cudaEventDisableTiming);

    cudaEventRecord(evFork, 0);
    cudaStreamWaitEvent(s1, evFork, 0);
    cudaStreamWaitEvent(s2, evFork, 0);

    // ---- s1: x-side chain + off-critical folds ----
    fold_w_kernel<<<64, 256, 0, s1>>>(wv, vn_g, vn_b, bv, fwv, fbv, DD, DD);
    fold_w_kernel<<<64, 256, 0, s1>>>(wo, nullptr, nullptr, nullptr, fwo, nullptr, DD, DD);
    fold_w_kernel<<<64, 256, 0, s1>>>(wq, qn_g, qn_b, bq, fwqk, fbqk, DD, INCC);
    fold_w_kernel<<<64, 256, 0, s1>>>(wk, kn_g, kn_b, bk, fwqk + (size_t)DD * INCC, fbqk + DD, DD, INCC);
    convT_kernel<<<(DD * 64) / 256, 256, 0, s1>>>(convv_w, cvT, DD);
    convT_kernel<<<(INCC * 64) / 256, 256, 0, s1>>>(convk_w, ckT, INCC);
    ln_norm_kernel<512><<<MTOK / 8, 256, 0, s1>>>(x, xn);
    dwconv_kernel<512,float><<<dim3(4, BT * GG), 128, 0, s1>>>(x, cvT, convv_b, vg);
    ln_norm_kernel<512><<<(BT * NGLOB) / 8, 256, 0, s1>>>(vg, vgn);
    mma_gemm<1,0><<<dim3(4, 256), 256, SMEM_GEMM, s1>>>(
        xn, fwv, fbv, nullptr, Vl, nullptr, MTOK, DD, DD, DD, 0);
    mma_gemm<2,0><<<dim3(4, 4), 256, SMEM_GEMM, s1>>>(
        vgn, fwv, fbv, nullptr, Vg, nullptr, BT * NGLOB, DD, DD, DD, 0);
    cudaEventRecord(evJoinV, s1);

    // ---- default stream: frw fold + prep, then rw half0 chain ----
    fold_w_kernel<<<80, 256>>>(rw_w, nullptr, nullptr, nullptr, frw, nullptr, INCC, INCC);
    prep_xf_kernel<<<MTOK * INCC / 2048, 256>>>(x, f, xf);
    cudaEventRecord(evPrep, 0);

    mma_gemm<0,0><<<dim3(5, 128), 256, SMEM_GEMM>>>(
        xf, frw, rw_b, nullptr, qkh, nullptr, MTOK, INCC, INCC, INCC, 0);
    cudaEventRecord(evRW0, 0);
    ln_norm_h_kernel<640><<<MH / 8, 256>>>(qkh, qkn, 0);
    mma_gemm<1,1><<<dim3(8, 128), 256, SMEM_GEMM>>>(
        qkn, fwqk, fbqk, nullptr, Q, Kl, MTOK, 2 * DD, INCC, DD, 0);

    // ---- s2: rw half1 chain (overlaps half0 LN/QKproj) ----
    cudaStreamWaitEvent(s2, evPrep, 0);
    mma_gemm<0,0><<<dim3(5, 128), 256, SMEM_GEMM, s2>>>(
        xf, frw, rw_b, nullptr, qkh, nullptr, MTOK, INCC, INCC, INCC, MH);
    cudaEventRecord(evRW1, s2);
    ln_norm_h_kernel<640><<<MH / 8, 256, 0, s2>>>(qkh, qkn, MH);
    mma_gemm<1,1><<<dim3(8, 128), 256, SMEM_GEMM, s2>>>(
        qkn, fwqk, fbqk, nullptr, Q, Kl, MTOK, 2 * DD, INCC, DD, MH);
    cudaEventRecord(evQK1, s2);

    // ---- s1: kg chain (needs full qkh) ----
    cudaStreamWaitEvent(s1, evRW0, 0);
    cudaStreamWaitEvent(s1, evRW1, 0);
    dwconv_kernel<640,__half><<<dim3(5, BT * GG), 128, 0, s1>>>(qkh, ckT, convk_b, kg);
    ln_norm_kernel<640><<<(BT * NGLOB) / 8, 256, 0, s1>>>(kg, kgn);
    mma_gemm<2,0><<<dim3(4, 4), 256, SMEM_GEMM, s1>>>(
        kgn, fwqk + (size_t)DD * INCC, fbqk + DD, nullptr, Kg, nullptr,
        BT * NGLOB, DD, INCC, DD, 0);
    cudaEventRecord(evJoinKG, s1);

    // ---- tail: staggered attention + out-projection ----
    cudaStreamWaitEvent(0, evJoinV, 0);
    cudaStreamWaitEvent(0, evJoinKG, 0);
    attn_kernel<<<BT * GG * NHEAD / 2, 256, ATTN_SMEM_BYTES>>>(Q, Kl, Kg, Vl, Vg, O, 0);
    cudaEventRecord(evA0, 0);
    cudaStreamWaitEvent(0, evQK1, 0);
    attn_kernel<<<BT * GG * NHEAD / 2, 256, ATTN_SMEM_BYTES>>>(Q, Kl, Kg, Vl, Vg, O,
                                                               BT * GG * NHEAD / 2);
    // s2: out-projection half0 overlapping attention half1
    cudaStreamWaitEvent(s2, evA0, 0);
    cudaStreamWaitEvent(s2, evJoinV, 0);
    mma_gemm<3,0><<<dim3(4, 128), 256, SMEM_GEMM, s2>>>(
        O, fwo, bo, out, nullptr, nullptr, MTOK, DD, DD, DD, 0);
    cudaEventRecord(evO0, s2);
    // default: out-projection half1, then join
    mma_gemm<3,0><<<dim3(4, 128), 256, SMEM_GEMM>>>(
        O, fwo, bo, out, nullptr, nullptr, MTOK, DD, DD, DD, MH);
    cudaStreamWaitEvent(0, evO0, 0);

    cudaEventDestroy(evFork);
    cudaEventDestroy(evJoinV);
    cudaEventDestroy(evPrep);
    cudaEventDestroy(evRW0);
    cudaEventDestroy(evRW1);
    cudaEventDestroy(evQK1);
    cudaEventDestroy(evJoinKG);
    cudaEventDestroy(evA0);
    cudaEventDestroy(evO0);
    cudaStreamDestroy(s1);
    cudaStreamDestroy(s2);
}

// round 14
// speedup vs baseline: 3.2615x; 1.0284x over previous
#include <cuda_runtime.h>
#include <cuda_fp16.h>
#include <cstdint>

// ---------------- problem constants ----------------
#define BT     8
#define NPIX   4096
#define DD     512
#define CFF    128
#define INCC   640
#define GG     64
#define NWIN   64
#define NGLOB  64
#define NHEAD  8
#define DHH    64
#define MTOK   32768

// ---------------- scratch ----------------
__device__ float  g_kg [BT*NGLOB*INCC];
__device__ float  g_vg [BT*NGLOB*DD];
__device__ __half g_xf [MTOK*INCC];
__device__ __half g_qkh[MTOK*INCC];
__device__ __half g_qkn[MTOK*INCC];
__device__ __half g_xn [MTOK*DD];
__device__ __half g_kgn[BT*NGLOB*INCC];
__device__ __half g_vgn[BT*NGLOB*DD];
__device__ __half g_Q  [MTOK*DD];
__device__ __half g_Kl [MTOK*DD];
__device__ __half g_Vl [MTOK*DD];
__device__ __half g_Kg [BT*NGLOB*DD];
__device__ __half g_Vg [BT*NGLOB*DD];
__device__ __half g_O  [MTOK*DD];
__device__ __half g_fwqk[2*DD*INCC];
__device__ float  g_fbqk[2*DD];
__device__ __half g_fwv[DD*DD];
__device__ __half g_fwo[DD*DD];
__device__ __half g_frw[INCC*INCC];
__device__ float  g_fbv[DD];
__device__ float  g_cvT[64*DD];
__device__ float  g_ckT[64*INCC];

// ---------------- helpers ----------------
__device__ __forceinline__ int win_map(int r) {
    int b = r >> 12;
    int p = r & 4095;
    int h = p >> 6, w = p & 63;
    int g = ((h >> 3) << 3) | (w >> 3);
    int n = ((h & 7) << 3) | (w & 7);
    return (((b << 6) | g) << 6) | n;
}

__device__ __forceinline__ uint32_t h2b(float a, float b) {
    __half2 h = __floats2half2_rn(a, b);
    return *(uint32_t*)&h;
}
__device__ __forceinline__ uint32_t h2ex2(uint32_t t) {
    uint32_t d;
    asm("ex2.approx.f16x2 %0, %1;" : "=r"(d) : "r"(t));
    return d;
}
__device__ __forceinline__ uint32_t h2tanh(uint32_t t) {
    uint32_t d;
    asm("tanh.approx.f16x2 %0, %1;" : "=r"(d) : "r"(t));
    return d;
}

__device__ __forceinline__ void mma_f16(float* d, const uint32_t* a, const uint32_t* b) {
    asm volatile(
        "mma.sync.aligned.m16n8k16.row.col.f32.f16.f16.f32 "
        "{%0,%1,%2,%3}, {%4,%5,%6,%7}, {%8,%9}, {%0,%1,%2,%3};"
        : "+f"(d[0]), "+f"(d[1]), "+f"(d[2]), "+f"(d[3])
        : "r"(a[0]), "r"(a[1]), "r"(a[2]), "r"(a[3]), "r"(b[0]), "r"(b[1]));
}

__device__ __forceinline__ void ldsm_x4(uint32_t* r, uint32_t addr) {
    asm volatile("ldmatrix.sync.aligned.m8n8.x4.shared.b16 {%0,%1,%2,%3}, [%4];"
                 : "=r"(r[0]), "=r"(r[1]), "=r"(r[2]), "=r"(r[3]) : "r"(addr));
}
__device__ __forceinline__ void ldsm_x4_t(uint32_t* r, uint32_t addr) {
    asm volatile("ldmatrix.sync.aligned.m8n8.x4.trans.shared.b16 {%0,%1,%2,%3}, [%4];"
                 : "=r"(r[0]), "=r"(r[1]), "=r"(r[2]), "=r"(r[3]) : "r"(addr));
}

#define CP_ASYNC16(dst, src) \
    asm volatile("cp.async.ca.shared.global [%0], [%1], 16;" :: "r"(dst), "l"(src))
#define CP_COMMIT() asm volatile("cp.async.commit_group;" ::: "memory")
#define CP_WAIT0()  asm volatile("cp.async.wait_group 0;" ::: "memory")

// ---------------- weight fold ----------------
__global__ __launch_bounds__(256)
void fold_w_kernel(const float* __restrict__ W, const float* __restrict__ gamma,
                   const float* __restrict__ beta, const float* __restrict__ b,
                   __half* __restrict__ Wo, float* __restrict__ bo, int N, int K) {
    int n = blockIdx.x * 8 + (threadIdx.x >> 5);
    if (n >= N) return;
    int lane = threadIdx.x & 31;
    const float* wr = W + (size_t)n * K;
    __half* wor = Wo + (size_t)n * K;
    float acc = 0.f;
    for (int k = lane; k < K; k += 32) {
        float w = wr[k];
        if (beta) acc += beta[k] * w;
        wor[k] = __float2half(gamma ? w * gamma[k] : w);
    }
    if (beta) {
        #pragma unroll
        for (int o = 16; o; o >>= 1) acc += __shfl_xor_sync(0xffffffffu, acc, o);
        if (lane == 0) bo[n] = b[n] + acc;
    }
}

// ---------------- conv weight transpose ----------------
__global__ __launch_bounds__(256)
void convT_kernel(const float* __restrict__ W, float* __restrict__ Wt, int C) {
    int idx = blockIdx.x * 256 + threadIdx.x;
    if (idx >= C * 64) return;
    int c = idx >> 6, k = idx & 63;
    Wt[k * C + c] = W[idx];
}

// ---------------- raw concat(x,f) -> half ----------------
__global__ __launch_bounds__(256)
void prep_xf_kernel(const float* __restrict__ x, const float* __restrict__ f,
                    __half* __restrict__ xf) {
    size_t idx = ((size_t)blockIdx.x * 256 + threadIdx.x) * 8;
    int r = (int)(idx / INCC);
    int c = (int)(idx % INCC);
    const float* src = (c < 512) ? (x + (size_t)r * 512 + c)
                                 : (f + (size_t)r * 128 + (c - 512));
    float4 a = *(const float4*)src;
    float4 b = *(const float4*)(src + 4);
    uint4 o;
    o.x = h2b(a.x, a.y); o.y = h2b(a.z, a.w);
    o.z = h2b(b.x, b.y); o.w = h2b(b.z, b.w);
    *(uint4*)(xf + idx) = o;
}

// ---------------- fused LN (fp32 input) ----------------
template<int K>
__global__ __launch_bounds__(256)
void ln_norm_kernel(const float* __restrict__ X, __half* __restrict__ Xn) {
    const int NSEG = K / 128;
    int row = blockIdx.x * 8 + (threadIdx.x >> 5);
    int lane = threadIdx.x & 31;
    const float* xr = X + (size_t)row * K;
    float4 v[NSEG];
    float s = 0.f, ss = 0.f;
    #pragma unroll
    for (int i = 0; i < NSEG; i++) {
        v[i] = *(const float4*)(xr + lane * 4 + i * 128);
        s  += v[i].x + v[i].y + v[i].z + v[i].w;
        ss += v[i].x * v[i].x + v[i].y * v[i].y + v[i].z * v[i].z + v[i].w * v[i].w;
    }
    #pragma unroll
    for (int o = 16; o; o >>= 1) {
        s  += __shfl_xor_sync(0xffffffffu, s, o);
        ss += __shfl_xor_sync(0xffffffffu, ss, o);
    }
    float mean = s / K;
    float rstd = rsqrtf(ss / K - mean * mean + 1e-5f);
    __half* xo = Xn + (size_t)row * K;
    #pragma unroll
    for (int i = 0; i < NSEG; i++) {
        uint2 o;
        o.x = h2b((v[i].x - mean) * rstd, (v[i].y - mean) * rstd);
        o.y = h2b((v[i].z - mean) * rstd, (v[i].w - mean) * rstd);
        *(uint2*)(xo + lane * 4 + i * 128) = o;
    }
}

// ---------------- fused LN (half input) ----------------
template<int K>
__global__ __launch_bounds__(256)
void ln_norm_h_kernel(const __half* __restrict__ X, __half* __restrict__ Xn, int row0) {
    const int NSEG = K / 128;
    int row = row0 + blockIdx.x * 8 + (threadIdx.x >> 5);
    int lane = threadIdx.x & 31;
    const __half* xr = X + (size_t)row * K;
    float v[NSEG][4];
    float s = 0.f, ss = 0.f;
    #pragma unroll
    for (int i = 0; i < NSEG; i++) {
        uint2 p = *(const uint2*)(xr + lane * 4 + i * 128);
        __half2 h0 = *(__half2*)&p.x;
        __half2 h1 = *(__half2*)&p.y;
        v[i][0] = __half2float(h0.x); v[i][1] = __half2float(h0.y);
        v[i][2] = __half2float(h1.x); v[i][3] = __half2float(h1.y);
        #pragma unroll
        for (int j = 0; j < 4; j++) { s += v[i][j]; ss += v[i][j] * v[i][j]; }
    }
    #pragma unroll
    for (int o = 16; o; o >>= 1) {
        s  += __shfl_xor_sync(0xffffffffu, s, o);
        ss += __shfl_xor_sync(0xffffffffu, ss, o);
    }
    float mean = s / K;
    float rstd = rsqrtf(ss / K - mean * mean + 1e-5f);
    __half* xo = Xn + (size_t)row * K;
    #pragma unroll
    for (int i = 0; i < NSEG; i++) {
        uint2 o;
        o.x = h2b((v[i][0] - mean) * rstd, (v[i][1] - mean) * rstd);
        o.y = h2b((v[i][2] - mean) * rstd, (v[i][3] - mean) * rstd);
        *(uint2*)(xo + lane * 4 + i * 128) = o;
    }
}

// ---------------- depthwise conv ----------------
template<int C, typename T>
__global__ __launch_bounds__(128)
void dwconv_kernel(const T* __restrict__ X, const float* __restrict__ Wt,
                   const float* __restrict__ bc, float* __restrict__ out) {
    int bw = blockIdx.y;
    int c = blockIdx.x * 128 + threadIdx.x;
    int b = bw >> 6;
    int g = bw & 63;
    int gh = g >> 3, gw = g & 7;
    const T* xb = X + ((size_t)b * NPIX + (size_t)(gh * 8) * 64 + gw * 8) * C + c;
    float s = bc[c];
    #pragma unroll
    for (int i = 0; i < 8; i++)
        #pragma unroll
        for (int j = 0; j < 8; j++)
            s += (float)xb[(size_t)(i * 64 + j) * C] * Wt[(i * 8 + j) * C + c];
    out[(size_t)bw * C + c] = s;
}

// ---------------- fp16 mma GEMM ----------------
#define GS 72
template<int MODE, int SPLIT>
__global__ __launch_bounds__(256)
void mma_gemm(const __half* __restrict__ A, const __half* __restrict__ W,
              const float* __restrict__ bias,
              float* __restrict__ Cf, __half* __restrict__ Ch, __half* __restrict__ Ch2,
              int M, int N, int K, int ldc, int m_off) {
    extern __shared__ __half sh[];
    __half* As = sh;
    __half* Bs = sh + 2 * 128 * GS;

    const int tid = threadIdx.x;
    const int m0 = blockIdx.y * 128 + m_off;
    const int n0 = blockIdx.x * 128;
    const int q = tid & 7;
    const int lrow = tid >> 3;
    const int lane = tid & 31, grp = lane >> 2, tig = lane & 3;
    const int w = tid >> 5, mblk = (w & 3) * 32, nblk = (w >> 2) * 64;
    const int NC = K >> 6;

    const uint32_t as_s = (uint32_t)__cvta_generic_to_shared(As);
    const uint32_t bs_s = (uint32_t)__cvta_generic_to_shared(Bs);

    const uint32_t aoff0 = (uint32_t)(((mblk + (lane & 15)) * GS + (lane >> 4) * 8) * 2);
    const uint32_t aoff1 = aoff0 + (uint32_t)(16 * GS * 2);
    const uint32_t boff  = (uint32_t)(((nblk + (lane & 7) + ((lane & 16) ? 8 : 0)) * GS
                                       + ((lane & 8) ? 8 : 0)) * 2);

    int arow[4];
    #pragma unroll
    for (int i = 0; i < 4; i++) {
        int r = m0 + lrow + i * 32;
        arow[i] = (MODE == 3) ? win_map(r) : r;
    }

    float acc[2][8][4];
    #pragma unroll
    for (int mt = 0; mt < 2; mt++)
        #pragma unroll
        for (int nt = 0; nt < 8; nt++)
            #pragma unroll
            for (int e = 0; e < 4; e++) acc[mt][nt][e] = 0.f;

    auto issue = [&](int ch, int buf) {
        int gk = (ch << 6) + q * 8;
        #pragma unroll
        for (int i = 0; i < 4; i++) {
            int r = lrow + i * 32;
            CP_ASYNC16(as_s + (uint32_t)(((buf * 128 + r) * GS + q * 8) * 2),
                       A + (size_t)arow[i] * K + gk);
            CP_ASYNC16(bs_s + (uint32_t)(((buf * 128 + r) * GS + q * 8) * 2),
                       W + (size_t)(n0 + r) * K + gk);
        }
        CP_COMMIT();
    };
    auto compute = [&](int buf) {
        uint32_t abase = as_s + (uint32_t)(buf * 128 * GS * 2);
        uint32_t bbase = bs_s + (uint32_t)(buf * 128 * GS * 2);
        #pragma unroll
        for (int k16 = 0; k16 < 4; k16++) {
            uint32_t kb = (uint32_t)(k16 * 32);
            uint32_t af0[4], af1[4];
            ldsm_x4(af0, abase + aoff0 + kb);
            ldsm_x4(af1, abase + aoff1 + kb);
            #pragma unroll
            for (int p = 0; p < 4; p++) {
                uint32_t bf[4];
                ldsm_x4(bf, bbase + boff + (uint32_t)(p * 16 * GS * 2) + kb);
                mma_f16(acc[0][2 * p],     af0, bf);
                mma_f16(acc[1][2 * p],     af1, bf);
                mma_f16(acc[0][2 * p + 1], af0, bf + 2);
                mma_f16(acc[1][2 * p + 1], af1, bf + 2);
            }
        }
    };

    issue(0, 0);
    CP_WAIT0();
    __syncthreads();

    for (int ch = 0; ch < NC; ch++) {
        int buf = ch & 1;
        int nx = ch + 1;
        if (nx < NC) issue(nx, buf ^ 1);
        compute(buf);
        if (nx < NC) CP_WAIT0();
        __syncthreads();
    }

    const __half2 hhalf = __floats2half2_rn(0.5f, 0.5f);
    #pragma unroll
    for (int mt = 0; mt < 2; mt++) {
        #pragma unroll
        for (int hr = 0; hr < 2; hr++) {
            int r = m0 + mblk + mt * 16 + grp + hr * 8;
            size_t orow = (MODE == 1) ? (size_t)win_map(r) : (size_t)r;
            #pragma unroll
            for (int nt = 0; nt < 8; nt++) {
                int c = n0 + nblk + nt * 8 + 2 * tig;
                float y0 = acc[mt][nt][hr * 2 + 0] + bias[c];
                float y1 = acc[mt][nt][hr * 2 + 1] + bias[c + 1];
                if (MODE == 0) {
                    // sigmoid via tanh.approx.f16x2: sigma(y) = 0.5*tanh(y/2)+0.5
                    __half2 a01 = *(const __half2*)(A + (size_t)r * K + c);
                    uint32_t th = h2tanh(h2b(y0 * 0.5f, y1 * 0.5f));
                    __half2 sig = __hfma2(*(__half2*)&th, hhalf, hhalf);
                    *(__half2*)(Ch + orow * (size_t)ldc + c) = __hmul2(a01, sig);
                } else if (MODE == 3) {
                    *(float2*)(Cf + orow * (size_t)ldc + c) = make_float2(y0, y1);
                } else {
                    __half* base = Ch;
                    int cc = c;
                    if (SPLIT) { base = (c < 512) ? Ch : Ch2; cc = c & 511; }
                    *(__half2*)(base + orow * (size_t)ldc + cc) = __floats2half2_rn(y0, y1);
                }
            }
        }
    }
}

// ---------------- attention: register softmax (ex2.f16x2) + trans-ldmatrix PV ----------------
#define AQ_STR 72
#define PS_STR 136
#define ATTN_SMEM_BYTES ((64*AQ_STR + 128*AQ_STR + 128*AQ_STR + 64*PS_STR) * 2 + 2 * 128 * 4)
#define C_LG2E 0.18033688f   // 0.125 * log2(e)

__global__ __launch_bounds__(256)
void attn_kernel(const __half* __restrict__ Q, const __half* __restrict__ Kl,
                 const __half* __restrict__ Kg, const __half* __restrict__ Vl,
                 const __half* __restrict__ Vg, __half* __restrict__ O, int bid_off) {
    extern __shared__ char smraw[];
    __half* Qs = (__half*)smraw;
    __half* Ks = Qs + 64 * AQ_STR;
    __half* Vs = Ks + 128 * AQ_STR;
    __half* Ps = Vs + 128 * AQ_STR;
    float* Rmax = (float*)(Ps + 64 * PS_STR);
    float* Rsum = Rmax + 128;

    int bid = blockIdx.x + bid_off;
    int b = bid >> 9;
    int rem = bid & 511;
    int g = rem >> 3;
    int h = rem & 7;

    size_t wbase = ((size_t)(b * GG + g) * NWIN) * DD + (size_t)h * DHH;
    size_t gbase = ((size_t)b * NGLOB) * DD + (size_t)h * DHH;
    const __half* Qp  = Q  + wbase;
    const __half* Klp = Kl + wbase;
    const __half* Vlp = Vl + wbase;
    const __half* Kgp = Kg + gbase;
    const __half* Vgp = Vg + gbase;
    __half* Op = O + wbase;

    int tid = threadIdx.x;
    const uint32_t qs_s = (uint32_t)__cvta_generic_to_shared(Qs);
    const uint32_t ks_s = (uint32_t)__cvta_generic_to_shared(Ks);
    const uint32_t vs_s = (uint32_t)__cvta_generic_to_shared(Vs);
    const uint32_t ps_s = (uint32_t)__cvta_generic_to_shared(Ps);

    for (int e = tid; e < 64 * 8; e += 256) {
        int m = e >> 3, sg = e & 7;
        CP_ASYNC16(qs_s + (uint32_t)((m * AQ_STR + sg * 8) * 2), Qp + (size_t)m * DD + sg * 8);
    }
    for (int e = tid; e < 128 * 8; e += 256) {
        int kk = e >> 3, sg = e & 7;
        const __half* ksrc = (kk < 64) ? (Klp + (size_t)kk * DD)
                                       : (Kgp + (size_t)(kk - 64) * DD);
        CP_ASYNC16(ks_s + (uint32_t)((kk * AQ_STR + sg * 8) * 2), ksrc + sg * 8);
        const __half* vsrc = (kk < 64) ? (Vlp + (size_t)kk * DD)
                                       : (Vgp + (size_t)(kk - 64) * DD);
        CP_ASYNC16(vs_s + (uint32_t)((kk * AQ_STR + sg * 8) * 2), vsrc + sg * 8);
    }
    CP_COMMIT();
    CP_WAIT0();
    __syncthreads();

    int w = tid >> 5, lane = tid & 31, grp = lane >> 2, tig = lane & 3;
    int mrow = (w & 3) * 16;
    int hh = w >> 2;
    int nb0 = hh * 64;
    int r0 = mrow + grp, r1 = r0 + 8;

    float acc[8][4];
    {
        const uint32_t aoff = qs_s +
            (uint32_t)(((mrow + (lane & 15)) * AQ_STR + (lane >> 4) * 8) * 2);
        const uint32_t boff = ks_s +
            (uint32_t)(((nb0 + (lane & 7) + ((lane & 16) ? 8 : 0)) * AQ_STR
                        + ((lane & 8) ? 8 : 0)) * 2);
        #pragma unroll
        for (int nt = 0; nt < 8; nt++)
            #pragma unroll
            for (int e = 0; e < 4; e++) acc[nt][e] = 0.f;
        #pragma unroll
        for (int k16 = 0; k16 < 4; k16++) {
            uint32_t kb = (uint32_t)(k16 * 32);
            uint32_t af[4];
            ldsm_x4(af, aoff + kb);
            #pragma unroll
            for (int p = 0; p < 4; p++) {
                uint32_t bf[4];
                ldsm_x4(bf, boff + (uint32_t)(p * 16 * AQ_STR * 2) + kb);
                mma_f16(acc[2 * p],     af, bf);
                mma_f16(acc[2 * p + 1], af, bf + 2);
            }
        }
    }

    float m0 = -1e30f, m1 = -1e30f;
    #pragma unroll
    for (int nt = 0; nt < 8; nt++) {
        m0 = fmaxf(m0, fmaxf(acc[nt][0], acc[nt][1]));
        m1 = fmaxf(m1, fmaxf(acc[nt][2], acc[nt][3]));
    }
    m0 = fmaxf(m0, __shfl_xor_sync(0xffffffffu, m0, 1));
    m0 = fmaxf(m0, __shfl_xor_sync(0xffffffffu, m0, 2));
    m1 = fmaxf(m1, __shfl_xor_sync(0xffffffffu, m1, 1));
    m1 = fmaxf(m1, __shfl_xor_sync(0xffffffffu, m1, 2));
    if (tig == 0) {
        Rmax[hh * 64 + r0] = m0;
        Rmax[hh * 64 + r1] = m1;
    }
    __syncthreads();
    float M0 = fmaxf(Rmax[r0], Rmax[64 + r0]) * C_LG2E;
    float M1 = fmaxf(Rmax[r1], Rmax[64 + r1]) * C_LG2E;

    float s0 = 0.f, s1 = 0.f;
    #pragma unroll
    for (int nt = 0; nt < 8; nt++) {
        // P = 2^(acc*C - M)  via packed half2 ex2
        uint32_t p01 = h2ex2(h2b(acc[nt][0] * C_LG2E - M0, acc[nt][1] * C_LG2E - M0));
        uint32_t p23 = h2ex2(h2b(acc[nt][2] * C_LG2E - M1, acc[nt][3] * C_LG2E - M1));
        int c = nb0 + nt * 8 + 2 * tig;
        *(uint32_t*)&Ps[r0 * PS_STR + c] = p01;
        *(uint32_t*)&Ps[r1 * PS_STR + c] = p23;
        float2 f01 = __half22float2(*(__half2*)&p01);
        float2 f23 = __half22float2(*(__half2*)&p23);
        s0 += f01.x + f01.y;
        s1 += f23.x + f23.y;
    }
    s0 += __shfl_xor_sync(0xffffffffu, s0, 1);
    s0 += __shfl_xor_sync(0xffffffffu, s0, 2);
    s1 += __shfl_xor_sync(0xffffffffu, s1, 1);
    s1 += __shfl_xor_sync(0xffffffffu, s1, 2);
    if (tig == 0) {
        Rsum[hh * 64 + r0] = s0;
        Rsum[hh * 64 + r1] = s1;
    }
    __syncthreads();
    float inv0 = 1.f / (Rsum[r0] + Rsum[64 + r0]);
    float inv1 = 1.f / (Rsum[r1] + Rsum[64 + r1]);

    {
        int db0 = hh * 32;
        const uint32_t aoff = ps_s +
            (uint32_t)(((mrow + (lane & 15)) * PS_STR + (lane >> 4) * 8) * 2);
        const uint32_t bvoff = vs_s +
            (uint32_t)((((lane & 7) + ((lane & 8) ? 8 : 0)) * AQ_STR
                        + db0 + ((lane & 16) ? 8 : 0)) * 2);
        float pac[4][4];
        #pragma unroll
        for (int nt = 0; nt < 4; nt++)
            #pragma unroll
            for (int e = 0; e < 4; e++) pac[nt][e] = 0.f;
        #pragma unroll
        for (int k16 = 0; k16 < 8; k16++) {
            uint32_t kba = (uint32_t)(k16 * 32);
            uint32_t kbb = (uint32_t)(k16 * 16 * AQ_STR * 2);
            uint32_t af[4];
            ldsm_x4(af, aoff + kba);
            #pragma unroll
            for (int p = 0; p < 2; p++) {
                uint32_t bf[4];
                ldsm_x4_t(bf, bvoff + (uint32_t)(p * 16 * 2) + kbb);
                mma_f16(pac[2 * p],     af, bf);
                mma_f16(pac[2 * p + 1], af, bf + 2);
            }
        }
        #pragma unroll
        for (int nt = 0; nt < 4; nt++) {
            int c = db0 + nt * 8 + 2 * tig;
            *(__half2*)(Op + (size_t)r0 * DD + c) =
                __floats2half2_rn(pac[nt][0] * inv0, pac[nt][1] * inv0);
            *(__half2*)(Op + (size_t)r1 * DD + c) =
                __floats2half2_rn(pac[nt][2] * inv1, pac[nt][3] * inv1);
        }
    }
}

// ---------------- launch ----------------
#define SMEM_GEMM (4 * 128 * GS * 2)
#define MH (MTOK / 2)

extern "C" void kernel_launch(void* const* d_in, const int* in_sizes, int n_in,
                              void* d_out, int out_size) {
    const float* x       = (const float*)d_in[0];
    const float* f       = (const float*)d_in[1];
    const float* wq      = (const float*)d_in[2];
    const float* bq      = (const float*)d_in[3];
    const float* wk      = (const float*)d_in[4];
    const float* bk      = (const float*)d_in[5];
    const float* wv      = (const float*)d_in[6];
    const float* bv      = (const float*)d_in[7];
    const float* wo      = (const float*)d_in[8];
    const float* bo      = (const float*)d_in[9];
    const float* rw_w    = (const float*)d_in[10];
    const float* rw_b    = (const float*)d_in[11];
    const float* convk_w = (const float*)d_in[12];
    const float* convk_b = (const float*)d_in[13];
    const float* convv_w = (const float*)d_in[14];
    const float* convv_b = (const float*)d_in[15];
    const float* qn_g    = (const float*)d_in[16];
    const float* qn_b    = (const float*)d_in[17];
    const float* kn_g    = (const float*)d_in[18];
    const float* kn_b    = (const float*)d_in[19];
    const float* vn_g    = (const float*)d_in[20];
    const float* vn_b    = (const float*)d_in[21];
    float* out = (float*)d_out;

    float *kg, *vg, *fbqk, *fbv, *cvT, *ckT;
    __half *xf, *qkh, *qkn, *xn, *kgn, *vgn, *Q, *Kl, *Vl, *Kg, *Vg, *O;
    __half *fwqk, *fwv, *fwo, *frw;
    cudaGetSymbolAddress((void**)&kg,   g_kg);
    cudaGetSymbolAddress((void**)&vg,   g_vg);
    cudaGetSymbolAddress((void**)&xf,   g_xf);
    cudaGetSymbolAddress((void**)&qkh,  g_qkh);
    cudaGetSymbolAddress((void**)&qkn,  g_qkn);
    cudaGetSymbolAddress((void**)&xn,   g_xn);
    cudaGetSymbolAddress((void**)&kgn,  g_kgn);
    cudaGetSymbolAddress((void**)&vgn,  g_vgn);
    cudaGetSymbolAddress((void**)&Q,    g_Q);
    cudaGetSymbolAddress((void**)&Kl,   g_Kl);
    cudaGetSymbolAddress((void**)&Vl,   g_Vl);
    cudaGetSymbolAddress((void**)&Kg,   g_Kg);
    cudaGetSymbolAddress((void**)&Vg,   g_Vg);
    cudaGetSymbolAddress((void**)&O,    g_O);
    cudaGetSymbolAddress((void**)&fwqk, g_fwqk);
    cudaGetSymbolAddress((void**)&fbqk, g_fbqk);
    cudaGetSymbolAddress((void**)&fwv,  g_fwv);
    cudaGetSymbolAddress((void**)&fwo,  g_fwo);
    cudaGetSymbolAddress((void**)&frw,  g_frw);
    cudaGetSymbolAddress((void**)&fbv,  g_fbv);
    cudaGetSymbolAddress((void**)&cvT,  g_cvT);
    cudaGetSymbolAddress((void**)&ckT,  g_ckT);

    cudaFuncSetAttribute(attn_kernel, cudaFuncAttributeMaxDynamicSharedMemorySize,
                         ATTN_SMEM_BYTES);
    cudaFuncSetAttribute(mma_gemm<0,0>, cudaFuncAttributeMaxDynamicSharedMemorySize, SMEM_GEMM);
    cudaFuncSetAttribute(mma_gemm<1,1>, cudaFuncAttributeMaxDynamicSharedMemorySize, SMEM_GEMM);
    cudaFuncSetAttribute(mma_gemm<1,0>, cudaFuncAttributeMaxDynamicSharedMemorySize, SMEM_GEMM);
    cudaFuncSetAttribute(mma_gemm<2,0>, cudaFuncAttributeMaxDynamicSharedMemorySize, SMEM_GEMM);
    cudaFuncSetAttribute(mma_gemm<3,0>, cudaFuncAttributeMaxDynamicSharedMemorySize, SMEM_GEMM);

    cudaStream_t s1, s2;
    cudaStreamCreateWithFlags(&s1, cudaStreamNonBlocking);
    cudaStreamCreateWithFlags(&s2, cudaStreamNonBlocking);
    cudaEvent_t evFork, evFRW, evJoinV, evPrep, evRW0, evRW1, evQK1, evJoinKG, evA0, evO0;
    cudaEventCreateWithFlags(&evFork,   cudaEventDisableTiming);
    cudaEventCreateWithFlags(&evFRW,    cudaEventDisableTiming);
    cudaEventCreateWithFlags(&evJoinV,  cudaEventDisableTiming);
    cudaEventCreateWithFlags(&evPrep,   cudaEventDisableTiming);
    cudaEventCreateWithFlags(&evRW0,    cudaEventDisableTiming);
    cudaEventCreateWithFlags(&evRW1,    cudaEventDisableTiming);
    cudaEventCreateWithFlags(&evQK1,    cudaEventDisableTiming);
    cudaEventCreateWithFlags(&evJoinKG, cudaEventDisableTiming);
    cudaEventCreateWithFlags(&evA0,     cudaEventDisableTiming);
    cudaEventCreateWithFlags(&evO0,     cudaEventDisableTiming);

    cudaEventRecord(evFork, 0);
    cudaStreamWaitEvent(s1, evFork, 0);
    cudaStreamWaitEvent(s2, evFork, 0);

    // ---- s1: frw fold first (gates reweight), then x-side chain ----
    fold_w_kernel<<<80, 256, 0, s1>>>(rw_w, nullptr, nullptr, nullptr, frw, nullptr, INCC, INCC);
    cudaEventRecord(evFRW, s1);
    fold_w_kernel<<<64, 256, 0, s1>>>(wv, vn_g, vn_b, bv, fwv, fbv, DD, DD);
    fold_w_kernel<<<64, 256, 0, s1>>>(wo, nullptr, nullptr, nullptr, fwo, nullptr, DD, DD);
    fold_w_kernel<<<64, 256, 0, s1>>>(wq, qn_g, qn_b, bq, fwqk, fbqk, DD, INCC);
    fold_w_kernel<<<64, 256, 0, s1>>>(wk, kn_g, kn_b, bk, fwqk + (size_t)DD * INCC, fbqk + DD, DD, INCC);
    convT_kernel<<<(DD * 64) / 256, 256, 0, s1>>>(convv_w, cvT, DD);
    convT_kernel<<<(INCC * 64) / 256, 256, 0, s1>>>(convk_w, ckT, INCC);
    ln_norm_kernel<512><<<MTOK / 8, 256, 0, s1>>>(x, xn);
    dwconv_kernel<512,float><<<dim3(4, BT * GG), 128, 0, s1>>>(x, cvT, convv_b, vg);
    ln_norm_kernel<512><<<(BT * NGLOB) / 8, 256, 0, s1>>>(vg, vgn);
    mma_gemm<1,0><<<dim3(4, 256), 256, SMEM_GEMM, s1>>>(
        xn, fwv, fbv, nullptr, Vl, nullptr, MTOK, DD, DD, DD, 0);
    mma_gemm<2,0><<<dim3(4, 4), 256, SMEM_GEMM, s1>>>(
        vgn, fwv, fbv, nullptr, Vg, nullptr, BT * NGLOB, DD, DD, DD, 0);
    cudaEventRecord(evJoinV, s1);

    // ---- default stream: prep then rw half0 chain ----
    prep_xf_kernel<<<MTOK * INCC / 2048, 256>>>(x, f, xf);
    cudaEventRecord(evPrep, 0);

    cudaStreamWaitEvent(0, evFRW, 0);
    mma_gemm<0,0><<<dim3(5, 128), 256, SMEM_GEMM>>>(
        xf, frw, rw_b, nullptr, qkh, nullptr, MTOK, INCC, INCC, INCC, 0);
    cudaEventRecord(evRW0, 0);
    ln_norm_h_kernel<640><<<MH / 8, 256>>>(qkh, qkn, 0);
    mma_gemm<1,1><<<dim3(8, 128), 256, SMEM_GEMM>>>(
        qkn, fwqk, fbqk, nullptr, Q, Kl, MTOK, 2 * DD, INCC, DD, 0);

    // ---- s2: rw half1 chain ----
    cudaStreamWaitEvent(s2, evPrep, 0);
    cudaStreamWaitEvent(s2, evFRW, 0);
    mma_gemm<0,0><<<dim3(5, 128), 256, SMEM_GEMM, s2>>>(
        xf, frw, rw_b, nullptr, qkh, nullptr, MTOK, INCC, INCC, INCC, MH);
    cudaEventRecord(evRW1, s2);
    ln_norm_h_kernel<640><<<MH / 8, 256, 0, s2>>>(qkh, qkn, MH);
    mma_gemm<1,1><<<dim3(8, 128), 256, SMEM_GEMM, s2>>>(
        qkn, fwqk, fbqk, nullptr, Q, Kl, MTOK, 2 * DD, INCC, DD, MH);
    cudaEventRecord(evQK1, s2);

    // ---- s1: kg chain (needs full qkh) ----
    cudaStreamWaitEvent(s1, evRW0, 0);
    cudaStreamWaitEvent(s1, evRW1, 0);
    dwconv_kernel<640,__half><<<dim3(5, BT * GG), 128, 0, s1>>>(qkh, ckT, convk_b, kg);
    ln_norm_kernel<640><<<(BT * NGLOB) / 8, 256, 0, s1>>>(kg, kgn);
    mma_gemm<2,0><<<dim3(4, 4), 256, SMEM_GEMM, s1>>>(
        kgn, fwqk + (size_t)DD * INCC, fbqk + DD, nullptr, Kg, nullptr,
        BT * NGLOB, DD, INCC, DD, 0);
    cudaEventRecord(evJoinKG, s1);

    // ---- tail: staggered attention + out-projection ----
    cudaStreamWaitEvent(0, evJoinV, 0);
    cudaStreamWaitEvent(0, evJoinKG, 0);
    attn_kernel<<<BT * GG * NHEAD / 2, 256, ATTN_SMEM_BYTES>>>(Q, Kl, Kg, Vl, Vg, O, 0);
    cudaEventRecord(evA0, 0);
    cudaStreamWaitEvent(0, evQK1, 0);
    attn_kernel<<<BT * GG * NHEAD / 2, 256, ATTN_SMEM_BYTES>>>(Q, Kl, Kg, Vl, Vg, O,
                                                               BT * GG * NHEAD / 2);
    cudaStreamWaitEvent(s2, evA0, 0);
    cudaStreamWaitEvent(s2, evJoinV, 0);
    mma_gemm<3,0><<<dim3(4, 128), 256, SMEM_GEMM, s2>>>(
        O, fwo, bo, out, nullptr, nullptr, MTOK, DD, DD, DD, 0);
    cudaEventRecord(evO0, s2);
    mma_gemm<3,0><<<dim3(4, 128), 256, SMEM_GEMM>>>(
        O, fwo, bo, out, nullptr, nullptr, MTOK, DD, DD, DD, MH);
    cudaStreamWaitEvent(0, evO0, 0);

    cudaEventDestroy(evFork);
    cudaEventDestroy(evFRW);
    cudaEventDestroy(evJoinV);
    cudaEventDestroy(evPrep);
    cudaEventDestroy(evRW0);
    cudaEventDestroy(evRW1);
    cudaEventDestroy(evQK1);
    cudaEventDestroy(evJoinKG);
    cudaEventDestroy(evA0);
    cudaEventDestroy(evO0);
    cudaStreamDestroy(s1);
    cudaStreamDestroy(s2);
}